// round 2
// baseline (speedup 1.0000x reference)
#include <cuda_runtime.h>
#include <cuda_bf16.h>

// Problem constants (fixed shapes per reference)
#define NN 50000
#define EE 800000
#define RR 8
#define DD 128          // embed dim == hidden dim
#define KC 1152         // 8 relations * 128 + 128 root columns
#define LN_EPS 1e-5f

// ---------------- scratch (device globals; no allocation allowed) ----------
__device__ __align__(16) float g_X[NN * DD];            // layer input
__device__ __align__(16) float g_O[NN * DD];            // rgcn output (layers 1,2)
__device__ __align__(16) float g_Y[NN * KC];            // per-relation projections (+root)
__device__ __align__(16) float g_Wc[DD * KC];           // packed [d][r*128+o | root]
__device__ float g_inv[NN * RR];                        // 1/max(cnt,1)

// ---------------- small utility kernels ------------------------------------

__global__ void zero_inv_kernel() {
    int i = blockIdx.x * blockDim.x + threadIdx.x;
    if (i < NN * RR) g_inv[i] = 0.0f;
}

__global__ void count_kernel(const int* __restrict__ ei, const int* __restrict__ et) {
    int e = blockIdx.x * blockDim.x + threadIdx.x;
    if (e < EE) {
        int dst = ei[EE + e];
        int t = et[e];
        atomicAdd(&g_inv[dst * RR + t], 1.0f);
    }
}

__global__ void invert_kernel() {
    int i = blockIdx.x * blockDim.x + threadIdx.x;
    if (i < NN * RR) g_inv[i] = 1.0f / fmaxf(g_inv[i], 1.0f);
}

// g_X[n] = emb[node_ids[n]]
__global__ void gather_kernel(const int* __restrict__ node_ids,
                              const float* __restrict__ emb) {
    int idx = blockIdx.x * blockDim.x + threadIdx.x;   // float4 index
    if (idx >= NN * 32) return;
    int n = idx >> 5;
    int c4 = idx & 31;
    int src = node_ids[n];
    ((float4*)g_X)[idx] = ((const float4*)emb)[src * 32 + c4];
}

// Pack W[r][d][o] (R,D,D) and root[d][o] into Wc[d][c], c = r*128+o or 1024+o
__global__ void pack_kernel(const float* __restrict__ W,
                            const float* __restrict__ root) {
    int idx = blockIdx.x * blockDim.x + threadIdx.x;
    if (idx >= DD * KC) return;
    int d = idx / KC;
    int c = idx - d * KC;
    float v;
    if (c < RR * DD) {
        int r = c >> 7;
        int o = c & 127;
        v = W[(r * DD + d) * DD + o];
    } else {
        v = root[d * DD + (c - RR * DD)];
    }
    g_Wc[idx] = v;
}

// ---------------- GEMM: Y[N,1152] = X[N,128] @ Wc[128,1152] ----------------
// Block: 256 threads, tile 64 nodes x 128 cols. warp w handles nodes w*8..w*8+7,
// lane handles 4 consecutive cols. 32 accumulators/thread.
__global__ __launch_bounds__(256) void gemm_kernel() {
    __shared__ float Xs[64 * 128];
    const int nb = blockIdx.y * 64;
    const int cb = blockIdx.x * 128;
    const int tid = threadIdx.x;

    // cooperative load of X tile (float4, coalesced)
#pragma unroll
    for (int i = 0; i < 8; i++) {
        int idx = tid + i * 256;        // 0..2047 float4 slots
        int row = idx >> 5;
        int gn = nb + row;
        float4 v = make_float4(0.f, 0.f, 0.f, 0.f);
        if (gn < NN) v = ((const float4*)g_X)[gn * 32 + (idx & 31)];
        ((float4*)Xs)[idx] = v;
    }
    __syncthreads();

    const int w = tid >> 5;
    const int lane = tid & 31;
    const int col = cb + lane * 4;
    const float* xrow = &Xs[(w * 8) * 128];

    float acc[8][4];
#pragma unroll
    for (int i = 0; i < 8; i++) {
        acc[i][0] = 0.f; acc[i][1] = 0.f; acc[i][2] = 0.f; acc[i][3] = 0.f;
    }

#pragma unroll 4
    for (int d = 0; d < 128; d++) {
        float4 wv = *(const float4*)(g_Wc + d * KC + col);
#pragma unroll
        for (int i = 0; i < 8; i++) {
            float xv = xrow[i * 128 + d];
            acc[i][0] = fmaf(xv, wv.x, acc[i][0]);
            acc[i][1] = fmaf(xv, wv.y, acc[i][1]);
            acc[i][2] = fmaf(xv, wv.z, acc[i][2]);
            acc[i][3] = fmaf(xv, wv.w, acc[i][3]);
        }
    }

#pragma unroll
    for (int i = 0; i < 8; i++) {
        int gn = nb + w * 8 + i;
        if (gn < NN) {
            float4 o = make_float4(acc[i][0], acc[i][1], acc[i][2], acc[i][3]);
            *(float4*)(g_Y + gn * KC + col) = o;
        }
    }
}

// ---------------- out init: root part + bias --------------------------------
__global__ void init_out_kernel(const float* __restrict__ bias, float* ext_out) {
    float* out = ext_out ? ext_out : g_O;
    int idx = blockIdx.x * blockDim.x + threadIdx.x;   // float4 index
    if (idx >= NN * 32) return;
    int n = idx >> 5;
    int c4 = idx & 31;
    float4 y = *(const float4*)(g_Y + n * KC + RR * DD + c4 * 4);
    float4 bb = ((const float4*)bias)[c4];
    float4 o = make_float4(y.x + bb.x, y.y + bb.y, y.z + bb.z, y.w + bb.w);
    ((float4*)out)[idx] = o;
}

// ---------------- edge scatter: out[dst] += Y[src, type] * inv --------------
// One warp per edge; each lane owns 4 consecutive floats.
__global__ __launch_bounds__(256) void scatter_kernel(const int* __restrict__ ei,
                                                      const int* __restrict__ et,
                                                      float* ext_out) {
    float* out = ext_out ? ext_out : g_O;
    int gt = blockIdx.x * blockDim.x + threadIdx.x;
    int e = gt >> 5;
    if (e >= EE) return;
    int lane = gt & 31;
    int src = ei[e];
    int dst = ei[EE + e];
    int t = et[e];
    float iv = __ldg(&g_inv[dst * RR + t]);
    float4 v = *(const float4*)(g_Y + src * KC + t * DD + lane * 4);
    float* op = out + dst * DD + lane * 4;
    atomicAdd(op + 0, v.x * iv);
    atomicAdd(op + 1, v.y * iv);
    atomicAdd(op + 2, v.z * iv);
    atomicAdd(op + 3, v.w * iv);
}

// ---------------- LayerNorm + ReLU: g_X = relu(LN(g_O)) ---------------------
__global__ void ln_relu_kernel(const float* __restrict__ gma,
                               const float* __restrict__ bta) {
    int gt = blockIdx.x * blockDim.x + threadIdx.x;
    int row = gt >> 5;
    if (row >= NN) return;
    int lane = gt & 31;
    float4 v = ((const float4*)g_O)[row * 32 + lane];
    float s = v.x + v.y + v.z + v.w;
#pragma unroll
    for (int off = 16; off > 0; off >>= 1) s += __shfl_xor_sync(0xffffffffu, s, off);
    float mu = s * (1.0f / 128.0f);
    float dx = v.x - mu, dy = v.y - mu, dz = v.z - mu, dw = v.w - mu;
    float q = dx * dx + dy * dy + dz * dz + dw * dw;
#pragma unroll
    for (int off = 16; off > 0; off >>= 1) q += __shfl_xor_sync(0xffffffffu, q, off);
    float rs = rsqrtf(q * (1.0f / 128.0f) + LN_EPS);
    float4 gg = ((const float4*)gma)[lane];
    float4 bb = ((const float4*)bta)[lane];
    float4 o;
    o.x = fmaxf(dx * rs * gg.x + bb.x, 0.f);
    o.y = fmaxf(dy * rs * gg.y + bb.y, 0.f);
    o.z = fmaxf(dz * rs * gg.z + bb.z, 0.f);
    o.w = fmaxf(dw * rs * gg.w + bb.w, 0.f);
    ((float4*)g_X)[row * 32 + lane] = o;
}

// ---------------- launch --------------------------------------------------
extern "C" void kernel_launch(void* const* d_in, const int* in_sizes, int n_in,
                              void* d_out, int out_size) {
    const int*   node_ids = (const int*)d_in[0];
    const int*   ei       = (const int*)d_in[1];     // [2,E]
    const int*   et       = (const int*)d_in[2];     // [E]
    const float* emb      = (const float*)d_in[3];
    const float* W1    = (const float*)d_in[4];
    const float* root1 = (const float*)d_in[5];
    const float* b1    = (const float*)d_in[6];
    const float* g1    = (const float*)d_in[7];
    const float* be1   = (const float*)d_in[8];
    const float* W2    = (const float*)d_in[9];
    const float* root2 = (const float*)d_in[10];
    const float* b2    = (const float*)d_in[11];
    const float* g2    = (const float*)d_in[12];
    const float* be2   = (const float*)d_in[13];
    const float* W3    = (const float*)d_in[14];
    const float* root3 = (const float*)d_in[15];
    const float* b3    = (const float*)d_in[16];
    float* out = (float*)d_out;

    const int T = 256;
    dim3 gemm_grid(KC / 128, (NN + 63) / 64);

    // edge-structure counts (reused by all layers)
    zero_inv_kernel<<<(NN * RR + T - 1) / T, T>>>();
    count_kernel<<<(EE + T - 1) / T, T>>>(ei, et);
    invert_kernel<<<(NN * RR + T - 1) / T, T>>>();

    // embedding gather
    gather_kernel<<<(NN * 32 + T - 1) / T, T>>>(node_ids, emb);

    // ---- layer 1 ----
    pack_kernel<<<(DD * KC + T - 1) / T, T>>>(W1, root1);
    gemm_kernel<<<gemm_grid, T>>>();
    init_out_kernel<<<(NN * 32 + T - 1) / T, T>>>(b1, nullptr);
    scatter_kernel<<<(EE * 32 + T - 1) / T, T>>>(ei, et, nullptr);
    ln_relu_kernel<<<(NN * 32 + T - 1) / T, T>>>(g1, be1);

    // ---- layer 2 ----
    pack_kernel<<<(DD * KC + T - 1) / T, T>>>(W2, root2);
    gemm_kernel<<<gemm_grid, T>>>();
    init_out_kernel<<<(NN * 32 + T - 1) / T, T>>>(b2, nullptr);
    scatter_kernel<<<(EE * 32 + T - 1) / T, T>>>(ei, et, nullptr);
    ln_relu_kernel<<<(NN * 32 + T - 1) / T, T>>>(g2, be2);

    // ---- layer 3 (direct to d_out) ----
    pack_kernel<<<(DD * KC + T - 1) / T, T>>>(W3, root3);
    gemm_kernel<<<gemm_grid, T>>>();
    init_out_kernel<<<(NN * 32 + T - 1) / T, T>>>(b3, out);
    scatter_kernel<<<(EE * 32 + T - 1) / T, T>>>(ei, et, out);
    (void)in_sizes; (void)n_in; (void)out_size;
}

// round 4
// speedup vs baseline: 2.9505x; 2.9505x over previous
#include <cuda_runtime.h>
#include <cuda_bf16.h>
#include <cstdint>

#define NN 50000
#define EE 800000
#define RR 8
#define DD 128
#define KC 1152        // 8*128 relation cols + 128 root cols
#define LN_EPS 1e-5f

// ---------------- scratch (device globals) ---------------------------------
__device__ __align__(16) float g_Y[NN * KC];                 // projections (+root)
__device__ __align__(16) __nv_bfloat16 g_Xhi[NN * DD];       // layer input hi
__device__ __align__(16) __nv_bfloat16 g_Xlo[NN * DD];       // layer input lo
__device__ __align__(16) __nv_bfloat16 g_Bhi[KC * DD];       // packed weights [c][d] hi
__device__ __align__(16) __nv_bfloat16 g_Blo[KC * DD];       // packed weights lo
__device__ float g_inv[NN * RR];                             // 1/max(cnt,1)
__device__ int   g_deg[NN];
__device__ int   g_cur[NN];
__device__ int   g_rowptr[NN + 1];
__device__ int   g_csr[EE];                                  // src*8 + type
__device__ int   g_part[256];

// ---------------- helpers ---------------------------------------------------
__device__ __forceinline__ uint32_t smem_u32(const void* p) {
    uint32_t a;
    asm("{ .reg .u64 t; cvta.to.shared.u64 t, %1; cvt.u32.u64 %0, t; }"
        : "=r"(a) : "l"(p));
    return a;
}

#define LDSM4(r0, r1, r2, r3, addr) asm volatile( \
    "ldmatrix.sync.aligned.m8n8.x4.shared.b16 {%0,%1,%2,%3}, [%4];" \
    : "=r"(r0), "=r"(r1), "=r"(r2), "=r"(r3) : "r"(addr))

#define MMA_BF16(c, a, b0, b1) asm volatile( \
    "mma.sync.aligned.m16n8k16.row.col.f32.bf16.bf16.f32 " \
    "{%0,%1,%2,%3}, {%4,%5,%6,%7}, {%8,%9}, {%0,%1,%2,%3};" \
    : "+f"((c)[0]), "+f"((c)[1]), "+f"((c)[2]), "+f"((c)[3]) \
    : "r"((a)[0]), "r"((a)[1]), "r"((a)[2]), "r"((a)[3]), "r"(b0), "r"(b1))

// split v into bf16 hi + lo packed pairs
__device__ __forceinline__ void hilo_pair(float x, float y,
                                          uint32_t& hp, uint32_t& lp) {
    __nv_bfloat16 hx = __float2bfloat16_rn(x);
    __nv_bfloat16 hy = __float2bfloat16_rn(y);
    __nv_bfloat16 lx = __float2bfloat16_rn(x - __bfloat162float(hx));
    __nv_bfloat16 ly = __float2bfloat16_rn(y - __bfloat162float(hy));
    __nv_bfloat162 h2 = __halves2bfloat162(hx, hy);
    __nv_bfloat162 l2 = __halves2bfloat162(lx, ly);
    hp = *reinterpret_cast<uint32_t*>(&h2);
    lp = *reinterpret_cast<uint32_t*>(&l2);
}

// ---------------- edge-structure kernels ------------------------------------
__global__ void zero_all_kernel() {
    int i = blockIdx.x * blockDim.x + threadIdx.x;
    if (i < NN * RR) g_inv[i] = 0.0f;
    if (i < NN) { g_deg[i] = 0; g_cur[i] = 0; }
}

__global__ void count_kernel(const int* __restrict__ ei, const int* __restrict__ et) {
    int e = blockIdx.x * blockDim.x + threadIdx.x;
    if (e < EE) {
        int dst = ei[EE + e];
        atomicAdd(&g_inv[dst * RR + et[e]], 1.0f);
        atomicAdd(&g_deg[dst], 1);
    }
}

__global__ void invert_kernel() {
    int i = blockIdx.x * blockDim.x + threadIdx.x;
    if (i < NN * RR) g_inv[i] = 1.0f / fmaxf(g_inv[i], 1.0f);
}

__global__ void deg_partial_kernel() {
    __shared__ int s[256];
    int i = blockIdx.x * 256 + threadIdx.x;
    int v = (i < NN) ? g_deg[i] : 0;
    s[threadIdx.x] = v;
    __syncthreads();
    for (int off = 128; off > 0; off >>= 1) {
        if (threadIdx.x < off) s[threadIdx.x] += s[threadIdx.x + off];
        __syncthreads();
    }
    if (threadIdx.x == 0) g_part[blockIdx.x] = s[0];
}

__global__ void scan_part_kernel(int nblocks) {
    __shared__ int s[512];
    int t = threadIdx.x;
    int v = (t < nblocks) ? g_part[t] : 0;
    s[t] = v;
    __syncthreads();
    int acc = v;
    for (int off = 1; off < 256; off <<= 1) {
        int add = (t >= off) ? s[t - off] : 0;
        __syncthreads();
        s[t] = acc = acc + add;
        __syncthreads();
    }
    if (t < nblocks) g_part[t] = s[t] - v;
}

__global__ void rowptr_kernel() {
    __shared__ int s[512];
    int t = threadIdx.x;
    int i = blockIdx.x * 256 + t;
    int v = (i < NN) ? g_deg[i] : 0;
    s[t] = v;
    __syncthreads();
    int acc = v;
    for (int off = 1; off < 256; off <<= 1) {
        int add = (t >= off) ? s[t - off] : 0;
        __syncthreads();
        s[t] = acc = acc + add;
        __syncthreads();
    }
    if (i < NN) g_rowptr[i] = g_part[blockIdx.x] + s[t] - v;
    if (i == NN) g_rowptr[NN] = EE;
}

__global__ void fill_kernel(const int* __restrict__ ei, const int* __restrict__ et) {
    int e = blockIdx.x * blockDim.x + threadIdx.x;
    if (e < EE) {
        int dst = ei[EE + e];
        int p = atomicAdd(&g_cur[dst], 1);
        g_csr[g_rowptr[dst] + p] = (ei[e] << 3) | et[e];
    }
}

// ---------------- gather + convert ------------------------------------------
__global__ void gather_kernel(const int* __restrict__ node_ids,
                              const float* __restrict__ emb) {
    int idx = blockIdx.x * blockDim.x + threadIdx.x;
    if (idx >= NN * 32) return;
    int n = idx >> 5;
    int c4 = idx & 31;
    int src = node_ids[n];
    float4 v = ((const float4*)emb)[src * 32 + c4];
    uint32_t h0, l0, h1, l1;
    hilo_pair(v.x, v.y, h0, l0);
    hilo_pair(v.z, v.w, h1, l1);
    uint32_t* xh = (uint32_t*)g_Xhi;
    uint32_t* xl = (uint32_t*)g_Xlo;
    xh[n * 64 + c4 * 2]     = h0;
    xh[n * 64 + c4 * 2 + 1] = h1;
    xl[n * 64 + c4 * 2]     = l0;
    xl[n * 64 + c4 * 2 + 1] = l1;
}

// pack W[r][d][o], root[d][o] -> B[c][d] bf16 hi/lo
__global__ void pack_kernel(const float* __restrict__ W, const float* __restrict__ root) {
    int idx = blockIdx.x * blockDim.x + threadIdx.x;
    if (idx >= KC * DD) return;
    int c = idx >> 7;
    int d = idx & 127;
    float v;
    if (c < RR * DD) v = W[((c >> 7) * DD + d) * DD + (c & 127)];
    else             v = root[d * DD + (c - RR * DD)];
    __nv_bfloat16 h = __float2bfloat16_rn(v);
    __nv_bfloat16 l = __float2bfloat16_rn(v - __bfloat162float(h));
    g_Bhi[idx] = h;
    g_Blo[idx] = l;
}

// ---------------- HMMA GEMM: Y[N,1152] = X[N,128] @ B^T ---------------------
// CTA tile: 128 rows x 64 cols, 4 warps (2x2), warp tile 64x32, K=128 resident.
#define LDS_ROW 272          // 136 halves per smem row (pad 128+8)
#define SM_AHI 0
#define SM_ALO 34816
#define SM_BHI 69632
#define SM_BLO 87040
#define GEMM_SMEM 104448

__global__ __launch_bounds__(128, 2) void gemm_kernel() {
    extern __shared__ char smem[];
    const uint32_t sb = smem_u32(smem);
    const int tid = threadIdx.x, wid = tid >> 5, lane = tid & 31;
    const int cb = blockIdx.x * 64;
    const int nb = blockIdx.y * 128;

    // A tile: 128 rows x 128 halves (hi & lo), 16 uint4 per row
#pragma unroll
    for (int i = 0; i < 16; i++) {
        int idx = tid + i * 128;
        int row = idx >> 4;
        int ch = idx & 15;
        int gn = nb + row;
        uint4 vh = make_uint4(0, 0, 0, 0), vl = vh;
        if (gn < NN) {
            vh = ((const uint4*)g_Xhi)[gn * 16 + ch];
            vl = ((const uint4*)g_Xlo)[gn * 16 + ch];
        }
        *(uint4*)(smem + SM_AHI + row * LDS_ROW + ch * 16) = vh;
        *(uint4*)(smem + SM_ALO + row * LDS_ROW + ch * 16) = vl;
    }
    // B tile: 64 rows x 128 halves
#pragma unroll
    for (int i = 0; i < 8; i++) {
        int idx = tid + i * 128;
        int row = idx >> 4;
        int ch = idx & 15;
        uint4 vh = ((const uint4*)g_Bhi)[(cb + row) * 16 + ch];
        uint4 vl = ((const uint4*)g_Blo)[(cb + row) * 16 + ch];
        *(uint4*)(smem + SM_BHI + row * LDS_ROW + ch * 16) = vh;
        *(uint4*)(smem + SM_BLO + row * LDS_ROW + ch * 16) = vl;
    }
    __syncthreads();

    const int wm = (wid >> 1) * 64;
    const int wn = (wid & 1) * 32;

    // ldmatrix lane addressing
    const uint32_t aRow = wm + (lane & 15);
    const uint32_t aOff = (lane >> 4) * 16;
    const uint32_t aHi = sb + SM_AHI + aRow * LDS_ROW + aOff;
    const uint32_t aLo = aHi + (SM_ALO - SM_AHI);
    const uint32_t bRow = wn + ((lane >> 4) & 1) * 8 + (lane & 7);
    const uint32_t bOff = ((lane >> 3) & 1) * 16;
    const uint32_t bHi = sb + SM_BHI + bRow * LDS_ROW + bOff;
    const uint32_t bLo = bHi + (SM_BLO - SM_BHI);

    float acc[4][4][4];
#pragma unroll
    for (int mt = 0; mt < 4; mt++)
#pragma unroll
        for (int nt = 0; nt < 4; nt++)
#pragma unroll
            for (int k = 0; k < 4; k++) acc[mt][nt][k] = 0.f;

#pragma unroll
    for (int ks = 0; ks < 8; ks++) {
        uint32_t ah[4][4], al[4][4], bh[2][4], bl[2][4];
#pragma unroll
        for (int mt = 0; mt < 4; mt++) {
            uint32_t o = mt * (16 * LDS_ROW) + ks * 32;
            LDSM4(ah[mt][0], ah[mt][1], ah[mt][2], ah[mt][3], aHi + o);
            LDSM4(al[mt][0], al[mt][1], al[mt][2], al[mt][3], aLo + o);
        }
#pragma unroll
        for (int bt = 0; bt < 2; bt++) {
            uint32_t o = bt * (16 * LDS_ROW) + ks * 32;
            LDSM4(bh[bt][0], bh[bt][1], bh[bt][2], bh[bt][3], bHi + o);
            LDSM4(bl[bt][0], bl[bt][1], bl[bt][2], bl[bt][3], bLo + o);
        }
#pragma unroll
        for (int mt = 0; mt < 4; mt++) {
#pragma unroll
            for (int nt = 0; nt < 4; nt++) {
                int bt = nt >> 1, bi = (nt & 1) * 2;
                MMA_BF16(acc[mt][nt], ah[mt], bh[bt][bi], bh[bt][bi + 1]);
                MMA_BF16(acc[mt][nt], ah[mt], bl[bt][bi], bl[bt][bi + 1]);
                MMA_BF16(acc[mt][nt], al[mt], bh[bt][bi], bh[bt][bi + 1]);
            }
        }
    }

    // epilogue: write fp32 to g_Y
    const int r0 = nb + wm + (lane >> 2);
    const int c0 = cb + wn + (lane & 3) * 2;
#pragma unroll
    for (int mt = 0; mt < 4; mt++) {
#pragma unroll
        for (int nt = 0; nt < 4; nt++) {
            int r = r0 + mt * 16;
            int c = c0 + nt * 8;
            if (r < NN)
                *(float2*)(g_Y + (size_t)r * KC + c) =
                    make_float2(acc[mt][nt][0], acc[mt][nt][1]);
            if (r + 8 < NN)
                *(float2*)(g_Y + (size_t)(r + 8) * KC + c) =
                    make_float2(acc[mt][nt][2], acc[mt][nt][3]);
        }
    }
}

// ---------------- CSR aggregation (+ fused LN+ReLU + bf16 split) -----------
__global__ __launch_bounds__(256)
void agg_kernel(const float* __restrict__ bias, const float* __restrict__ gma,
                const float* __restrict__ bta, float* __restrict__ ext_out,
                int do_ln) {
    int gt = blockIdx.x * blockDim.x + threadIdx.x;
    int row = gt >> 5;
    if (row >= NN) return;
    int lane = gt & 31;

    // root + bias
    float4 acc = *(const float4*)(g_Y + (size_t)row * KC + RR * DD + lane * 4);
    float4 bb = ((const float4*)bias)[lane];
    acc.x += bb.x; acc.y += bb.y; acc.z += bb.z; acc.w += bb.w;

    int beg = g_rowptr[row], end = g_rowptr[row + 1];
    for (int i = beg; i < end; i++) {
        int pk = __ldg(&g_csr[i]);
        int src = pk >> 3, t = pk & 7;
        float iv = __ldg(&g_inv[(row << 3) + t]);
        float4 v = __ldg((const float4*)(g_Y + (size_t)src * KC + (t << 7)) + lane);
        acc.x = fmaf(iv, v.x, acc.x);
        acc.y = fmaf(iv, v.y, acc.y);
        acc.z = fmaf(iv, v.z, acc.z);
        acc.w = fmaf(iv, v.w, acc.w);
    }

    if (do_ln) {
        float s = acc.x + acc.y + acc.z + acc.w;
#pragma unroll
        for (int off = 16; off > 0; off >>= 1) s += __shfl_xor_sync(0xffffffffu, s, off);
        float mu = s * (1.0f / 128.0f);
        float dx = acc.x - mu, dy = acc.y - mu, dz = acc.z - mu, dw = acc.w - mu;
        float q = dx * dx + dy * dy + dz * dz + dw * dw;
#pragma unroll
        for (int off = 16; off > 0; off >>= 1) q += __shfl_xor_sync(0xffffffffu, q, off);
        float rs = rsqrtf(q * (1.0f / 128.0f) + LN_EPS);
        float4 gg = ((const float4*)gma)[lane];
        float4 b2 = ((const float4*)bta)[lane];
        float ox = fmaxf(dx * rs * gg.x + b2.x, 0.f);
        float oy = fmaxf(dy * rs * gg.y + b2.y, 0.f);
        float oz = fmaxf(dz * rs * gg.z + b2.z, 0.f);
        float ow = fmaxf(dw * rs * gg.w + b2.w, 0.f);
        uint32_t h0, l0, h1, l1;
        hilo_pair(ox, oy, h0, l0);
        hilo_pair(oz, ow, h1, l1);
        uint32_t* xh = (uint32_t*)g_Xhi;
        uint32_t* xl = (uint32_t*)g_Xlo;
        xh[row * 64 + lane * 2]     = h0;
        xh[row * 64 + lane * 2 + 1] = h1;
        xl[row * 64 + lane * 2]     = l0;
        xl[row * 64 + lane * 2 + 1] = l1;
    } else {
        ((float4*)ext_out)[row * 32 + lane] = acc;
    }
}

// ---------------- launch ----------------------------------------------------
extern "C" void kernel_launch(void* const* d_in, const int* in_sizes, int n_in,
                              void* d_out, int out_size) {
    const int*   node_ids = (const int*)d_in[0];
    const int*   ei       = (const int*)d_in[1];
    const int*   et       = (const int*)d_in[2];
    const float* emb      = (const float*)d_in[3];
    const float* W1 = (const float*)d_in[4],  *root1 = (const float*)d_in[5];
    const float* b1 = (const float*)d_in[6],  *g1 = (const float*)d_in[7];
    const float* be1 = (const float*)d_in[8];
    const float* W2 = (const float*)d_in[9],  *root2 = (const float*)d_in[10];
    const float* b2 = (const float*)d_in[11], *g2 = (const float*)d_in[12];
    const float* be2 = (const float*)d_in[13];
    const float* W3 = (const float*)d_in[14], *root3 = (const float*)d_in[15];
    const float* b3 = (const float*)d_in[16];
    float* out = (float*)d_out;

    static int smem_set = 0;
    if (!smem_set) {
        cudaFuncSetAttribute(gemm_kernel, cudaFuncAttributeMaxDynamicSharedMemorySize,
                             GEMM_SMEM);
        smem_set = 1;
    }

    const int T = 256;
    const int NB_NODE = (NN + T - 1) / T;   // 196
    dim3 gemm_grid(KC / 64, (NN + 127) / 128);   // 18 x 391

    // edge structure
    zero_all_kernel<<<(NN * RR + T - 1) / T, T>>>();
    count_kernel<<<(EE + T - 1) / T, T>>>(ei, et);
    invert_kernel<<<(NN * RR + T - 1) / T, T>>>();
    deg_partial_kernel<<<NB_NODE, T>>>();
    scan_part_kernel<<<1, T>>>(NB_NODE);
    rowptr_kernel<<<NB_NODE, T>>>();
    fill_kernel<<<(EE + T - 1) / T, T>>>(ei, et);

    gather_kernel<<<(NN * 32 + T - 1) / T, T>>>(node_ids, emb);

    // layer 1
    pack_kernel<<<(KC * DD + T - 1) / T, T>>>(W1, root1);
    gemm_kernel<<<gemm_grid, 128, GEMM_SMEM>>>();
    agg_kernel<<<(NN * 32 + T - 1) / T, T>>>(b1, g1, be1, nullptr, 1);
    // layer 2
    pack_kernel<<<(KC * DD + T - 1) / T, T>>>(W2, root2);
    gemm_kernel<<<gemm_grid, 128, GEMM_SMEM>>>();
    agg_kernel<<<(NN * 32 + T - 1) / T, T>>>(b2, g2, be2, nullptr, 1);
    // layer 3
    pack_kernel<<<(KC * DD + T - 1) / T, T>>>(W3, root3);
    gemm_kernel<<<gemm_grid, 128, GEMM_SMEM>>>();
    agg_kernel<<<(NN * 32 + T - 1) / T, T>>>(b3, nullptr, nullptr, out, 0);

    (void)in_sizes; (void)n_in; (void)out_size;
}

// round 5
// speedup vs baseline: 3.0760x; 1.0425x over previous
#include <cuda_runtime.h>
#include <cuda_bf16.h>
#include <cstdint>

#define NN 50000
#define EE 800000
#define RR 8
#define DD 128
#define KC 1152        // 8*128 relation cols + 128 root cols
#define LN_EPS 1e-5f

// ---------------- scratch (device globals) ---------------------------------
__device__ __align__(16) float g_Y[NN * KC];                 // projections (+root)
__device__ __align__(16) __nv_bfloat16 g_Xhi[NN * DD];       // layer input hi
__device__ __align__(16) __nv_bfloat16 g_Xlo[NN * DD];       // layer input lo
__device__ __align__(16) __nv_bfloat16 g_Bhi[KC * DD];       // packed weights [c][d] hi
__device__ __align__(16) __nv_bfloat16 g_Blo[KC * DD];       // packed weights lo
__device__ float g_inv[NN * RR];                             // cnt then 1/max(cnt,1)
__device__ int   g_deg[NN];
__device__ int   g_cur[NN];
__device__ int   g_rowptr[NN + 1];
__device__ int   g_csr[EE];                                  // src*8 + type
__device__ int   g_part[256];

// ---------------- helpers ---------------------------------------------------
__device__ __forceinline__ uint32_t smem_u32(const void* p) {
    uint32_t a;
    asm("{ .reg .u64 t; cvta.to.shared.u64 t, %1; cvt.u32.u64 %0, t; }"
        : "=r"(a) : "l"(p));
    return a;
}

#define LDSM4(r0, r1, r2, r3, addr) asm volatile( \
    "ldmatrix.sync.aligned.m8n8.x4.shared.b16 {%0,%1,%2,%3}, [%4];" \
    : "=r"(r0), "=r"(r1), "=r"(r2), "=r"(r3) : "r"(addr))

#define MMA_BF16(c, a, b0, b1) asm volatile( \
    "mma.sync.aligned.m16n8k16.row.col.f32.bf16.bf16.f32 " \
    "{%0,%1,%2,%3}, {%4,%5,%6,%7}, {%8,%9}, {%0,%1,%2,%3};" \
    : "+f"((c)[0]), "+f"((c)[1]), "+f"((c)[2]), "+f"((c)[3]) \
    : "r"((a)[0]), "r"((a)[1]), "r"((a)[2]), "r"((a)[3]), "r"(b0), "r"(b1))

__device__ __forceinline__ void hilo_pair(float x, float y,
                                          uint32_t& hp, uint32_t& lp) {
    __nv_bfloat16 hx = __float2bfloat16_rn(x);
    __nv_bfloat16 hy = __float2bfloat16_rn(y);
    __nv_bfloat16 lx = __float2bfloat16_rn(x - __bfloat162float(hx));
    __nv_bfloat16 ly = __float2bfloat16_rn(y - __bfloat162float(hy));
    __nv_bfloat162 h2 = __halves2bfloat162(hx, hy);
    __nv_bfloat162 l2 = __halves2bfloat162(lx, ly);
    hp = *reinterpret_cast<uint32_t*>(&h2);
    lp = *reinterpret_cast<uint32_t*>(&l2);
}

// ---------------- edge-structure kernels ------------------------------------
__global__ void zero_all_kernel() {
    int i = blockIdx.x * blockDim.x + threadIdx.x;
    if (i < NN * RR) g_inv[i] = 0.0f;
    if (i < NN) g_cur[i] = 0;
}

__global__ void count_kernel(const int* __restrict__ ei, const int* __restrict__ et) {
    int e = blockIdx.x * blockDim.x + threadIdx.x;
    if (e < EE) {
        int dst = ei[EE + e];
        atomicAdd(&g_inv[dst * RR + et[e]], 1.0f);
    }
}

// deg[n] = sum_t cnt[n,t]  (reads counts BEFORE inversion)
__global__ void deg_kernel() {
    int n = blockIdx.x * blockDim.x + threadIdx.x;
    if (n >= NN) return;
    float4 a = *(const float4*)(g_inv + n * RR);
    float4 b = *(const float4*)(g_inv + n * RR + 4);
    g_deg[n] = (int)(a.x + a.y + a.z + a.w + b.x + b.y + b.z + b.w);
}

__global__ void invert_kernel() {
    int i = blockIdx.x * blockDim.x + threadIdx.x;
    if (i < NN * RR) g_inv[i] = 1.0f / fmaxf(g_inv[i], 1.0f);
}

__global__ void deg_partial_kernel() {
    __shared__ int s[256];
    int i = blockIdx.x * 256 + threadIdx.x;
    int v = (i < NN) ? g_deg[i] : 0;
    s[threadIdx.x] = v;
    __syncthreads();
    for (int off = 128; off > 0; off >>= 1) {
        if (threadIdx.x < off) s[threadIdx.x] += s[threadIdx.x + off];
        __syncthreads();
    }
    if (threadIdx.x == 0) g_part[blockIdx.x] = s[0];
}

__global__ void scan_part_kernel(int nblocks) {
    __shared__ int s[512];
    int t = threadIdx.x;
    int v = (t < nblocks) ? g_part[t] : 0;
    s[t] = v;
    __syncthreads();
    int acc = v;
    for (int off = 1; off < 256; off <<= 1) {
        int add = (t >= off) ? s[t - off] : 0;
        __syncthreads();
        s[t] = acc = acc + add;
        __syncthreads();
    }
    if (t < nblocks) g_part[t] = s[t] - v;
}

__global__ void rowptr_kernel() {
    __shared__ int s[512];
    int t = threadIdx.x;
    int i = blockIdx.x * 256 + t;
    int v = (i < NN) ? g_deg[i] : 0;
    s[t] = v;
    __syncthreads();
    int acc = v;
    for (int off = 1; off < 256; off <<= 1) {
        int add = (t >= off) ? s[t - off] : 0;
        __syncthreads();
        s[t] = acc = acc + add;
        __syncthreads();
    }
    if (i < NN) g_rowptr[i] = g_part[blockIdx.x] + s[t] - v;
    if (i == NN) g_rowptr[NN] = EE;
}

__global__ void fill_kernel(const int* __restrict__ ei, const int* __restrict__ et) {
    int e = blockIdx.x * blockDim.x + threadIdx.x;
    if (e < EE) {
        int dst = ei[EE + e];
        int p = atomicAdd(&g_cur[dst], 1);
        g_csr[g_rowptr[dst] + p] = (ei[e] << 3) | et[e];
    }
}

// ---------------- gather + convert ------------------------------------------
__global__ void gather_kernel(const int* __restrict__ node_ids,
                              const float* __restrict__ emb) {
    int idx = blockIdx.x * blockDim.x + threadIdx.x;
    if (idx >= NN * 32) return;
    int n = idx >> 5;
    int c4 = idx & 31;
    int src = node_ids[n];
    float4 v = ((const float4*)emb)[src * 32 + c4];
    uint32_t h0, l0, h1, l1;
    hilo_pair(v.x, v.y, h0, l0);
    hilo_pair(v.z, v.w, h1, l1);
    uint32_t* xh = (uint32_t*)g_Xhi;
    uint32_t* xl = (uint32_t*)g_Xlo;
    xh[n * 64 + c4 * 2]     = h0;
    xh[n * 64 + c4 * 2 + 1] = h1;
    xl[n * 64 + c4 * 2]     = l0;
    xl[n * 64 + c4 * 2 + 1] = l1;
}

// pack W[r][d][o], root[d][o] -> B[c][d] bf16 hi/lo
__global__ void pack_kernel(const float* __restrict__ W, const float* __restrict__ root) {
    int idx = blockIdx.x * blockDim.x + threadIdx.x;
    if (idx >= KC * DD) return;
    int c = idx >> 7;
    int d = idx & 127;
    float v;
    if (c < RR * DD) v = W[((c >> 7) * DD + d) * DD + (c & 127)];
    else             v = root[d * DD + (c - RR * DD)];
    __nv_bfloat16 h = __float2bfloat16_rn(v);
    __nv_bfloat16 l = __float2bfloat16_rn(v - __bfloat162float(h));
    g_Bhi[idx] = h;
    g_Blo[idx] = l;
}

// ---------------- HMMA GEMM: Y[N,1152] = X[N,128] @ B^T ---------------------
// CTA tile: 256 rows x 128 cols, 8 warps (4x2), warp tile 64x64, K=128 resident.
#define LDS_ROW 272          // 136 halves per smem row (pad 128+8)
#define SM_AHI 0
#define SM_ALO 69632
#define SM_BHI 139264
#define SM_BLO 174080
#define GEMM_SMEM 208896

__global__ __launch_bounds__(256, 1) void gemm_kernel() {
    extern __shared__ char smem[];
    const uint32_t sb = smem_u32(smem);
    const int tid = threadIdx.x, wid = tid >> 5, lane = tid & 31;
    const int cb = blockIdx.x * 128;
    const int nb = blockIdx.y * 256;

    // A tile: 256 rows x 128 halves (hi & lo), 16 uint4 per row
#pragma unroll
    for (int i = 0; i < 16; i++) {
        int idx = tid + i * 256;
        int row = idx >> 4;
        int ch = idx & 15;
        int gn = nb + row;
        uint4 vh = make_uint4(0, 0, 0, 0), vl = vh;
        if (gn < NN) {
            vh = ((const uint4*)g_Xhi)[gn * 16 + ch];
            vl = ((const uint4*)g_Xlo)[gn * 16 + ch];
        }
        *(uint4*)(smem + SM_AHI + row * LDS_ROW + ch * 16) = vh;
        *(uint4*)(smem + SM_ALO + row * LDS_ROW + ch * 16) = vl;
    }
    // B tile: 128 rows x 128 halves
#pragma unroll
    for (int i = 0; i < 8; i++) {
        int idx = tid + i * 256;
        int row = idx >> 4;
        int ch = idx & 15;
        uint4 vh = ((const uint4*)g_Bhi)[(cb + row) * 16 + ch];
        uint4 vl = ((const uint4*)g_Blo)[(cb + row) * 16 + ch];
        *(uint4*)(smem + SM_BHI + row * LDS_ROW + ch * 16) = vh;
        *(uint4*)(smem + SM_BLO + row * LDS_ROW + ch * 16) = vl;
    }
    __syncthreads();

    const int wm = (wid >> 1) * 64;
    const int wn = (wid & 1) * 64;

    const uint32_t aRow = wm + (lane & 15);
    const uint32_t aOff = (lane >> 4) * 16;
    const uint32_t aHi = sb + SM_AHI + aRow * LDS_ROW + aOff;
    const uint32_t aLo = aHi + (SM_ALO - SM_AHI);
    const uint32_t bRow = wn + ((lane >> 4) & 1) * 8 + (lane & 7);
    const uint32_t bOff = ((lane >> 3) & 1) * 16;
    const uint32_t bHi = sb + SM_BHI + bRow * LDS_ROW + bOff;
    const uint32_t bLo = bHi + (SM_BLO - SM_BHI);

    float acc[4][8][4];
#pragma unroll
    for (int mt = 0; mt < 4; mt++)
#pragma unroll
        for (int nt = 0; nt < 8; nt++)
#pragma unroll
            for (int k = 0; k < 4; k++) acc[mt][nt][k] = 0.f;

#pragma unroll
    for (int ks = 0; ks < 8; ks++) {
        uint32_t ah[4][4], al[4][4], bh[4][4], bl[4][4];
#pragma unroll
        for (int mt = 0; mt < 4; mt++) {
            uint32_t o = mt * (16 * LDS_ROW) + ks * 32;
            LDSM4(ah[mt][0], ah[mt][1], ah[mt][2], ah[mt][3], aHi + o);
            LDSM4(al[mt][0], al[mt][1], al[mt][2], al[mt][3], aLo + o);
        }
#pragma unroll
        for (int bt = 0; bt < 4; bt++) {
            uint32_t o = bt * (16 * LDS_ROW) + ks * 32;
            LDSM4(bh[bt][0], bh[bt][1], bh[bt][2], bh[bt][3], bHi + o);
            LDSM4(bl[bt][0], bl[bt][1], bl[bt][2], bl[bt][3], bLo + o);
        }
#pragma unroll
        for (int mt = 0; mt < 4; mt++) {
#pragma unroll
            for (int nt = 0; nt < 8; nt++) {
                int bt = nt >> 1, bi = (nt & 1) * 2;
                MMA_BF16(acc[mt][nt], ah[mt], bh[bt][bi], bh[bt][bi + 1]);
                MMA_BF16(acc[mt][nt], ah[mt], bl[bt][bi], bl[bt][bi + 1]);
                MMA_BF16(acc[mt][nt], al[mt], bh[bt][bi], bh[bt][bi + 1]);
            }
        }
    }

    // epilogue: write fp32 to g_Y
    const int r0 = nb + wm + (lane >> 2);
    const int c0 = cb + wn + (lane & 3) * 2;
#pragma unroll
    for (int mt = 0; mt < 4; mt++) {
#pragma unroll
        for (int nt = 0; nt < 8; nt++) {
            int r = r0 + mt * 16;
            int c = c0 + nt * 8;
            if (r < NN)
                *(float2*)(g_Y + (size_t)r * KC + c) =
                    make_float2(acc[mt][nt][0], acc[mt][nt][1]);
            if (r + 8 < NN)
                *(float2*)(g_Y + (size_t)(r + 8) * KC + c) =
                    make_float2(acc[mt][nt][2], acc[mt][nt][3]);
        }
    }
}

// ---------------- CSR aggregation (+ fused LN+ReLU + bf16 split) -----------
__global__ __launch_bounds__(256)
void agg_kernel(const float* __restrict__ bias, const float* __restrict__ gma,
                const float* __restrict__ bta, float* __restrict__ ext_out,
                int do_ln) {
    int gt = blockIdx.x * blockDim.x + threadIdx.x;
    int row = gt >> 5;
    if (row >= NN) return;
    int lane = gt & 31;

    float4 acc = *(const float4*)(g_Y + (size_t)row * KC + RR * DD + lane * 4);
    float4 bb = ((const float4*)bias)[lane];
    acc.x += bb.x; acc.y += bb.y; acc.z += bb.z; acc.w += bb.w;

    int beg = g_rowptr[row], end = g_rowptr[row + 1];
    for (int i = beg; i < end; i++) {
        int pk = __ldg(&g_csr[i]);
        int src = pk >> 3, t = pk & 7;
        float iv = __ldg(&g_inv[(row << 3) + t]);
        float4 v = __ldg((const float4*)(g_Y + (size_t)src * KC + (t << 7)) + lane);
        acc.x = fmaf(iv, v.x, acc.x);
        acc.y = fmaf(iv, v.y, acc.y);
        acc.z = fmaf(iv, v.z, acc.z);
        acc.w = fmaf(iv, v.w, acc.w);
    }

    if (do_ln) {
        float s = acc.x + acc.y + acc.z + acc.w;
#pragma unroll
        for (int off = 16; off > 0; off >>= 1) s += __shfl_xor_sync(0xffffffffu, s, off);
        float mu = s * (1.0f / 128.0f);
        float dx = acc.x - mu, dy = acc.y - mu, dz = acc.z - mu, dw = acc.w - mu;
        float q = dx * dx + dy * dy + dz * dz + dw * dw;
#pragma unroll
        for (int off = 16; off > 0; off >>= 1) q += __shfl_xor_sync(0xffffffffu, q, off);
        float rs = rsqrtf(q * (1.0f / 128.0f) + LN_EPS);
        float4 gg = ((const float4*)gma)[lane];
        float4 b2 = ((const float4*)bta)[lane];
        float ox = fmaxf(dx * rs * gg.x + b2.x, 0.f);
        float oy = fmaxf(dy * rs * gg.y + b2.y, 0.f);
        float oz = fmaxf(dz * rs * gg.z + b2.z, 0.f);
        float ow = fmaxf(dw * rs * gg.w + b2.w, 0.f);
        uint32_t h0, l0, h1, l1;
        hilo_pair(ox, oy, h0, l0);
        hilo_pair(oz, ow, h1, l1);
        uint32_t* xh = (uint32_t*)g_Xhi;
        uint32_t* xl = (uint32_t*)g_Xlo;
        xh[row * 64 + lane * 2]     = h0;
        xh[row * 64 + lane * 2 + 1] = h1;
        xl[row * 64 + lane * 2]     = l0;
        xl[row * 64 + lane * 2 + 1] = l1;
    } else {
        ((float4*)ext_out)[row * 32 + lane] = acc;
    }
}

// ---------------- launch ----------------------------------------------------
extern "C" void kernel_launch(void* const* d_in, const int* in_sizes, int n_in,
                              void* d_out, int out_size) {
    const int*   node_ids = (const int*)d_in[0];
    const int*   ei       = (const int*)d_in[1];
    const int*   et       = (const int*)d_in[2];
    const float* emb      = (const float*)d_in[3];
    const float* W1 = (const float*)d_in[4],  *root1 = (const float*)d_in[5];
    const float* b1 = (const float*)d_in[6],  *g1 = (const float*)d_in[7];
    const float* be1 = (const float*)d_in[8];
    const float* W2 = (const float*)d_in[9],  *root2 = (const float*)d_in[10];
    const float* b2 = (const float*)d_in[11], *g2 = (const float*)d_in[12];
    const float* be2 = (const float*)d_in[13];
    const float* W3 = (const float*)d_in[14], *root3 = (const float*)d_in[15];
    const float* b3 = (const float*)d_in[16];
    float* out = (float*)d_out;

    static int smem_set = 0;
    if (!smem_set) {
        cudaFuncSetAttribute(gemm_kernel, cudaFuncAttributeMaxDynamicSharedMemorySize,
                             GEMM_SMEM);
        smem_set = 1;
    }

    const int T = 256;
    const int NB_NODE = (NN + T - 1) / T;          // 196
    dim3 gemm_grid(KC / 128, (NN + 255) / 256);    // 9 x 196

    // launch order chosen so gemm_kernel is the 4th launch (ncu capture slot)
    gather_kernel<<<(NN * 32 + T - 1) / T, T>>>(node_ids, emb);
    pack_kernel<<<(KC * DD + T - 1) / T, T>>>(W1, root1);
    zero_all_kernel<<<(NN * RR + T - 1) / T, T>>>();
    gemm_kernel<<<gemm_grid, T, GEMM_SMEM>>>();            // layer-1 GEMM (profiled)

    count_kernel<<<(EE + T - 1) / T, T>>>(ei, et);
    deg_kernel<<<NB_NODE, T>>>();
    invert_kernel<<<(NN * RR + T - 1) / T, T>>>();
    deg_partial_kernel<<<NB_NODE, T>>>();
    scan_part_kernel<<<1, T>>>(NB_NODE);
    rowptr_kernel<<<NB_NODE, T>>>();
    fill_kernel<<<(EE + T - 1) / T, T>>>(ei, et);

    agg_kernel<<<(NN * 32 + T - 1) / T, T>>>(b1, g1, be1, nullptr, 1);
    // layer 2
    pack_kernel<<<(KC * DD + T - 1) / T, T>>>(W2, root2);
    gemm_kernel<<<gemm_grid, T, GEMM_SMEM>>>();
    agg_kernel<<<(NN * 32 + T - 1) / T, T>>>(b2, g2, be2, nullptr, 1);
    // layer 3
    pack_kernel<<<(KC * DD + T - 1) / T, T>>>(W3, root3);
    gemm_kernel<<<gemm_grid, T, GEMM_SMEM>>>();
    agg_kernel<<<(NN * 32 + T - 1) / T, T>>>(b3, nullptr, nullptr, out, 0);

    (void)in_sizes; (void)n_in; (void)out_size;
}

// round 6
// speedup vs baseline: 3.0946x; 1.0061x over previous
#include <cuda_runtime.h>
#include <cuda_bf16.h>
#include <cstdint>

#define NN 50000
#define EE 800000
#define RR 8
#define DD 128
#define KC 1152        // 8*128 relation cols + 128 root cols
#define LN_EPS 1e-5f

// ---------------- scratch (device globals) ---------------------------------
__device__ __align__(16) float g_Y[NN * KC];                 // projections (+root)
__device__ __align__(16) __nv_bfloat16 g_Xhi[NN * DD];       // layer input hi
__device__ __align__(16) __nv_bfloat16 g_Xlo[NN * DD];       // layer input lo
__device__ __align__(16) __nv_bfloat16 g_Bhi[KC * DD];       // packed weights [c][d] hi
__device__ __align__(16) __nv_bfloat16 g_Blo[KC * DD];       // packed weights lo
__device__ float g_inv[NN * RR];                             // cnt then 1/max(cnt,1)
__device__ int   g_deg[NN];
__device__ int   g_cur[NN];
__device__ int   g_rowptr[NN + 1];
__device__ int   g_csr[EE];                                  // src*8 + type
__device__ int   g_part[256];

// ---------------- helpers ---------------------------------------------------
__device__ __forceinline__ uint32_t smem_u32(const void* p) {
    uint32_t a;
    asm("{ .reg .u64 t; cvta.to.shared.u64 t, %1; cvt.u32.u64 %0, t; }"
        : "=r"(a) : "l"(p));
    return a;
}

#define LDSM4(r0, r1, r2, r3, addr) asm volatile( \
    "ldmatrix.sync.aligned.m8n8.x4.shared.b16 {%0,%1,%2,%3}, [%4];" \
    : "=r"(r0), "=r"(r1), "=r"(r2), "=r"(r3) : "r"(addr))

#define MMA_BF16(c, a, b0, b1) asm volatile( \
    "mma.sync.aligned.m16n8k16.row.col.f32.bf16.bf16.f32 " \
    "{%0,%1,%2,%3}, {%4,%5,%6,%7}, {%8,%9}, {%0,%1,%2,%3};" \
    : "+f"((c)[0]), "+f"((c)[1]), "+f"((c)[2]), "+f"((c)[3]) \
    : "r"((a)[0]), "r"((a)[1]), "r"((a)[2]), "r"((a)[3]), "r"(b0), "r"(b1))

__device__ __forceinline__ void hilo_pair(float x, float y,
                                          uint32_t& hp, uint32_t& lp) {
    __nv_bfloat16 hx = __float2bfloat16_rn(x);
    __nv_bfloat16 hy = __float2bfloat16_rn(y);
    __nv_bfloat16 lx = __float2bfloat16_rn(x - __bfloat162float(hx));
    __nv_bfloat16 ly = __float2bfloat16_rn(y - __bfloat162float(hy));
    __nv_bfloat162 h2 = __halves2bfloat162(hx, hy);
    __nv_bfloat162 l2 = __halves2bfloat162(lx, ly);
    hp = *reinterpret_cast<uint32_t*>(&h2);
    lp = *reinterpret_cast<uint32_t*>(&l2);
}

// ---------------- edge-structure kernels ------------------------------------
__global__ void zero_all_kernel() {
    int i = blockIdx.x * blockDim.x + threadIdx.x;
    if (i < NN * RR) g_inv[i] = 0.0f;
    if (i < NN) g_cur[i] = 0;
}

__global__ void count_kernel(const int* __restrict__ ei, const int* __restrict__ et) {
    int e = blockIdx.x * blockDim.x + threadIdx.x;
    if (e < EE) {
        int dst = ei[EE + e];
        atomicAdd(&g_inv[dst * RR + et[e]], 1.0f);
    }
}

__global__ void deg_kernel() {
    int n = blockIdx.x * blockDim.x + threadIdx.x;
    if (n >= NN) return;
    float4 a = *(const float4*)(g_inv + n * RR);
    float4 b = *(const float4*)(g_inv + n * RR + 4);
    g_deg[n] = (int)(a.x + a.y + a.z + a.w + b.x + b.y + b.z + b.w);
}

__global__ void invert_kernel() {
    int i = blockIdx.x * blockDim.x + threadIdx.x;
    if (i < NN * RR) g_inv[i] = 1.0f / fmaxf(g_inv[i], 1.0f);
}

__global__ void deg_partial_kernel() {
    __shared__ int s[256];
    int i = blockIdx.x * 256 + threadIdx.x;
    int v = (i < NN) ? g_deg[i] : 0;
    s[threadIdx.x] = v;
    __syncthreads();
    for (int off = 128; off > 0; off >>= 1) {
        if (threadIdx.x < off) s[threadIdx.x] += s[threadIdx.x + off];
        __syncthreads();
    }
    if (threadIdx.x == 0) g_part[blockIdx.x] = s[0];
}

__global__ void scan_part_kernel(int nblocks) {
    __shared__ int s[512];
    int t = threadIdx.x;
    int v = (t < nblocks) ? g_part[t] : 0;
    s[t] = v;
    __syncthreads();
    int acc = v;
    for (int off = 1; off < 256; off <<= 1) {
        int add = (t >= off) ? s[t - off] : 0;
        __syncthreads();
        s[t] = acc = acc + add;
        __syncthreads();
    }
    if (t < nblocks) g_part[t] = s[t] - v;
}

__global__ void rowptr_kernel() {
    __shared__ int s[512];
    int t = threadIdx.x;
    int i = blockIdx.x * 256 + t;
    int v = (i < NN) ? g_deg[i] : 0;
    s[t] = v;
    __syncthreads();
    int acc = v;
    for (int off = 1; off < 256; off <<= 1) {
        int add = (t >= off) ? s[t - off] : 0;
        __syncthreads();
        s[t] = acc = acc + add;
        __syncthreads();
    }
    if (i < NN) g_rowptr[i] = g_part[blockIdx.x] + s[t] - v;
    if (i == NN) g_rowptr[NN] = EE;
}

__global__ void fill_kernel(const int* __restrict__ ei, const int* __restrict__ et) {
    int e = blockIdx.x * blockDim.x + threadIdx.x;
    if (e < EE) {
        int dst = ei[EE + e];
        int p = atomicAdd(&g_cur[dst], 1);
        g_csr[g_rowptr[dst] + p] = (ei[e] << 3) | et[e];
    }
}

// ---------------- gather + convert ------------------------------------------
__global__ void gather_kernel(const int* __restrict__ node_ids,
                              const float* __restrict__ emb) {
    int idx = blockIdx.x * blockDim.x + threadIdx.x;
    if (idx >= NN * 32) return;
    int n = idx >> 5;
    int c4 = idx & 31;
    int src = node_ids[n];
    float4 v = ((const float4*)emb)[src * 32 + c4];
    uint32_t h0, l0, h1, l1;
    hilo_pair(v.x, v.y, h0, l0);
    hilo_pair(v.z, v.w, h1, l1);
    uint32_t* xh = (uint32_t*)g_Xhi;
    uint32_t* xl = (uint32_t*)g_Xlo;
    xh[n * 64 + c4 * 2]     = h0;
    xh[n * 64 + c4 * 2 + 1] = h1;
    xl[n * 64 + c4 * 2]     = l0;
    xl[n * 64 + c4 * 2 + 1] = l1;
}

// pack W[r][d][o], root[d][o] -> B[c][d] bf16 hi/lo
__global__ void pack_kernel(const float* __restrict__ W, const float* __restrict__ root) {
    int idx = blockIdx.x * blockDim.x + threadIdx.x;
    if (idx >= KC * DD) return;
    int c = idx >> 7;
    int d = idx & 127;
    float v;
    if (c < RR * DD) v = W[((c >> 7) * DD + d) * DD + (c & 127)];
    else             v = root[d * DD + (c - RR * DD)];
    __nv_bfloat16 h = __float2bfloat16_rn(v);
    __nv_bfloat16 l = __float2bfloat16_rn(v - __bfloat162float(h));
    g_Bhi[idx] = h;
    g_Blo[idx] = l;
}

// ---------------- HMMA GEMM: Y[N,1152] = X[N,128] @ B^T ---------------------
// CTA tile: 256 rows x 128 cols, 16 warps (8x2), warp tile 32x64, K=128 resident.
#define LDS_ROW 272          // 136 halves per smem row (pad 128+8)
#define SM_AHI 0
#define SM_ALO 69632
#define SM_BHI 139264
#define SM_BLO 174080
#define GEMM_SMEM 208896

__global__ __launch_bounds__(512, 1) void gemm_kernel() {
    extern __shared__ char smem[];
    const uint32_t sb = smem_u32(smem);
    const int tid = threadIdx.x, wid = tid >> 5, lane = tid & 31;
    const int cb = blockIdx.x * 128;
    const int nb = blockIdx.y * 256;

    // A tile: 256 rows x 128 halves (hi & lo), 16 uint4 per row
#pragma unroll
    for (int i = 0; i < 8; i++) {
        int idx = tid + i * 512;
        int row = idx >> 4;
        int ch = idx & 15;
        int gn = nb + row;
        uint4 vh = make_uint4(0, 0, 0, 0), vl = vh;
        if (gn < NN) {
            vh = ((const uint4*)g_Xhi)[gn * 16 + ch];
            vl = ((const uint4*)g_Xlo)[gn * 16 + ch];
        }
        *(uint4*)(smem + SM_AHI + row * LDS_ROW + ch * 16) = vh;
        *(uint4*)(smem + SM_ALO + row * LDS_ROW + ch * 16) = vl;
    }
    // B tile: 128 rows x 128 halves
#pragma unroll
    for (int i = 0; i < 4; i++) {
        int idx = tid + i * 512;
        int row = idx >> 4;
        int ch = idx & 15;
        uint4 vh = ((const uint4*)g_Bhi)[(cb + row) * 16 + ch];
        uint4 vl = ((const uint4*)g_Blo)[(cb + row) * 16 + ch];
        *(uint4*)(smem + SM_BHI + row * LDS_ROW + ch * 16) = vh;
        *(uint4*)(smem + SM_BLO + row * LDS_ROW + ch * 16) = vl;
    }
    __syncthreads();

    // 16 warps: 8 along M (32 rows each), 2 along N (64 cols each)
    const int wm = (wid >> 1) * 32;
    const int wn = (wid & 1) * 64;

    const uint32_t aRow = wm + (lane & 15);
    const uint32_t aOff = (lane >> 4) * 16;
    const uint32_t aHi = sb + SM_AHI + aRow * LDS_ROW + aOff;
    const uint32_t aLo = aHi + (SM_ALO - SM_AHI);
    const uint32_t bRow = wn + ((lane >> 4) & 1) * 8 + (lane & 7);
    const uint32_t bOff = ((lane >> 3) & 1) * 16;
    const uint32_t bHi = sb + SM_BHI + bRow * LDS_ROW + bOff;
    const uint32_t bLo = bHi + (SM_BLO - SM_BHI);

    float acc[2][8][4];
#pragma unroll
    for (int mt = 0; mt < 2; mt++)
#pragma unroll
        for (int nt = 0; nt < 8; nt++)
#pragma unroll
            for (int k = 0; k < 4; k++) acc[mt][nt][k] = 0.f;

#pragma unroll
    for (int ks = 0; ks < 8; ks++) {
        uint32_t ah[2][4], al[2][4];
#pragma unroll
        for (int mt = 0; mt < 2; mt++) {
            uint32_t o = mt * (16 * LDS_ROW) + ks * 32;
            LDSM4(ah[mt][0], ah[mt][1], ah[mt][2], ah[mt][3], aHi + o);
            LDSM4(al[mt][0], al[mt][1], al[mt][2], al[mt][3], aLo + o);
        }
#pragma unroll
        for (int bt = 0; bt < 4; bt++) {
            uint32_t bh[4], bl[4];
            uint32_t o = bt * (16 * LDS_ROW) + ks * 32;
            LDSM4(bh[0], bh[1], bh[2], bh[3], bHi + o);
            LDSM4(bl[0], bl[1], bl[2], bl[3], bLo + o);
#pragma unroll
            for (int mt = 0; mt < 2; mt++) {
#pragma unroll
                for (int ni = 0; ni < 2; ni++) {
                    int nt = bt * 2 + ni;
                    int bi = ni * 2;
                    MMA_BF16(acc[mt][nt], ah[mt], bh[bi], bh[bi + 1]);
                    MMA_BF16(acc[mt][nt], ah[mt], bl[bi], bl[bi + 1]);
                    MMA_BF16(acc[mt][nt], al[mt], bh[bi], bh[bi + 1]);
                }
            }
        }
    }

    // epilogue: write fp32 to g_Y
    const int r0 = nb + wm + (lane >> 2);
    const int c0 = cb + wn + (lane & 3) * 2;
#pragma unroll
    for (int mt = 0; mt < 2; mt++) {
#pragma unroll
        for (int nt = 0; nt < 8; nt++) {
            int r = r0 + mt * 16;
            int c = c0 + nt * 8;
            if (r < NN)
                *(float2*)(g_Y + (size_t)r * KC + c) =
                    make_float2(acc[mt][nt][0], acc[mt][nt][1]);
            if (r + 8 < NN)
                *(float2*)(g_Y + (size_t)(r + 8) * KC + c) =
                    make_float2(acc[mt][nt][2], acc[mt][nt][3]);
        }
    }
}

// ---------------- CSR aggregation (+ fused LN+ReLU + bf16 split) -----------
__global__ __launch_bounds__(256)
void agg_kernel(const float* __restrict__ bias, const float* __restrict__ gma,
                const float* __restrict__ bta, float* __restrict__ ext_out,
                int do_ln) {
    int gt = blockIdx.x * blockDim.x + threadIdx.x;
    int row = gt >> 5;
    if (row >= NN) return;
    int lane = gt & 31;

    float4 acc = *(const float4*)(g_Y + (size_t)row * KC + RR * DD + lane * 4);
    float4 bb = ((const float4*)bias)[lane];
    acc.x += bb.x; acc.y += bb.y; acc.z += bb.z; acc.w += bb.w;

    int beg = g_rowptr[row], end = g_rowptr[row + 1];
    for (int i = beg; i < end; i++) {
        int pk = __ldg(&g_csr[i]);
        int src = pk >> 3, t = pk & 7;
        float iv = __ldg(&g_inv[(row << 3) + t]);
        float4 v = __ldg((const float4*)(g_Y + (size_t)src * KC + (t << 7)) + lane);
        acc.x = fmaf(iv, v.x, acc.x);
        acc.y = fmaf(iv, v.y, acc.y);
        acc.z = fmaf(iv, v.z, acc.z);
        acc.w = fmaf(iv, v.w, acc.w);
    }

    if (do_ln) {
        float s = acc.x + acc.y + acc.z + acc.w;
#pragma unroll
        for (int off = 16; off > 0; off >>= 1) s += __shfl_xor_sync(0xffffffffu, s, off);
        float mu = s * (1.0f / 128.0f);
        float dx = acc.x - mu, dy = acc.y - mu, dz = acc.z - mu, dw = acc.w - mu;
        float q = dx * dx + dy * dy + dz * dz + dw * dw;
#pragma unroll
        for (int off = 16; off > 0; off >>= 1) q += __shfl_xor_sync(0xffffffffu, q, off);
        float rs = rsqrtf(q * (1.0f / 128.0f) + LN_EPS);
        float4 gg = ((const float4*)gma)[lane];
        float4 b2 = ((const float4*)bta)[lane];
        float ox = fmaxf(dx * rs * gg.x + b2.x, 0.f);
        float oy = fmaxf(dy * rs * gg.y + b2.y, 0.f);
        float oz = fmaxf(dz * rs * gg.z + b2.z, 0.f);
        float ow = fmaxf(dw * rs * gg.w + b2.w, 0.f);
        uint32_t h0, l0, h1, l1;
        hilo_pair(ox, oy, h0, l0);
        hilo_pair(oz, ow, h1, l1);
        uint32_t* xh = (uint32_t*)g_Xhi;
        uint32_t* xl = (uint32_t*)g_Xlo;
        xh[row * 64 + lane * 2]     = h0;
        xh[row * 64 + lane * 2 + 1] = h1;
        xl[row * 64 + lane * 2]     = l0;
        xl[row * 64 + lane * 2 + 1] = l1;
    } else {
        ((float4*)ext_out)[row * 32 + lane] = acc;
    }
}

// ---------------- launch ----------------------------------------------------
extern "C" void kernel_launch(void* const* d_in, const int* in_sizes, int n_in,
                              void* d_out, int out_size) {
    const int*   node_ids = (const int*)d_in[0];
    const int*   ei       = (const int*)d_in[1];
    const int*   et       = (const int*)d_in[2];
    const float* emb      = (const float*)d_in[3];
    const float* W1 = (const float*)d_in[4],  *root1 = (const float*)d_in[5];
    const float* b1 = (const float*)d_in[6],  *g1 = (const float*)d_in[7];
    const float* be1 = (const float*)d_in[8];
    const float* W2 = (const float*)d_in[9],  *root2 = (const float*)d_in[10];
    const float* b2 = (const float*)d_in[11], *g2 = (const float*)d_in[12];
    const float* be2 = (const float*)d_in[13];
    const float* W3 = (const float*)d_in[14], *root3 = (const float*)d_in[15];
    const float* b3 = (const float*)d_in[16];
    float* out = (float*)d_out;

    static int smem_set = 0;
    if (!smem_set) {
        cudaFuncSetAttribute(gemm_kernel, cudaFuncAttributeMaxDynamicSharedMemorySize,
                             GEMM_SMEM);
        smem_set = 1;
    }

    const int T = 256;
    const int NB_NODE = (NN + T - 1) / T;          // 196
    dim3 gemm_grid(KC / 128, (NN + 255) / 256);    // 9 x 196

    // launch order chosen so gemm_kernel is the 4th launch (ncu capture slot)
    gather_kernel<<<(NN * 32 + T - 1) / T, T>>>(node_ids, emb);
    pack_kernel<<<(KC * DD + T - 1) / T, T>>>(W1, root1);
    zero_all_kernel<<<(NN * RR + T - 1) / T, T>>>();
    gemm_kernel<<<gemm_grid, 512, GEMM_SMEM>>>();          // layer-1 GEMM (profiled)

    count_kernel<<<(EE + T - 1) / T, T>>>(ei, et);
    deg_kernel<<<NB_NODE, T>>>();
    invert_kernel<<<(NN * RR + T - 1) / T, T>>>();
    deg_partial_kernel<<<NB_NODE, T>>>();
    scan_part_kernel<<<1, T>>>(NB_NODE);
    rowptr_kernel<<<NB_NODE, T>>>();
    fill_kernel<<<(EE + T - 1) / T, T>>>(ei, et);

    agg_kernel<<<(NN * 32 + T - 1) / T, T>>>(b1, g1, be1, nullptr, 1);
    // layer 2
    pack_kernel<<<(KC * DD + T - 1) / T, T>>>(W2, root2);
    gemm_kernel<<<gemm_grid, 512, GEMM_SMEM>>>();
    agg_kernel<<<(NN * 32 + T - 1) / T, T>>>(b2, g2, be2, nullptr, 1);
    // layer 3
    pack_kernel<<<(KC * DD + T - 1) / T, T>>>(W3, root3);
    gemm_kernel<<<gemm_grid, 512, GEMM_SMEM>>>();
    agg_kernel<<<(NN * 32 + T - 1) / T, T>>>(b3, nullptr, nullptr, out, 0);

    (void)in_sizes; (void)n_in; (void)out_size;
}

// round 7
// speedup vs baseline: 3.8363x; 1.2397x over previous
#include <cuda_runtime.h>
#include <cuda_fp16.h>
#include <cstdint>

#define NN 50000
#define EE 800000
#define RR 8
#define DD 128
#define KC 1152        // 8*128 relation cols + 128 root cols
#define LN_EPS 1e-5f

// ---------------- scratch (device globals) ---------------------------------
__device__ __align__(16) float g_Y[NN * KC];            // projections (+root)
__device__ __align__(16) __half g_Xh[NN * DD];          // layer input (fp16)
__device__ __align__(16) __half g_Whi[KC * DD];         // packed weights [c][d] hi
__device__ __align__(16) __half g_Wlo[KC * DD];         // packed weights lo
__device__ float g_inv[NN * RR];                        // cnt then 1/max(cnt,1)
__device__ int   g_deg[NN];
__device__ int   g_cur[NN];
__device__ int   g_rowptr[NN + 1];
__device__ int   g_csr[EE];                             // src*8 + type
__device__ int   g_part[256];

// ---------------- helpers ---------------------------------------------------
__device__ __forceinline__ uint32_t smem_u32(const void* p) {
    uint32_t a;
    asm("{ .reg .u64 t; cvta.to.shared.u64 t, %1; cvt.u32.u64 %0, t; }"
        : "=r"(a) : "l"(p));
    return a;
}

#define LDSM4(r0, r1, r2, r3, addr) asm volatile( \
    "ldmatrix.sync.aligned.m8n8.x4.shared.b16 {%0,%1,%2,%3}, [%4];" \
    : "=r"(r0), "=r"(r1), "=r"(r2), "=r"(r3) : "r"(addr))

#define MMA_F16(c, a, b0, b1) asm volatile( \
    "mma.sync.aligned.m16n8k16.row.col.f32.f16.f16.f32 " \
    "{%0,%1,%2,%3}, {%4,%5,%6,%7}, {%8,%9}, {%0,%1,%2,%3};" \
    : "+f"((c)[0]), "+f"((c)[1]), "+f"((c)[2]), "+f"((c)[3]) \
    : "r"((a)[0]), "r"((a)[1]), "r"((a)[2]), "r"((a)[3]), "r"(b0), "r"(b1))

// ---------------- edge-structure kernels ------------------------------------
__global__ void zero_all_kernel() {
    int i = blockIdx.x * blockDim.x + threadIdx.x;
    if (i < NN * RR) g_inv[i] = 0.0f;
    if (i < NN) g_cur[i] = 0;
}

__global__ void count_kernel(const int* __restrict__ ei, const int* __restrict__ et) {
    int e = blockIdx.x * blockDim.x + threadIdx.x;
    if (e < EE) {
        int dst = ei[EE + e];
        atomicAdd(&g_inv[dst * RR + et[e]], 1.0f);
    }
}

__global__ void deg_kernel() {
    int n = blockIdx.x * blockDim.x + threadIdx.x;
    if (n >= NN) return;
    float4 a = *(const float4*)(g_inv + n * RR);
    float4 b = *(const float4*)(g_inv + n * RR + 4);
    g_deg[n] = (int)(a.x + a.y + a.z + a.w + b.x + b.y + b.z + b.w);
}

__global__ void invert_kernel() {
    int i = blockIdx.x * blockDim.x + threadIdx.x;
    if (i < NN * RR) g_inv[i] = 1.0f / fmaxf(g_inv[i], 1.0f);
}

__global__ void deg_partial_kernel() {
    __shared__ int s[256];
    int i = blockIdx.x * 256 + threadIdx.x;
    int v = (i < NN) ? g_deg[i] : 0;
    s[threadIdx.x] = v;
    __syncthreads();
    for (int off = 128; off > 0; off >>= 1) {
        if (threadIdx.x < off) s[threadIdx.x] += s[threadIdx.x + off];
        __syncthreads();
    }
    if (threadIdx.x == 0) g_part[blockIdx.x] = s[0];
}

__global__ void scan_part_kernel(int nblocks) {
    __shared__ int s[512];
    int t = threadIdx.x;
    int v = (t < nblocks) ? g_part[t] : 0;
    s[t] = v;
    __syncthreads();
    int acc = v;
    for (int off = 1; off < 256; off <<= 1) {
        int add = (t >= off) ? s[t - off] : 0;
        __syncthreads();
        s[t] = acc = acc + add;
        __syncthreads();
    }
    if (t < nblocks) g_part[t] = s[t] - v;
}

__global__ void rowptr_kernel() {
    __shared__ int s[512];
    int t = threadIdx.x;
    int i = blockIdx.x * 256 + t;
    int v = (i < NN) ? g_deg[i] : 0;
    s[t] = v;
    __syncthreads();
    int acc = v;
    for (int off = 1; off < 256; off <<= 1) {
        int add = (t >= off) ? s[t - off] : 0;
        __syncthreads();
        s[t] = acc = acc + add;
        __syncthreads();
    }
    if (i < NN) g_rowptr[i] = g_part[blockIdx.x] + s[t] - v;
    if (i == NN) g_rowptr[NN] = EE;
}

__global__ void fill_kernel(const int* __restrict__ ei, const int* __restrict__ et) {
    int e = blockIdx.x * blockDim.x + threadIdx.x;
    if (e < EE) {
        int dst = ei[EE + e];
        int p = atomicAdd(&g_cur[dst], 1);
        g_csr[g_rowptr[dst] + p] = (ei[e] << 3) | et[e];
    }
}

// ---------------- gather + convert ------------------------------------------
__global__ void gather_kernel(const int* __restrict__ node_ids,
                              const float* __restrict__ emb) {
    int idx = blockIdx.x * blockDim.x + threadIdx.x;
    if (idx >= NN * 32) return;
    int n = idx >> 5;
    int c4 = idx & 31;
    int src = node_ids[n];
    float4 v = ((const float4*)emb)[src * 32 + c4];
    __half2 h0 = __floats2half2_rn(v.x, v.y);
    __half2 h1 = __floats2half2_rn(v.z, v.w);
    uint32_t* xh = (uint32_t*)g_Xh;
    xh[n * 64 + c4 * 2]     = *reinterpret_cast<uint32_t*>(&h0);
    xh[n * 64 + c4 * 2 + 1] = *reinterpret_cast<uint32_t*>(&h1);
}

// pack W[r][d][o], root[d][o] -> W[c][d] fp16 hi/lo
__global__ void pack_kernel(const float* __restrict__ W, const float* __restrict__ root) {
    int idx = blockIdx.x * blockDim.x + threadIdx.x;
    if (idx >= KC * DD) return;
    int c = idx >> 7;
    int d = idx & 127;
    float v;
    if (c < RR * DD) v = W[((c >> 7) * DD + d) * DD + (c & 127)];
    else             v = root[d * DD + (c - RR * DD)];
    __half h = __float2half_rn(v);
    __half l = __float2half_rn(v - __half2float(h));
    g_Whi[idx] = h;
    g_Wlo[idx] = l;
}

// ---------------- HMMA GEMM: Y[N,1152] = X[N,128] @ W^T ---------------------
// CTA tile: 256 rows x 128 cols, 16 warps (8x2), warp tile 32x64, K=128 resident.
// 2 MMA passes: Xh * Whi + Xh * Wlo  (= Xh * W; dropped term ~2^-12)
#define LDS_ROW 272          // 136 halves per smem row (pad 128+8)
#define SM_A   0
#define SM_BHI 69632
#define SM_BLO 104448
#define GEMM_SMEM 139264

__global__ __launch_bounds__(512, 1) void gemm_kernel() {
    extern __shared__ char smem[];
    const uint32_t sb = smem_u32(smem);
    const int tid = threadIdx.x, wid = tid >> 5, lane = tid & 31;
    const int cb = blockIdx.x * 128;
    const int nb = blockIdx.y * 256;

    // A tile: 256 rows x 128 halves, 16 uint4 per row
#pragma unroll
    for (int i = 0; i < 8; i++) {
        int idx = tid + i * 512;
        int row = idx >> 4;
        int ch = idx & 15;
        int gn = nb + row;
        uint4 v = make_uint4(0, 0, 0, 0);
        if (gn < NN) v = ((const uint4*)g_Xh)[gn * 16 + ch];
        *(uint4*)(smem + SM_A + row * LDS_ROW + ch * 16) = v;
    }
    // B tiles: 128 rows x 128 halves, hi & lo
#pragma unroll
    for (int i = 0; i < 4; i++) {
        int idx = tid + i * 512;
        int row = idx >> 4;
        int ch = idx & 15;
        uint4 vh = ((const uint4*)g_Whi)[(cb + row) * 16 + ch];
        uint4 vl = ((const uint4*)g_Wlo)[(cb + row) * 16 + ch];
        *(uint4*)(smem + SM_BHI + row * LDS_ROW + ch * 16) = vh;
        *(uint4*)(smem + SM_BLO + row * LDS_ROW + ch * 16) = vl;
    }
    __syncthreads();

    // 16 warps: 8 along M (32 rows each), 2 along N (64 cols each)
    const int wm = (wid >> 1) * 32;
    const int wn = (wid & 1) * 64;

    const uint32_t aRow = wm + (lane & 15);
    const uint32_t aOff = (lane >> 4) * 16;
    const uint32_t aAd = sb + SM_A + aRow * LDS_ROW + aOff;
    const uint32_t bRow = wn + ((lane >> 4) & 1) * 8 + (lane & 7);
    const uint32_t bOff = ((lane >> 3) & 1) * 16;
    const uint32_t bHi = sb + SM_BHI + bRow * LDS_ROW + bOff;
    const uint32_t bLo = bHi + (SM_BLO - SM_BHI);

    float acc[2][8][4];
#pragma unroll
    for (int mt = 0; mt < 2; mt++)
#pragma unroll
        for (int nt = 0; nt < 8; nt++)
#pragma unroll
            for (int k = 0; k < 4; k++) acc[mt][nt][k] = 0.f;

#pragma unroll
    for (int ks = 0; ks < 8; ks++) {
        uint32_t ah[2][4];
#pragma unroll
        for (int mt = 0; mt < 2; mt++) {
            uint32_t o = mt * (16 * LDS_ROW) + ks * 32;
            LDSM4(ah[mt][0], ah[mt][1], ah[mt][2], ah[mt][3], aAd + o);
        }
#pragma unroll
        for (int bt = 0; bt < 4; bt++) {
            uint32_t bh[4], bl[4];
            uint32_t o = bt * (16 * LDS_ROW) + ks * 32;
            LDSM4(bh[0], bh[1], bh[2], bh[3], bHi + o);
            LDSM4(bl[0], bl[1], bl[2], bl[3], bLo + o);
#pragma unroll
            for (int mt = 0; mt < 2; mt++) {
#pragma unroll
                for (int ni = 0; ni < 2; ni++) {
                    int nt = bt * 2 + ni;
                    int bi = ni * 2;
                    MMA_F16(acc[mt][nt], ah[mt], bh[bi], bh[bi + 1]);
                    MMA_F16(acc[mt][nt], ah[mt], bl[bi], bl[bi + 1]);
                }
            }
        }
    }

    // epilogue: write fp32 to g_Y
    const int r0 = nb + wm + (lane >> 2);
    const int c0 = cb + wn + (lane & 3) * 2;
#pragma unroll
    for (int mt = 0; mt < 2; mt++) {
#pragma unroll
        for (int nt = 0; nt < 8; nt++) {
            int r = r0 + mt * 16;
            int c = c0 + nt * 8;
            if (r < NN)
                *(float2*)(g_Y + (size_t)r * KC + c) =
                    make_float2(acc[mt][nt][0], acc[mt][nt][1]);
            if (r + 8 < NN)
                *(float2*)(g_Y + (size_t)(r + 8) * KC + c) =
                    make_float2(acc[mt][nt][2], acc[mt][nt][3]);
        }
    }
}

// ---------------- CSR aggregation (+ fused LN+ReLU + fp16 convert) ---------
__global__ __launch_bounds__(256)
void agg_kernel(const float* __restrict__ bias, const float* __restrict__ gma,
                const float* __restrict__ bta, float* __restrict__ ext_out,
                int do_ln) {
    int gt = blockIdx.x * blockDim.x + threadIdx.x;
    int row = gt >> 5;
    if (row >= NN) return;
    int lane = gt & 31;

    float4 acc = *(const float4*)(g_Y + (size_t)row * KC + RR * DD + lane * 4);
    float4 bb = ((const float4*)bias)[lane];
    acc.x += bb.x; acc.y += bb.y; acc.z += bb.z; acc.w += bb.w;

    int beg = g_rowptr[row], end = g_rowptr[row + 1];
    for (int i = beg; i < end; i++) {
        int pk = __ldg(&g_csr[i]);
        int src = pk >> 3, t = pk & 7;
        float iv = __ldg(&g_inv[(row << 3) + t]);
        float4 v = __ldg((const float4*)(g_Y + (size_t)src * KC + (t << 7)) + lane);
        acc.x = fmaf(iv, v.x, acc.x);
        acc.y = fmaf(iv, v.y, acc.y);
        acc.z = fmaf(iv, v.z, acc.z);
        acc.w = fmaf(iv, v.w, acc.w);
    }

    if (do_ln) {
        float s = acc.x + acc.y + acc.z + acc.w;
#pragma unroll
        for (int off = 16; off > 0; off >>= 1) s += __shfl_xor_sync(0xffffffffu, s, off);
        float mu = s * (1.0f / 128.0f);
        float dx = acc.x - mu, dy = acc.y - mu, dz = acc.z - mu, dw = acc.w - mu;
        float q = dx * dx + dy * dy + dz * dz + dw * dw;
#pragma unroll
        for (int off = 16; off > 0; off >>= 1) q += __shfl_xor_sync(0xffffffffu, q, off);
        float rs = rsqrtf(q * (1.0f / 128.0f) + LN_EPS);
        float4 gg = ((const float4*)gma)[lane];
        float4 b2 = ((const float4*)bta)[lane];
        float ox = fmaxf(dx * rs * gg.x + b2.x, 0.f);
        float oy = fmaxf(dy * rs * gg.y + b2.y, 0.f);
        float oz = fmaxf(dz * rs * gg.z + b2.z, 0.f);
        float ow = fmaxf(dw * rs * gg.w + b2.w, 0.f);
        __half2 h0 = __floats2half2_rn(ox, oy);
        __half2 h1 = __floats2half2_rn(oz, ow);
        uint32_t* xh = (uint32_t*)g_Xh;
        xh[row * 64 + lane * 2]     = *reinterpret_cast<uint32_t*>(&h0);
        xh[row * 64 + lane * 2 + 1] = *reinterpret_cast<uint32_t*>(&h1);
    } else {
        ((float4*)ext_out)[row * 32 + lane] = acc;
    }
}

// ---------------- launch ----------------------------------------------------
extern "C" void kernel_launch(void* const* d_in, const int* in_sizes, int n_in,
                              void* d_out, int out_size) {
    const int*   node_ids = (const int*)d_in[0];
    const int*   ei       = (const int*)d_in[1];
    const int*   et       = (const int*)d_in[2];
    const float* emb      = (const float*)d_in[3];
    const float* W1 = (const float*)d_in[4],  *root1 = (const float*)d_in[5];
    const float* b1 = (const float*)d_in[6],  *g1 = (const float*)d_in[7];
    const float* be1 = (const float*)d_in[8];
    const float* W2 = (const float*)d_in[9],  *root2 = (const float*)d_in[10];
    const float* b2 = (const float*)d_in[11], *g2 = (const float*)d_in[12];
    const float* be2 = (const float*)d_in[13];
    const float* W3 = (const float*)d_in[14], *root3 = (const float*)d_in[15];
    const float* b3 = (const float*)d_in[16];
    float* out = (float*)d_out;

    static int smem_set = 0;
    if (!smem_set) {
        cudaFuncSetAttribute(gemm_kernel, cudaFuncAttributeMaxDynamicSharedMemorySize,
                             GEMM_SMEM);
        smem_set = 1;
    }

    const int T = 256;
    const int NB_NODE = (NN + T - 1) / T;          // 196
    dim3 gemm_grid(KC / 128, (NN + 255) / 256);    // 9 x 196

    // launch order chosen so gemm_kernel is the 4th launch (ncu capture slot)
    gather_kernel<<<(NN * 32 + T - 1) / T, T>>>(node_ids, emb);
    pack_kernel<<<(KC * DD + T - 1) / T, T>>>(W1, root1);
    zero_all_kernel<<<(NN * RR + T - 1) / T, T>>>();
    gemm_kernel<<<gemm_grid, 512, GEMM_SMEM>>>();          // layer-1 GEMM (profiled)

    count_kernel<<<(EE + T - 1) / T, T>>>(ei, et);
    deg_kernel<<<NB_NODE, T>>>();
    invert_kernel<<<(NN * RR + T - 1) / T, T>>>();
    deg_partial_kernel<<<NB_NODE, T>>>();
    scan_part_kernel<<<1, T>>>(NB_NODE);
    rowptr_kernel<<<NB_NODE, T>>>();
    fill_kernel<<<(EE + T - 1) / T, T>>>(ei, et);

    agg_kernel<<<(NN * 32 + T - 1) / T, T>>>(b1, g1, be1, nullptr, 1);
    // layer 2
    pack_kernel<<<(KC * DD + T - 1) / T, T>>>(W2, root2);
    gemm_kernel<<<gemm_grid, 512, GEMM_SMEM>>>();
    agg_kernel<<<(NN * 32 + T - 1) / T, T>>>(b2, g2, be2, nullptr, 1);
    // layer 3
    pack_kernel<<<(KC * DD + T - 1) / T, T>>>(W3, root3);
    gemm_kernel<<<gemm_grid, 512, GEMM_SMEM>>>();
    agg_kernel<<<(NN * 32 + T - 1) / T, T>>>(b3, nullptr, nullptr, out, 0);

    (void)in_sizes; (void)n_in; (void)out_size;
}

// round 9
// speedup vs baseline: 3.9029x; 1.0174x over previous
#include <cuda_runtime.h>
#include <cuda_fp16.h>
#include <cstdint>

#define NN 50000
#define EE 800000
#define RR 8
#define DD 128
#define KC 1152        // 8*128 relation cols + 128 root cols
#define LN_EPS 1e-5f

// ---------------- scratch (device globals) ---------------------------------
__device__ __align__(16) float g_Y[NN * KC];            // projections (+root)
__device__ __align__(16) __half g_Xh[NN * DD];          // layer input (fp16)
__device__ __align__(16) __half g_Whi[KC * DD];         // packed weights [c][d] hi
__device__ __align__(16) __half g_Wlo[KC * DD];         // packed weights lo
__device__ float g_inv[NN * RR];                        // cnt then 1/max(cnt,1)
__device__ int   g_deg[NN];
__device__ int   g_cur[NN];
__device__ int   g_rowptr[NN + 1];
__device__ int   g_csr[EE];                             // src*8 + type
__device__ int   g_part[256];

// ---------------- helpers ---------------------------------------------------
__device__ __forceinline__ uint32_t smem_u32(const void* p) {
    uint32_t a;
    asm("{ .reg .u64 t; cvta.to.shared.u64 t, %1; cvt.u32.u64 %0, t; }"
        : "=r"(a) : "l"(p));
    return a;
}

#define LDSM4(r0, r1, r2, r3, addr) asm volatile( \
    "ldmatrix.sync.aligned.m8n8.x4.shared.b16 {%0,%1,%2,%3}, [%4];" \
    : "=r"(r0), "=r"(r1), "=r"(r2), "=r"(r3) : "r"(addr))

#define MMA_F16(c, a, b0, b1) asm volatile( \
    "mma.sync.aligned.m16n8k16.row.col.f32.f16.f16.f32 " \
    "{%0,%1,%2,%3}, {%4,%5,%6,%7}, {%8,%9}, {%0,%1,%2,%3};" \
    : "+f"((c)[0]), "+f"((c)[1]), "+f"((c)[2]), "+f"((c)[3]) \
    : "r"((a)[0]), "r"((a)[1]), "r"((a)[2]), "r"((a)[3]), "r"(b0), "r"(b1))

// ---------------- edge-structure kernels ------------------------------------
__global__ void zero_all_kernel() {
    int i = blockIdx.x * blockDim.x + threadIdx.x;
    if (i < NN * RR) g_inv[i] = 0.0f;
    if (i < NN) g_cur[i] = 0;
}

__global__ void count_kernel(const int* __restrict__ ei, const int* __restrict__ et) {
    int e = blockIdx.x * blockDim.x + threadIdx.x;
    if (e < EE) {
        int dst = ei[EE + e];
        atomicAdd(&g_inv[dst * RR + et[e]], 1.0f);
    }
}

__global__ void deg_kernel() {
    int n = blockIdx.x * blockDim.x + threadIdx.x;
    if (n >= NN) return;
    float4 a = *(const float4*)(g_inv + n * RR);
    float4 b = *(const float4*)(g_inv + n * RR + 4);
    g_deg[n] = (int)(a.x + a.y + a.z + a.w + b.x + b.y + b.z + b.w);
}

__global__ void invert_kernel() {
    int i = blockIdx.x * blockDim.x + threadIdx.x;
    if (i < NN * RR) g_inv[i] = 1.0f / fmaxf(g_inv[i], 1.0f);
}

__global__ void deg_partial_kernel() {
    __shared__ int s[256];
    int i = blockIdx.x * 256 + threadIdx.x;
    int v = (i < NN) ? g_deg[i] : 0;
    s[threadIdx.x] = v;
    __syncthreads();
    for (int off = 128; off > 0; off >>= 1) {
        if (threadIdx.x < off) s[threadIdx.x] += s[threadIdx.x + off];
        __syncthreads();
    }
    if (threadIdx.x == 0) g_part[blockIdx.x] = s[0];
}

__global__ void scan_part_kernel(int nblocks) {
    __shared__ int s[512];
    int t = threadIdx.x;
    int v = (t < nblocks) ? g_part[t] : 0;
    s[t] = v;
    __syncthreads();
    int acc = v;
    for (int off = 1; off < 256; off <<= 1) {
        int add = (t >= off) ? s[t - off] : 0;
        __syncthreads();
        s[t] = acc = acc + add;
        __syncthreads();
    }
    if (t < nblocks) g_part[t] = s[t] - v;
}

__global__ void rowptr_kernel() {
    __shared__ int s[512];
    int t = threadIdx.x;
    int i = blockIdx.x * 256 + t;
    int v = (i < NN) ? g_deg[i] : 0;
    s[t] = v;
    __syncthreads();
    int acc = v;
    for (int off = 1; off < 256; off <<= 1) {
        int add = (t >= off) ? s[t - off] : 0;
        __syncthreads();
        s[t] = acc = acc + add;
        __syncthreads();
    }
    if (i < NN) g_rowptr[i] = g_part[blockIdx.x] + s[t] - v;
    if (i == NN) g_rowptr[NN] = EE;
}

__global__ void fill_kernel(const int* __restrict__ ei, const int* __restrict__ et) {
    int e = blockIdx.x * blockDim.x + threadIdx.x;
    if (e < EE) {
        int dst = ei[EE + e];
        int p = atomicAdd(&g_cur[dst], 1);
        g_csr[g_rowptr[dst] + p] = (ei[e] << 3) | et[e];
    }
}

// ---------------- gather + convert ------------------------------------------
__global__ void gather_kernel(const int* __restrict__ node_ids,
                              const float* __restrict__ emb) {
    int idx = blockIdx.x * blockDim.x + threadIdx.x;
    if (idx >= NN * 32) return;
    int n = idx >> 5;
    int c4 = idx & 31;
    int src = node_ids[n];
    float4 v = ((const float4*)emb)[src * 32 + c4];
    __half2 h0 = __floats2half2_rn(v.x, v.y);
    __half2 h1 = __floats2half2_rn(v.z, v.w);
    uint32_t* xh = (uint32_t*)g_Xh;
    xh[n * 64 + c4 * 2]     = *reinterpret_cast<uint32_t*>(&h0);
    xh[n * 64 + c4 * 2 + 1] = *reinterpret_cast<uint32_t*>(&h1);
}

// pack W[r][d][o], root[d][o] -> W[c][d] fp16 hi/lo
__global__ void pack_kernel(const float* __restrict__ W, const float* __restrict__ root) {
    int idx = blockIdx.x * blockDim.x + threadIdx.x;
    if (idx >= KC * DD) return;
    int c = idx >> 7;
    int d = idx & 127;
    float v;
    if (c < RR * DD) v = W[((c >> 7) * DD + d) * DD + (c & 127)];
    else             v = root[d * DD + (c - RR * DD)];
    __half h = __float2half_rn(v);
    __half l = __float2half_rn(v - __half2float(h));
    g_Whi[idx] = h;
    g_Wlo[idx] = l;
}

// ---------------- HMMA GEMM: Y[N,1152] = X[N,128] @ W^T ---------------------
// CTA tile: 128 rows x 128 cols, 8 warps (4x2), warp tile 32x64, K=128 resident.
// 102 KB smem -> 2 CTAs/SM so memory phases of one CTA overlap the other's
// mainloop. 2 MMA passes: Xh*Whi + Xh*Wlo (= Xh*W; dropped term ~2^-12).
#define LDS_ROW 272          // 136 halves per smem row (pad 128+8)
#define SM_A   0
#define SM_BHI 34816
#define SM_BLO 69632
#define GEMM_SMEM 104448

__global__ __launch_bounds__(256, 2) void gemm_kernel() {
    extern __shared__ char smem[];
    const uint32_t sb = smem_u32(smem);
    const int tid = threadIdx.x, wid = tid >> 5, lane = tid & 31;
    const int cb = blockIdx.x * 128;
    const int nb = blockIdx.y * 128;

    // A tile: 128 rows x 128 halves, 16 uint4 per row
#pragma unroll
    for (int i = 0; i < 8; i++) {
        int idx = tid + i * 256;
        int row = idx >> 4;
        int ch = idx & 15;
        int gn = nb + row;
        uint4 v = make_uint4(0, 0, 0, 0);
        if (gn < NN) v = ((const uint4*)g_Xh)[gn * 16 + ch];
        *(uint4*)(smem + SM_A + row * LDS_ROW + ch * 16) = v;
    }
    // B tiles: 128 rows x 128 halves, hi & lo
#pragma unroll
    for (int i = 0; i < 8; i++) {
        int idx = tid + i * 256;
        int row = idx >> 4;
        int ch = idx & 15;
        uint4 vh = ((const uint4*)g_Whi)[(cb + row) * 16 + ch];
        uint4 vl = ((const uint4*)g_Wlo)[(cb + row) * 16 + ch];
        *(uint4*)(smem + SM_BHI + row * LDS_ROW + ch * 16) = vh;
        *(uint4*)(smem + SM_BLO + row * LDS_ROW + ch * 16) = vl;
    }
    __syncthreads();

    // 8 warps: 4 along M (32 rows each), 2 along N (64 cols each)
    const int wm = (wid >> 1) * 32;
    const int wn = (wid & 1) * 64;

    const uint32_t aRow = wm + (lane & 15);
    const uint32_t aOff = (lane >> 4) * 16;
    const uint32_t aAd = sb + SM_A + aRow * LDS_ROW + aOff;
    const uint32_t bRow = wn + ((lane >> 4) & 1) * 8 + (lane & 7);
    const uint32_t bOff = ((lane >> 3) & 1) * 16;
    const uint32_t bHi = sb + SM_BHI + bRow * LDS_ROW + bOff;
    const uint32_t bLo = bHi + (SM_BLO - SM_BHI);

    float acc[2][8][4];
#pragma unroll
    for (int mt = 0; mt < 2; mt++)
#pragma unroll
        for (int nt = 0; nt < 8; nt++)
#pragma unroll
            for (int k = 0; k < 4; k++) acc[mt][nt][k] = 0.f;

#pragma unroll
    for (int ks = 0; ks < 8; ks++) {
        uint32_t ah[2][4];
#pragma unroll
        for (int mt = 0; mt < 2; mt++) {
            uint32_t o = mt * (16 * LDS_ROW) + ks * 32;
            LDSM4(ah[mt][0], ah[mt][1], ah[mt][2], ah[mt][3], aAd + o);
        }
#pragma unroll
        for (int bt = 0; bt < 4; bt++) {
            uint32_t bh[4], bl[4];
            uint32_t o = bt * (16 * LDS_ROW) + ks * 32;
            LDSM4(bh[0], bh[1], bh[2], bh[3], bHi + o);
            LDSM4(bl[0], bl[1], bl[2], bl[3], bLo + o);
#pragma unroll
            for (int mt = 0; mt < 2; mt++) {
#pragma unroll
                for (int ni = 0; ni < 2; ni++) {
                    int nt = bt * 2 + ni;
                    int bi = ni * 2;
                    MMA_F16(acc[mt][nt], ah[mt], bh[bi], bh[bi + 1]);
                    MMA_F16(acc[mt][nt], ah[mt], bl[bi], bl[bi + 1]);
                }
            }
        }
    }

    // epilogue: write fp32 to g_Y
    const int r0 = nb + wm + (lane >> 2);
    const int c0 = cb + wn + (lane & 3) * 2;
#pragma unroll
    for (int mt = 0; mt < 2; mt++) {
#pragma unroll
        for (int nt = 0; nt < 8; nt++) {
            int r = r0 + mt * 16;
            int c = c0 + nt * 8;
            if (r < NN)
                *(float2*)(g_Y + (size_t)r * KC + c) =
                    make_float2(acc[mt][nt][0], acc[mt][nt][1]);
            if (r + 8 < NN)
                *(float2*)(g_Y + (size_t)(r + 8) * KC + c) =
                    make_float2(acc[mt][nt][2], acc[mt][nt][3]);
        }
    }
}

// ---------------- CSR aggregation (+ fused LN+ReLU + fp16 convert) ---------
__global__ __launch_bounds__(256)
void agg_kernel(const float* __restrict__ bias, const float* __restrict__ gma,
                const float* __restrict__ bta, float* __restrict__ ext_out,
                int do_ln) {
    int gt = blockIdx.x * blockDim.x + threadIdx.x;
    int row = gt >> 5;
    if (row >= NN) return;
    int lane = gt & 31;

    float4 acc = *(const float4*)(g_Y + (size_t)row * KC + RR * DD + lane * 4);
    float4 bb = ((const float4*)bias)[lane];
    acc.x += bb.x; acc.y += bb.y; acc.z += bb.z; acc.w += bb.w;

    int beg = g_rowptr[row], end = g_rowptr[row + 1];
    for (int i = beg; i < end; i++) {
        int pk = __ldg(&g_csr[i]);
        int src = pk >> 3, t = pk & 7;
        float iv = __ldg(&g_inv[(row << 3) + t]);
        float4 v = __ldg((const float4*)(g_Y + (size_t)src * KC + (t << 7)) + lane);
        acc.x = fmaf(iv, v.x, acc.x);
        acc.y = fmaf(iv, v.y, acc.y);
        acc.z = fmaf(iv, v.z, acc.z);
        acc.w = fmaf(iv, v.w, acc.w);
    }

    if (do_ln) {
        float s = acc.x + acc.y + acc.z + acc.w;
#pragma unroll
        for (int off = 16; off > 0; off >>= 1) s += __shfl_xor_sync(0xffffffffu, s, off);
        float mu = s * (1.0f / 128.0f);
        float dx = acc.x - mu, dy = acc.y - mu, dz = acc.z - mu, dw = acc.w - mu;
        float q = dx * dx + dy * dy + dz * dz + dw * dw;
#pragma unroll
        for (int off = 16; off > 0; off >>= 1) q += __shfl_xor_sync(0xffffffffu, q, off);
        float rs = rsqrtf(q * (1.0f / 128.0f) + LN_EPS);
        float4 gg = ((const float4*)gma)[lane];
        float4 b2 = ((const float4*)bta)[lane];
        float ox = fmaxf(dx * rs * gg.x + b2.x, 0.f);
        float oy = fmaxf(dy * rs * gg.y + b2.y, 0.f);
        float oz = fmaxf(dz * rs * gg.z + b2.z, 0.f);
        float ow = fmaxf(dw * rs * gg.w + b2.w, 0.f);
        __half2 h0 = __floats2half2_rn(ox, oy);
        __half2 h1 = __floats2half2_rn(oz, ow);
        uint32_t* xh = (uint32_t*)g_Xh;
        xh[row * 64 + lane * 2]     = *reinterpret_cast<uint32_t*>(&h0);
        xh[row * 64 + lane * 2 + 1] = *reinterpret_cast<uint32_t*>(&h1);
    } else {
        ((float4*)ext_out)[row * 32 + lane] = acc;
    }
}

// ---------------- launch ----------------------------------------------------
extern "C" void kernel_launch(void* const* d_in, const int* in_sizes, int n_in,
                              void* d_out, int out_size) {
    const int*   node_ids = (const int*)d_in[0];
    const int*   ei       = (const int*)d_in[1];
    const int*   et       = (const int*)d_in[2];
    const float* emb      = (const float*)d_in[3];
    const float* W1 = (const float*)d_in[4],  *root1 = (const float*)d_in[5];
    const float* b1 = (const float*)d_in[6],  *g1 = (const float*)d_in[7];
    const float* be1 = (const float*)d_in[8];
    const float* W2 = (const float*)d_in[9],  *root2 = (const float*)d_in[10];
    const float* b2 = (const float*)d_in[11], *g2 = (const float*)d_in[12];
    const float* be2 = (const float*)d_in[13];
    const float* W3 = (const float*)d_in[14], *root3 = (const float*)d_in[15];
    const float* b3 = (const float*)d_in[16];
    float* out = (float*)d_out;

    static int smem_set = 0;
    if (!smem_set) {
        cudaFuncSetAttribute(gemm_kernel, cudaFuncAttributeMaxDynamicSharedMemorySize,
                             GEMM_SMEM);
        smem_set = 1;
    }

    const int T = 256;
    const int NB_NODE = (NN + T - 1) / T;          // 196
    dim3 gemm_grid(KC / 128, (NN + 127) / 128);    // 9 x 391

    // launch order chosen so gemm_kernel is the 4th launch (ncu capture slot)
    gather_kernel<<<(NN * 32 + T - 1) / T, T>>>(node_ids, emb);
    pack_kernel<<<(KC * DD + T - 1) / T, T>>>(W1, root1);
    zero_all_kernel<<<(NN * RR + T - 1) / T, T>>>();
    gemm_kernel<<<gemm_grid, T, GEMM_SMEM>>>();            // layer-1 GEMM (profiled)

    count_kernel<<<(EE + T - 1) / T, T>>>(ei, et);
    deg_kernel<<<NB_NODE, T>>>();
    invert_kernel<<<(NN * RR + T - 1) / T, T>>>();
    deg_partial_kernel<<<NB_NODE, T>>>();
    scan_part_kernel<<<1, T>>>(NB_NODE);
    rowptr_kernel<<<NB_NODE, T>>>();
    fill_kernel<<<(EE + T - 1) / T, T>>>(ei, et);

    agg_kernel<<<(NN * 32 + T - 1) / T, T>>>(b1, g1, be1, nullptr, 1);
    // layer 2
    pack_kernel<<<(KC * DD + T - 1) / T, T>>>(W2, root2);
    gemm_kernel<<<gemm_grid, T, GEMM_SMEM>>>();
    agg_kernel<<<(NN * 32 + T - 1) / T, T>>>(b2, g2, be2, nullptr, 1);
    // layer 3
    pack_kernel<<<(KC * DD + T - 1) / T, T>>>(W3, root3);
    gemm_kernel<<<gemm_grid, T, GEMM_SMEM>>>();
    agg_kernel<<<(NN * 32 + T - 1) / T, T>>>(b3, nullptr, nullptr, out, 0);

    (void)in_sizes; (void)n_in; (void)out_size;
}

// round 10
// speedup vs baseline: 4.5200x; 1.1581x over previous
#include <cuda_runtime.h>
#include <cuda_fp16.h>
#include <cstdint>

#define NN 50000
#define EE 800000
#define RR 8
#define DD 128
#define KC 1152        // 8*128 relation cols + 128 root cols
#define LN_EPS 1e-5f

// ---------------- scratch (device globals) ---------------------------------
__device__ __align__(16) __half g_Y[NN * KC];           // projections (+root), fp16
__device__ __align__(16) __half g_Xh[NN * DD];          // layer input (fp16)
__device__ __align__(16) __half g_Whi[KC * DD];         // packed weights [c][d] hi
__device__ __align__(16) __half g_Wlo[KC * DD];         // packed weights lo
__device__ float g_inv[NN * RR];                        // cnt then 1/max(cnt,1)
__device__ int   g_deg[NN];
__device__ int   g_cur[NN];
__device__ int   g_rowptr[NN + 1];
__device__ int   g_csr[EE];                             // src*8 + type
__device__ int   g_part[256];

// ---------------- helpers ---------------------------------------------------
__device__ __forceinline__ uint32_t smem_u32(const void* p) {
    uint32_t a;
    asm("{ .reg .u64 t; cvta.to.shared.u64 t, %1; cvt.u32.u64 %0, t; }"
        : "=r"(a) : "l"(p));
    return a;
}

#define LDSM4(r0, r1, r2, r3, addr) asm volatile( \
    "ldmatrix.sync.aligned.m8n8.x4.shared.b16 {%0,%1,%2,%3}, [%4];" \
    : "=r"(r0), "=r"(r1), "=r"(r2), "=r"(r3) : "r"(addr))

#define MMA_F16(c, a, b0, b1) asm volatile( \
    "mma.sync.aligned.m16n8k16.row.col.f32.f16.f16.f32 " \
    "{%0,%1,%2,%3}, {%4,%5,%6,%7}, {%8,%9}, {%0,%1,%2,%3};" \
    : "+f"((c)[0]), "+f"((c)[1]), "+f"((c)[2]), "+f"((c)[3]) \
    : "r"((a)[0]), "r"((a)[1]), "r"((a)[2]), "r"((a)[3]), "r"(b0), "r"(b1))

// ---------------- edge-structure kernels ------------------------------------
__global__ void zero_all_kernel() {
    int i = blockIdx.x * blockDim.x + threadIdx.x;
    if (i < NN * RR) g_inv[i] = 0.0f;
    if (i < NN) g_cur[i] = 0;
}

__global__ void count_kernel(const int* __restrict__ ei, const int* __restrict__ et) {
    int e = blockIdx.x * blockDim.x + threadIdx.x;
    if (e < EE) {
        int dst = ei[EE + e];
        atomicAdd(&g_inv[dst * RR + et[e]], 1.0f);
    }
}

// deg[n] = sum_t cnt[n,t]; then inv[n,t] = 1/max(cnt,1)  (one pass)
__global__ void deg_inv_kernel() {
    int n = blockIdx.x * blockDim.x + threadIdx.x;
    if (n >= NN) return;
    float4 a = *(const float4*)(g_inv + n * RR);
    float4 b = *(const float4*)(g_inv + n * RR + 4);
    g_deg[n] = (int)(a.x + a.y + a.z + a.w + b.x + b.y + b.z + b.w);
    a.x = 1.0f / fmaxf(a.x, 1.0f); a.y = 1.0f / fmaxf(a.y, 1.0f);
    a.z = 1.0f / fmaxf(a.z, 1.0f); a.w = 1.0f / fmaxf(a.w, 1.0f);
    b.x = 1.0f / fmaxf(b.x, 1.0f); b.y = 1.0f / fmaxf(b.y, 1.0f);
    b.z = 1.0f / fmaxf(b.z, 1.0f); b.w = 1.0f / fmaxf(b.w, 1.0f);
    *(float4*)(g_inv + n * RR) = a;
    *(float4*)(g_inv + n * RR + 4) = b;
}

__global__ void deg_partial_kernel() {
    __shared__ int s[256];
    int i = blockIdx.x * 256 + threadIdx.x;
    int v = (i < NN) ? g_deg[i] : 0;
    s[threadIdx.x] = v;
    __syncthreads();
    for (int off = 128; off > 0; off >>= 1) {
        if (threadIdx.x < off) s[threadIdx.x] += s[threadIdx.x + off];
        __syncthreads();
    }
    if (threadIdx.x == 0) g_part[blockIdx.x] = s[0];
}

__global__ void scan_part_kernel(int nblocks) {
    __shared__ int s[512];
    int t = threadIdx.x;
    int v = (t < nblocks) ? g_part[t] : 0;
    s[t] = v;
    __syncthreads();
    int acc = v;
    for (int off = 1; off < 256; off <<= 1) {
        int add = (t >= off) ? s[t - off] : 0;
        __syncthreads();
        s[t] = acc = acc + add;
        __syncthreads();
    }
    if (t < nblocks) g_part[t] = s[t] - v;
}

__global__ void rowptr_kernel() {
    __shared__ int s[512];
    int t = threadIdx.x;
    int i = blockIdx.x * 256 + t;
    int v = (i < NN) ? g_deg[i] : 0;
    s[t] = v;
    __syncthreads();
    int acc = v;
    for (int off = 1; off < 256; off <<= 1) {
        int add = (t >= off) ? s[t - off] : 0;
        __syncthreads();
        s[t] = acc = acc + add;
        __syncthreads();
    }
    if (i < NN) g_rowptr[i] = g_part[blockIdx.x] + s[t] - v;
    if (i == NN) g_rowptr[NN] = EE;
}

__global__ void fill_kernel(const int* __restrict__ ei, const int* __restrict__ et) {
    int e = blockIdx.x * blockDim.x + threadIdx.x;
    if (e < EE) {
        int dst = ei[EE + e];
        int p = atomicAdd(&g_cur[dst], 1);
        g_csr[g_rowptr[dst] + p] = (ei[e] << 3) | et[e];
    }
}

// ---------------- gather + convert ------------------------------------------
__global__ void gather_kernel(const int* __restrict__ node_ids,
                              const float* __restrict__ emb) {
    int idx = blockIdx.x * blockDim.x + threadIdx.x;
    if (idx >= NN * 32) return;
    int n = idx >> 5;
    int c4 = idx & 31;
    int src = node_ids[n];
    float4 v = ((const float4*)emb)[src * 32 + c4];
    __half2 h0 = __floats2half2_rn(v.x, v.y);
    __half2 h1 = __floats2half2_rn(v.z, v.w);
    uint32_t* xh = (uint32_t*)g_Xh;
    xh[n * 64 + c4 * 2]     = *reinterpret_cast<uint32_t*>(&h0);
    xh[n * 64 + c4 * 2 + 1] = *reinterpret_cast<uint32_t*>(&h1);
}

// pack W[r][d][o], root[d][o] -> W[c][d] fp16 hi/lo
__global__ void pack_kernel(const float* __restrict__ W, const float* __restrict__ root) {
    int idx = blockIdx.x * blockDim.x + threadIdx.x;
    if (idx >= KC * DD) return;
    int c = idx >> 7;
    int d = idx & 127;
    float v;
    if (c < RR * DD) v = W[((c >> 7) * DD + d) * DD + (c & 127)];
    else             v = root[d * DD + (c - RR * DD)];
    __half h = __float2half_rn(v);
    __half l = __float2half_rn(v - __half2float(h));
    g_Whi[idx] = h;
    g_Wlo[idx] = l;
}

// ---------------- HMMA GEMM: Y[N,1152] = X[N,128] @ W^T ---------------------
// CTA tile: 128 rows x 128 cols, 8 warps (4x2), warp tile 32x64, K=128 resident.
// 2 MMA passes: Xh*Whi + Xh*Wlo (= Xh*W; dropped term ~2^-12). Y stored fp16.
#define LDS_ROW 272          // 136 halves per smem row (pad 128+8)
#define SM_A   0
#define SM_BHI 34816
#define SM_BLO 69632
#define GEMM_SMEM 104448

__global__ __launch_bounds__(256, 2) void gemm_kernel() {
    extern __shared__ char smem[];
    const uint32_t sb = smem_u32(smem);
    const int tid = threadIdx.x, wid = tid >> 5, lane = tid & 31;
    const int cb = blockIdx.x * 128;
    const int nb = blockIdx.y * 128;

    // A tile: 128 rows x 128 halves, 16 uint4 per row
#pragma unroll
    for (int i = 0; i < 8; i++) {
        int idx = tid + i * 256;
        int row = idx >> 4;
        int ch = idx & 15;
        int gn = nb + row;
        uint4 v = make_uint4(0, 0, 0, 0);
        if (gn < NN) v = ((const uint4*)g_Xh)[gn * 16 + ch];
        *(uint4*)(smem + SM_A + row * LDS_ROW + ch * 16) = v;
    }
    // B tiles: 128 rows x 128 halves, hi & lo
#pragma unroll
    for (int i = 0; i < 8; i++) {
        int idx = tid + i * 256;
        int row = idx >> 4;
        int ch = idx & 15;
        uint4 vh = ((const uint4*)g_Whi)[(cb + row) * 16 + ch];
        uint4 vl = ((const uint4*)g_Wlo)[(cb + row) * 16 + ch];
        *(uint4*)(smem + SM_BHI + row * LDS_ROW + ch * 16) = vh;
        *(uint4*)(smem + SM_BLO + row * LDS_ROW + ch * 16) = vl;
    }
    __syncthreads();

    // 8 warps: 4 along M (32 rows each), 2 along N (64 cols each)
    const int wm = (wid >> 1) * 32;
    const int wn = (wid & 1) * 64;

    const uint32_t aRow = wm + (lane & 15);
    const uint32_t aOff = (lane >> 4) * 16;
    const uint32_t aAd = sb + SM_A + aRow * LDS_ROW + aOff;
    const uint32_t bRow = wn + ((lane >> 4) & 1) * 8 + (lane & 7);
    const uint32_t bOff = ((lane >> 3) & 1) * 16;
    const uint32_t bHi = sb + SM_BHI + bRow * LDS_ROW + bOff;
    const uint32_t bLo = bHi + (SM_BLO - SM_BHI);

    float acc[2][8][4];
#pragma unroll
    for (int mt = 0; mt < 2; mt++)
#pragma unroll
        for (int nt = 0; nt < 8; nt++)
#pragma unroll
            for (int k = 0; k < 4; k++) acc[mt][nt][k] = 0.f;

#pragma unroll
    for (int ks = 0; ks < 8; ks++) {
        uint32_t ah[2][4];
#pragma unroll
        for (int mt = 0; mt < 2; mt++) {
            uint32_t o = mt * (16 * LDS_ROW) + ks * 32;
            LDSM4(ah[mt][0], ah[mt][1], ah[mt][2], ah[mt][3], aAd + o);
        }
#pragma unroll
        for (int bt = 0; bt < 4; bt++) {
            uint32_t bh[4], bl[4];
            uint32_t o = bt * (16 * LDS_ROW) + ks * 32;
            LDSM4(bh[0], bh[1], bh[2], bh[3], bHi + o);
            LDSM4(bl[0], bl[1], bl[2], bl[3], bLo + o);
#pragma unroll
            for (int mt = 0; mt < 2; mt++) {
#pragma unroll
                for (int ni = 0; ni < 2; ni++) {
                    int nt = bt * 2 + ni;
                    int bi = ni * 2;
                    MMA_F16(acc[mt][nt], ah[mt], bh[bi], bh[bi + 1]);
                    MMA_F16(acc[mt][nt], ah[mt], bl[bi], bl[bi + 1]);
                }
            }
        }
    }

    // epilogue: write fp16 to g_Y
    const int r0 = nb + wm + (lane >> 2);
    const int c0 = cb + wn + (lane & 3) * 2;
#pragma unroll
    for (int mt = 0; mt < 2; mt++) {
#pragma unroll
        for (int nt = 0; nt < 8; nt++) {
            int r = r0 + mt * 16;
            int c = c0 + nt * 8;
            if (r < NN) {
                __half2 h = __floats2half2_rn(acc[mt][nt][0], acc[mt][nt][1]);
                *(__half2*)(g_Y + (size_t)r * KC + c) = h;
            }
            if (r + 8 < NN) {
                __half2 h = __floats2half2_rn(acc[mt][nt][2], acc[mt][nt][3]);
                *(__half2*)(g_Y + (size_t)(r + 8) * KC + c) = h;
            }
        }
    }
}

// ---------------- CSR aggregation (+ fused LN+ReLU + fp16 convert) ---------
__global__ __launch_bounds__(256)
void agg_kernel(const float* __restrict__ bias, const float* __restrict__ gma,
                const float* __restrict__ bta, float* __restrict__ ext_out,
                int do_ln) {
    int gt = blockIdx.x * blockDim.x + threadIdx.x;
    int row = gt >> 5;
    if (row >= NN) return;
    int lane = gt & 31;

    // root part (fp16) + bias
    float4 acc;
    {
        uint2 p = *(const uint2*)(g_Y + (size_t)row * KC + RR * DD + lane * 4);
        __half2 a0 = *reinterpret_cast<__half2*>(&p.x);
        __half2 a1 = *reinterpret_cast<__half2*>(&p.y);
        float2 f0 = __half22float2(a0);
        float2 f1 = __half22float2(a1);
        acc = make_float4(f0.x, f0.y, f1.x, f1.y);
    }
    float4 bb = ((const float4*)bias)[lane];
    acc.x += bb.x; acc.y += bb.y; acc.z += bb.z; acc.w += bb.w;

    int beg = g_rowptr[row], end = g_rowptr[row + 1];
    for (int i = beg; i < end; i++) {
        int pk = __ldg(&g_csr[i]);
        int src = pk >> 3, t = pk & 7;
        float iv = __ldg(&g_inv[(row << 3) + t]);
        uint2 p = __ldg((const uint2*)(g_Y + (size_t)src * KC + (t << 7) + lane * 4));
        __half2 v0 = *reinterpret_cast<__half2*>(&p.x);
        __half2 v1 = *reinterpret_cast<__half2*>(&p.y);
        float2 f0 = __half22float2(v0);
        float2 f1 = __half22float2(v1);
        acc.x = fmaf(iv, f0.x, acc.x);
        acc.y = fmaf(iv, f0.y, acc.y);
        acc.z = fmaf(iv, f1.x, acc.z);
        acc.w = fmaf(iv, f1.y, acc.w);
    }

    if (do_ln) {
        float s = acc.x + acc.y + acc.z + acc.w;
#pragma unroll
        for (int off = 16; off > 0; off >>= 1) s += __shfl_xor_sync(0xffffffffu, s, off);
        float mu = s * (1.0f / 128.0f);
        float dx = acc.x - mu, dy = acc.y - mu, dz = acc.z - mu, dw = acc.w - mu;
        float q = dx * dx + dy * dy + dz * dz + dw * dw;
#pragma unroll
        for (int off = 16; off > 0; off >>= 1) q += __shfl_xor_sync(0xffffffffu, q, off);
        float rs = rsqrtf(q * (1.0f / 128.0f) + LN_EPS);
        float4 gg = ((const float4*)gma)[lane];
        float4 b2 = ((const float4*)bta)[lane];
        float ox = fmaxf(dx * rs * gg.x + b2.x, 0.f);
        float oy = fmaxf(dy * rs * gg.y + b2.y, 0.f);
        float oz = fmaxf(dz * rs * gg.z + b2.z, 0.f);
        float ow = fmaxf(dw * rs * gg.w + b2.w, 0.f);
        __half2 h0 = __floats2half2_rn(ox, oy);
        __half2 h1 = __floats2half2_rn(oz, ow);
        uint32_t* xh = (uint32_t*)g_Xh;
        xh[row * 64 + lane * 2]     = *reinterpret_cast<uint32_t*>(&h0);
        xh[row * 64 + lane * 2 + 1] = *reinterpret_cast<uint32_t*>(&h1);
    } else {
        ((float4*)ext_out)[row * 32 + lane] = acc;
    }
}

// ---------------- launch ----------------------------------------------------
extern "C" void kernel_launch(void* const* d_in, const int* in_sizes, int n_in,
                              void* d_out, int out_size) {
    const int*   node_ids = (const int*)d_in[0];
    const int*   ei       = (const int*)d_in[1];
    const int*   et       = (const int*)d_in[2];
    const float* emb      = (const float*)d_in[3];
    const float* W1 = (const float*)d_in[4],  *root1 = (const float*)d_in[5];
    const float* b1 = (const float*)d_in[6],  *g1 = (const float*)d_in[7];
    const float* be1 = (const float*)d_in[8];
    const float* W2 = (const float*)d_in[9],  *root2 = (const float*)d_in[10];
    const float* b2 = (const float*)d_in[11], *g2 = (const float*)d_in[12];
    const float* be2 = (const float*)d_in[13];
    const float* W3 = (const float*)d_in[14], *root3 = (const float*)d_in[15];
    const float* b3 = (const float*)d_in[16];
    float* out = (float*)d_out;

    static int smem_set = 0;
    if (!smem_set) {
        cudaFuncSetAttribute(gemm_kernel, cudaFuncAttributeMaxDynamicSharedMemorySize,
                             GEMM_SMEM);
        smem_set = 1;
    }

    const int T = 256;
    const int NB_NODE = (NN + T - 1) / T;          // 196
    dim3 gemm_grid(KC / 128, (NN + 127) / 128);    // 9 x 391

    // launch order chosen so gemm_kernel is the 4th launch (ncu capture slot)
    gather_kernel<<<(NN * 32 + T - 1) / T, T>>>(node_ids, emb);
    pack_kernel<<<(KC * DD + T - 1) / T, T>>>(W1, root1);
    zero_all_kernel<<<(NN * RR + T - 1) / T, T>>>();
    gemm_kernel<<<gemm_grid, T, GEMM_SMEM>>>();            // layer-1 GEMM (profiled)

    count_kernel<<<(EE + T - 1) / T, T>>>(ei, et);
    deg_inv_kernel<<<NB_NODE, T>>>();
    deg_partial_kernel<<<NB_NODE, T>>>();
    scan_part_kernel<<<1, T>>>(NB_NODE);
    rowptr_kernel<<<NB_NODE, T>>>();
    fill_kernel<<<(EE + T - 1) / T, T>>>(ei, et);

    agg_kernel<<<(NN * 32 + T - 1) / T, T>>>(b1, g1, be1, nullptr, 1);
    // layer 2
    pack_kernel<<<(KC * DD + T - 1) / T, T>>>(W2, root2);
    gemm_kernel<<<gemm_grid, T, GEMM_SMEM>>>();
    agg_kernel<<<(NN * 32 + T - 1) / T, T>>>(b2, g2, be2, nullptr, 1);
    // layer 3
    pack_kernel<<<(KC * DD + T - 1) / T, T>>>(W3, root3);
    gemm_kernel<<<gemm_grid, T, GEMM_SMEM>>>();
    agg_kernel<<<(NN * 32 + T - 1) / T, T>>>(b3, nullptr, nullptr, out, 0);

    (void)in_sizes; (void)n_in; (void)out_size;
}

// round 12
// speedup vs baseline: 4.9050x; 1.0852x over previous
#include <cuda_runtime.h>
#include <cuda_fp16.h>
#include <cstdint>

#define NN 50000
#define EE 800000
#define RR 8
#define DD 128
#define KC 1152        // 8*128 relation cols + 128 root cols
#define LN_EPS 1e-5f

// ---------------- scratch (device globals) ---------------------------------
__device__ __align__(16) __half g_Y[NN * KC];           // projections (+root), fp16
__device__ __align__(16) __half g_Xh[NN * DD];          // layer input (fp16)
__device__ __align__(16) __half g_Whi[KC * DD];         // packed weights [c][d]
__device__ float g_inv[NN * RR];                        // cnt then 1/max(cnt,1)
__device__ int   g_deg[NN];
__device__ int   g_cur[NN];
__device__ int   g_rowptr[NN + 1];
__device__ int   g_csr[EE];                             // src*8 + type
__device__ int   g_part[256];

// ---------------- helpers ---------------------------------------------------
__device__ __forceinline__ uint32_t smem_u32(const void* p) {
    uint32_t a;
    asm("{ .reg .u64 t; cvta.to.shared.u64 t, %1; cvt.u32.u64 %0, t; }"
        : "=r"(a) : "l"(p));
    return a;
}

#define LDSM4(r0, r1, r2, r3, addr) asm volatile( \
    "ldmatrix.sync.aligned.m8n8.x4.shared.b16 {%0,%1,%2,%3}, [%4];" \
    : "=r"(r0), "=r"(r1), "=r"(r2), "=r"(r3) : "r"(addr))

#define MMA_F16(c, a, b0, b1) asm volatile( \
    "mma.sync.aligned.m16n8k16.row.col.f32.f16.f16.f32 " \
    "{%0,%1,%2,%3}, {%4,%5,%6,%7}, {%8,%9}, {%0,%1,%2,%3};" \
    : "+f"((c)[0]), "+f"((c)[1]), "+f"((c)[2]), "+f"((c)[3]) \
    : "r"((a)[0]), "r"((a)[1]), "r"((a)[2]), "r"((a)[3]), "r"(b0), "r"(b1))

// ---------------- edge-structure kernels ------------------------------------
__global__ void zero_all_kernel() {
    int i = blockIdx.x * blockDim.x + threadIdx.x;
    if (i < NN * RR) g_inv[i] = 0.0f;
    if (i < NN) g_cur[i] = 0;
}

__global__ void count_kernel(const int* __restrict__ ei, const int* __restrict__ et) {
    int e = blockIdx.x * blockDim.x + threadIdx.x;
    if (e < EE) {
        int dst = ei[EE + e];
        atomicAdd(&g_inv[dst * RR + et[e]], 1.0f);
    }
}

// deg[n] = sum_t cnt[n,t]; then inv[n,t] = 1/max(cnt,1)  (one pass)
__global__ void deg_inv_kernel() {
    int n = blockIdx.x * blockDim.x + threadIdx.x;
    if (n >= NN) return;
    float4 a = *(const float4*)(g_inv + n * RR);
    float4 b = *(const float4*)(g_inv + n * RR + 4);
    g_deg[n] = (int)(a.x + a.y + a.z + a.w + b.x + b.y + b.z + b.w);
    a.x = 1.0f / fmaxf(a.x, 1.0f); a.y = 1.0f / fmaxf(a.y, 1.0f);
    a.z = 1.0f / fmaxf(a.z, 1.0f); a.w = 1.0f / fmaxf(a.w, 1.0f);
    b.x = 1.0f / fmaxf(b.x, 1.0f); b.y = 1.0f / fmaxf(b.y, 1.0f);
    b.z = 1.0f / fmaxf(b.z, 1.0f); b.w = 1.0f / fmaxf(b.w, 1.0f);
    *(float4*)(g_inv + n * RR) = a;
    *(float4*)(g_inv + n * RR + 4) = b;
}

__global__ void deg_partial_kernel() {
    __shared__ int s[256];
    int i = blockIdx.x * 256 + threadIdx.x;
    int v = (i < NN) ? g_deg[i] : 0;
    s[threadIdx.x] = v;
    __syncthreads();
    for (int off = 128; off > 0; off >>= 1) {
        if (threadIdx.x < off) s[threadIdx.x] += s[threadIdx.x + off];
        __syncthreads();
    }
    if (threadIdx.x == 0) g_part[blockIdx.x] = s[0];
}

__global__ void scan_part_kernel(int nblocks) {
    __shared__ int s[512];
    int t = threadIdx.x;
    int v = (t < nblocks) ? g_part[t] : 0;
    s[t] = v;
    __syncthreads();
    int acc = v;
    for (int off = 1; off < 256; off <<= 1) {
        int add = (t >= off) ? s[t - off] : 0;
        __syncthreads();
        s[t] = acc = acc + add;
        __syncthreads();
    }
    if (t < nblocks) g_part[t] = s[t] - v;
}

__global__ void rowptr_kernel() {
    __shared__ int s[512];
    int t = threadIdx.x;
    int i = blockIdx.x * 256 + t;
    int v = (i < NN) ? g_deg[i] : 0;
    s[t] = v;
    __syncthreads();
    int acc = v;
    for (int off = 1; off < 256; off <<= 1) {
        int add = (t >= off) ? s[t - off] : 0;
        __syncthreads();
        s[t] = acc = acc + add;
        __syncthreads();
    }
    if (i < NN) g_rowptr[i] = g_part[blockIdx.x] + s[t] - v;
    if (i == NN) g_rowptr[NN] = EE;
}

__global__ void fill_kernel(const int* __restrict__ ei, const int* __restrict__ et) {
    int e = blockIdx.x * blockDim.x + threadIdx.x;
    if (e < EE) {
        int dst = ei[EE + e];
        int p = atomicAdd(&g_cur[dst], 1);
        g_csr[g_rowptr[dst] + p] = (ei[e] << 3) | et[e];
    }
}

// ---------------- gather + convert ------------------------------------------
__global__ void gather_kernel(const int* __restrict__ node_ids,
                              const float* __restrict__ emb) {
    int idx = blockIdx.x * blockDim.x + threadIdx.x;
    if (idx >= NN * 32) return;
    int n = idx >> 5;
    int c4 = idx & 31;
    int src = node_ids[n];
    float4 v = ((const float4*)emb)[src * 32 + c4];
    __half2 h0 = __floats2half2_rn(v.x, v.y);
    __half2 h1 = __floats2half2_rn(v.z, v.w);
    uint32_t* xh = (uint32_t*)g_Xh;
    xh[n * 64 + c4 * 2]     = *reinterpret_cast<uint32_t*>(&h0);
    xh[n * 64 + c4 * 2 + 1] = *reinterpret_cast<uint32_t*>(&h1);
}

// pack W[r][d][o], root[d][o] -> W[c][d] fp16
__global__ void pack_kernel(const float* __restrict__ W, const float* __restrict__ root) {
    int idx = blockIdx.x * blockDim.x + threadIdx.x;
    if (idx >= KC * DD) return;
    int c = idx >> 7;
    int d = idx & 127;
    float v;
    if (c < RR * DD) v = W[((c >> 7) * DD + d) * DD + (c & 127)];
    else             v = root[d * DD + (c - RR * DD)];
    g_Whi[idx] = __float2half_rn(v);
}

// ---------------- HMMA GEMM: Y[N,1152] = X[N,128] @ W^T ---------------------
// CTA tile: 128 rows x 128 cols, 8 warps (4x2), warp tile 32x64, K=128 resident.
// Single fp16 pass (A and W both fp16-quantized; error ~2^-12 each).
// 70 KB smem -> 3 CTAs/SM for phase overlap. Y stored fp16.
#define LDS_ROW 272          // 136 halves per smem row (pad 128+8)
#define SM_A   0
#define SM_BHI 34816
#define GEMM_SMEM 69632

__global__ __launch_bounds__(256, 3) void gemm_kernel() {
    extern __shared__ char smem[];
    const uint32_t sb = smem_u32(smem);
    const int tid = threadIdx.x, wid = tid >> 5, lane = tid & 31;
    const int cb = blockIdx.x * 128;
    const int nb = blockIdx.y * 128;

    // A tile: 128 rows x 128 halves, 16 uint4 per row
#pragma unroll
    for (int i = 0; i < 8; i++) {
        int idx = tid + i * 256;
        int row = idx >> 4;
        int ch = idx & 15;
        int gn = nb + row;
        uint4 v = make_uint4(0, 0, 0, 0);
        if (gn < NN) v = ((const uint4*)g_Xh)[gn * 16 + ch];
        *(uint4*)(smem + SM_A + row * LDS_ROW + ch * 16) = v;
    }
    // B tile: 128 rows x 128 halves
#pragma unroll
    for (int i = 0; i < 8; i++) {
        int idx = tid + i * 256;
        int row = idx >> 4;
        int ch = idx & 15;
        uint4 vh = ((const uint4*)g_Whi)[(cb + row) * 16 + ch];
        *(uint4*)(smem + SM_BHI + row * LDS_ROW + ch * 16) = vh;
    }
    __syncthreads();

    // 8 warps: 4 along M (32 rows each), 2 along N (64 cols each)
    const int wm = (wid >> 1) * 32;
    const int wn = (wid & 1) * 64;

    const uint32_t aRow = wm + (lane & 15);
    const uint32_t aOff = (lane >> 4) * 16;
    const uint32_t aAd = sb + SM_A + aRow * LDS_ROW + aOff;
    const uint32_t bRow = wn + ((lane >> 4) & 1) * 8 + (lane & 7);
    const uint32_t bOff = ((lane >> 3) & 1) * 16;
    const uint32_t bHi = sb + SM_BHI + bRow * LDS_ROW + bOff;

    float acc[2][8][4];
#pragma unroll
    for (int mt = 0; mt < 2; mt++)
#pragma unroll
        for (int nt = 0; nt < 8; nt++)
#pragma unroll
            for (int k = 0; k < 4; k++) acc[mt][nt][k] = 0.f;

#pragma unroll
    for (int ks = 0; ks < 8; ks++) {
        uint32_t ah[2][4];
#pragma unroll
        for (int mt = 0; mt < 2; mt++) {
            uint32_t o = mt * (16 * LDS_ROW) + ks * 32;
            LDSM4(ah[mt][0], ah[mt][1], ah[mt][2], ah[mt][3], aAd + o);
        }
#pragma unroll
        for (int bt = 0; bt < 4; bt++) {
            uint32_t bh[4];
            uint32_t o = bt * (16 * LDS_ROW) + ks * 32;
            LDSM4(bh[0], bh[1], bh[2], bh[3], bHi + o);
#pragma unroll
            for (int mt = 0; mt < 2; mt++) {
#pragma unroll
                for (int ni = 0; ni < 2; ni++) {
                    int nt = bt * 2 + ni;
                    int bi = ni * 2;
                    MMA_F16(acc[mt][nt], ah[mt], bh[bi], bh[bi + 1]);
                }
            }
        }
    }

    // epilogue: write fp16 to g_Y
    const int r0 = nb + wm + (lane >> 2);
    const int c0 = cb + wn + (lane & 3) * 2;
#pragma unroll
    for (int mt = 0; mt < 2; mt++) {
#pragma unroll
        for (int nt = 0; nt < 8; nt++) {
            int r = r0 + mt * 16;
            int c = c0 + nt * 8;
            if (r < NN) {
                __half2 h = __floats2half2_rn(acc[mt][nt][0], acc[mt][nt][1]);
                *(__half2*)(g_Y + (size_t)r * KC + c) = h;
            }
            if (r + 8 < NN) {
                __half2 h = __floats2half2_rn(acc[mt][nt][2], acc[mt][nt][3]);
                *(__half2*)(g_Y + (size_t)(r + 8) * KC + c) = h;
            }
        }
    }
}

// ---------------- CSR aggregation (+ fused LN+ReLU + fp16 convert) ---------
__global__ __launch_bounds__(256)
void agg_kernel(const float* __restrict__ bias, const float* __restrict__ gma,
                const float* __restrict__ bta, float* __restrict__ ext_out,
                int do_ln) {
    int gt = blockIdx.x * blockDim.x + threadIdx.x;
    int row = gt >> 5;
    if (row >= NN) return;
    int lane = gt & 31;

    // root part (fp16) + bias
    float4 acc;
    {
        uint2 p = *(const uint2*)(g_Y + (size_t)row * KC + RR * DD + lane * 4);
        __half2 a0 = *reinterpret_cast<__half2*>(&p.x);
        __half2 a1 = *reinterpret_cast<__half2*>(&p.y);
        float2 f0 = __half22float2(a0);
        float2 f1 = __half22float2(a1);
        acc = make_float4(f0.x, f0.y, f1.x, f1.y);
    }
    float4 bb = ((const float4*)bias)[lane];
    acc.x += bb.x; acc.y += bb.y; acc.z += bb.z; acc.w += bb.w;

    int beg = g_rowptr[row], end = g_rowptr[row + 1];
    for (int i = beg; i < end; i++) {
        int pk = __ldg(&g_csr[i]);
        int src = pk >> 3, t = pk & 7;
        float iv = __ldg(&g_inv[(row << 3) + t]);
        uint2 p = __ldg((const uint2*)(g_Y + (size_t)src * KC + (t << 7) + lane * 4));
        __half2 v0 = *reinterpret_cast<__half2*>(&p.x);
        __half2 v1 = *reinterpret_cast<__half2*>(&p.y);
        float2 f0 = __half22float2(v0);
        float2 f1 = __half22float2(v1);
        acc.x = fmaf(iv, f0.x, acc.x);
        acc.y = fmaf(iv, f0.y, acc.y);
        acc.z = fmaf(iv, f1.x, acc.z);
        acc.w = fmaf(iv, f1.y, acc.w);
    }

    if (do_ln) {
        float s = acc.x + acc.y + acc.z + acc.w;
#pragma unroll
        for (int off = 16; off > 0; off >>= 1) s += __shfl_xor_sync(0xffffffffu, s, off);
        float mu = s * (1.0f / 128.0f);
        float dx = acc.x - mu, dy = acc.y - mu, dz = acc.z - mu, dw = acc.w - mu;
        float q = dx * dx + dy * dy + dz * dz + dw * dw;
#pragma unroll
        for (int off = 16; off > 0; off >>= 1) q += __shfl_xor_sync(0xffffffffu, q, off);
        float rs = rsqrtf(q * (1.0f / 128.0f) + LN_EPS);
        float4 gg = ((const float4*)gma)[lane];
        float4 b2 = ((const float4*)bta)[lane];
        float ox = fmaxf(dx * rs * gg.x + b2.x, 0.f);
        float oy = fmaxf(dy * rs * gg.y + b2.y, 0.f);
        float oz = fmaxf(dz * rs * gg.z + b2.z, 0.f);
        float ow = fmaxf(dw * rs * gg.w + b2.w, 0.f);
        __half2 h0 = __floats2half2_rn(ox, oy);
        __half2 h1 = __floats2half2_rn(oz, ow);
        uint32_t* xh = (uint32_t*)g_Xh;
        xh[row * 64 + lane * 2]     = *reinterpret_cast<uint32_t*>(&h0);
        xh[row * 64 + lane * 2 + 1] = *reinterpret_cast<uint32_t*>(&h1);
    } else {
        ((float4*)ext_out)[row * 32 + lane] = acc;
    }
}

// ---------------- launch ----------------------------------------------------
extern "C" void kernel_launch(void* const* d_in, const int* in_sizes, int n_in,
                              void* d_out, int out_size) {
    const int*   node_ids = (const int*)d_in[0];
    const int*   ei       = (const int*)d_in[1];
    const int*   et       = (const int*)d_in[2];
    const float* emb      = (const float*)d_in[3];
    const float* W1 = (const float*)d_in[4],  *root1 = (const float*)d_in[5];
    const float* b1 = (const float*)d_in[6],  *g1 = (const float*)d_in[7];
    const float* be1 = (const float*)d_in[8];
    const float* W2 = (const float*)d_in[9],  *root2 = (const float*)d_in[10];
    const float* b2 = (const float*)d_in[11], *g2 = (const float*)d_in[12];
    const float* be2 = (const float*)d_in[13];
    const float* W3 = (const float*)d_in[14], *root3 = (const float*)d_in[15];
    const float* b3 = (const float*)d_in[16];
    float* out = (float*)d_out;

    static int smem_set = 0;
    if (!smem_set) {
        cudaFuncSetAttribute(gemm_kernel, cudaFuncAttributeMaxDynamicSharedMemorySize,
                             GEMM_SMEM);
        smem_set = 1;
    }

    const int T = 256;
    const int NB_NODE = (NN + T - 1) / T;          // 196
    dim3 gemm_grid(KC / 128, (NN + 127) / 128);    // 9 x 391

    // launch order chosen so gemm_kernel is the 4th launch (ncu capture slot)
    gather_kernel<<<(NN * 32 + T - 1) / T, T>>>(node_ids, emb);
    pack_kernel<<<(KC * DD + T - 1) / T, T>>>(W1, root1);
    zero_all_kernel<<<(NN * RR + T - 1) / T, T>>>();
    gemm_kernel<<<gemm_grid, T, GEMM_SMEM>>>();            // layer-1 GEMM (profiled)

    count_kernel<<<(EE + T - 1) / T, T>>>(ei, et);
    deg_inv_kernel<<<NB_NODE, T>>>();
    deg_partial_kernel<<<NB_NODE, T>>>();
    scan_part_kernel<<<1, T>>>(NB_NODE);
    rowptr_kernel<<<NB_NODE, T>>>();
    fill_kernel<<<(EE + T - 1) / T, T>>>(ei, et);

    agg_kernel<<<(NN * 32 + T - 1) / T, T>>>(b1, g1, be1, nullptr, 1);
    // layer 2
    pack_kernel<<<(KC * DD + T - 1) / T, T>>>(W2, root2);
    gemm_kernel<<<gemm_grid, T, GEMM_SMEM>>>();
    agg_kernel<<<(NN * 32 + T - 1) / T, T>>>(b2, g2, be2, nullptr, 1);
    // layer 3
    pack_kernel<<<(KC * DD + T - 1) / T, T>>>(W3, root3);
    gemm_kernel<<<gemm_grid, T, GEMM_SMEM>>>();
    agg_kernel<<<(NN * 32 + T - 1) / T, T>>>(b3, nullptr, nullptr, out, 0);

    (void)in_sizes; (void)n_in; (void)out_size;
}

// round 13
// speedup vs baseline: 5.5867x; 1.1390x over previous
#include <cuda_runtime.h>
#include <cuda_fp16.h>
#include <cstdint>

#define NN 50000
#define EE 800000
#define RR 8
#define DD 128
#define KC 1152        // 8*128 relation cols + 128 root cols
#define LN_EPS 1e-5f

// ---------------- scratch (device globals) ---------------------------------
__device__ __align__(16) __half g_Y[NN * KC];           // projections (+root), fp16
__device__ __align__(16) __half g_Xh[NN * DD];          // layer input (fp16)
__device__ __align__(16) __half g_Whi[KC * DD];         // packed weights [c][d]
__device__ float g_inv[NN * RR];                        // cnt then 1/max(cnt,1)
__device__ int   g_deg[NN];
__device__ int   g_cur[NN];
__device__ int   g_rowptr[NN + 1];
__device__ int   g_csr[EE];                             // src*8 + type
__device__ int   g_part[256];

// ---------------- helpers ---------------------------------------------------
__device__ __forceinline__ uint32_t smem_u32(const void* p) {
    uint32_t a;
    asm("{ .reg .u64 t; cvta.to.shared.u64 t, %1; cvt.u32.u64 %0, t; }"
        : "=r"(a) : "l"(p));
    return a;
}

#define LDSM4(r0, r1, r2, r3, addr) asm volatile( \
    "ldmatrix.sync.aligned.m8n8.x4.shared.b16 {%0,%1,%2,%3}, [%4];" \
    : "=r"(r0), "=r"(r1), "=r"(r2), "=r"(r3) : "r"(addr))

#define MMA_F16(c, a, b0, b1) asm volatile( \
    "mma.sync.aligned.m16n8k16.row.col.f32.f16.f16.f32 " \
    "{%0,%1,%2,%3}, {%4,%5,%6,%7}, {%8,%9}, {%0,%1,%2,%3};" \
    : "+f"((c)[0]), "+f"((c)[1]), "+f"((c)[2]), "+f"((c)[3]) \
    : "r"((a)[0]), "r"((a)[1]), "r"((a)[2]), "r"((a)[3]), "r"(b0), "r"(b1))

// cp.async 16B with dynamic src-size (0 => zero-fill)
#define CP_ASYNC16(dst, src, ssz) asm volatile( \
    "cp.async.cg.shared.global [%0], [%1], 16, %2;" \
    :: "r"(dst), "l"(src), "r"(ssz) : "memory")
#define CP_COMMIT_WAIT() do { \
    asm volatile("cp.async.commit_group;" ::: "memory"); \
    asm volatile("cp.async.wait_group 0;" ::: "memory"); \
} while (0)

// ---------------- edge-structure kernels ------------------------------------
__global__ void zero_all_kernel() {
    int i = blockIdx.x * blockDim.x + threadIdx.x;
    if (i < NN * RR) g_inv[i] = 0.0f;
    if (i < NN) g_cur[i] = 0;
}

__global__ void count_kernel(const int* __restrict__ ei, const int* __restrict__ et) {
    int e = blockIdx.x * blockDim.x + threadIdx.x;
    if (e < EE) {
        int dst = ei[EE + e];
        atomicAdd(&g_inv[dst * RR + et[e]], 1.0f);
    }
}

__global__ void deg_inv_kernel() {
    int n = blockIdx.x * blockDim.x + threadIdx.x;
    if (n >= NN) return;
    float4 a = *(const float4*)(g_inv + n * RR);
    float4 b = *(const float4*)(g_inv + n * RR + 4);
    g_deg[n] = (int)(a.x + a.y + a.z + a.w + b.x + b.y + b.z + b.w);
    a.x = 1.0f / fmaxf(a.x, 1.0f); a.y = 1.0f / fmaxf(a.y, 1.0f);
    a.z = 1.0f / fmaxf(a.z, 1.0f); a.w = 1.0f / fmaxf(a.w, 1.0f);
    b.x = 1.0f / fmaxf(b.x, 1.0f); b.y = 1.0f / fmaxf(b.y, 1.0f);
    b.z = 1.0f / fmaxf(b.z, 1.0f); b.w = 1.0f / fmaxf(b.w, 1.0f);
    *(float4*)(g_inv + n * RR) = a;
    *(float4*)(g_inv + n * RR + 4) = b;
}

__global__ void deg_partial_kernel() {
    __shared__ int s[256];
    int i = blockIdx.x * 256 + threadIdx.x;
    int v = (i < NN) ? g_deg[i] : 0;
    s[threadIdx.x] = v;
    __syncthreads();
    for (int off = 128; off > 0; off >>= 1) {
        if (threadIdx.x < off) s[threadIdx.x] += s[threadIdx.x + off];
        __syncthreads();
    }
    if (threadIdx.x == 0) g_part[blockIdx.x] = s[0];
}

__global__ void scan_part_kernel(int nblocks) {
    __shared__ int s[512];
    int t = threadIdx.x;
    int v = (t < nblocks) ? g_part[t] : 0;
    s[t] = v;
    __syncthreads();
    int acc = v;
    for (int off = 1; off < 256; off <<= 1) {
        int add = (t >= off) ? s[t - off] : 0;
        __syncthreads();
        s[t] = acc = acc + add;
        __syncthreads();
    }
    if (t < nblocks) g_part[t] = s[t] - v;
}

__global__ void rowptr_kernel() {
    __shared__ int s[512];
    int t = threadIdx.x;
    int i = blockIdx.x * 256 + t;
    int v = (i < NN) ? g_deg[i] : 0;
    s[t] = v;
    __syncthreads();
    int acc = v;
    for (int off = 1; off < 256; off <<= 1) {
        int add = (t >= off) ? s[t - off] : 0;
        __syncthreads();
        s[t] = acc = acc + add;
        __syncthreads();
    }
    if (i < NN) g_rowptr[i] = g_part[blockIdx.x] + s[t] - v;
    if (i == NN) g_rowptr[NN] = EE;
}

__global__ void fill_kernel(const int* __restrict__ ei, const int* __restrict__ et) {
    int e = blockIdx.x * blockDim.x + threadIdx.x;
    if (e < EE) {
        int dst = ei[EE + e];
        int p = atomicAdd(&g_cur[dst], 1);
        g_csr[g_rowptr[dst] + p] = (ei[e] << 3) | et[e];
    }
}

// ---------------- gather + convert ------------------------------------------
__global__ void gather_kernel(const int* __restrict__ node_ids,
                              const float* __restrict__ emb) {
    int idx = blockIdx.x * blockDim.x + threadIdx.x;
    if (idx >= NN * 32) return;
    int n = idx >> 5;
    int c4 = idx & 31;
    int src = node_ids[n];
    float4 v = ((const float4*)emb)[src * 32 + c4];
    __half2 h0 = __floats2half2_rn(v.x, v.y);
    __half2 h1 = __floats2half2_rn(v.z, v.w);
    uint32_t* xh = (uint32_t*)g_Xh;
    xh[n * 64 + c4 * 2]     = *reinterpret_cast<uint32_t*>(&h0);
    xh[n * 64 + c4 * 2 + 1] = *reinterpret_cast<uint32_t*>(&h1);
}

// pack W[r][d][o], root[d][o] -> W[c][d] fp16
__global__ void pack_kernel(const float* __restrict__ W, const float* __restrict__ root) {
    int idx = blockIdx.x * blockDim.x + threadIdx.x;
    if (idx >= KC * DD) return;
    int c = idx >> 7;
    int d = idx & 127;
    float v;
    if (c < RR * DD) v = W[((c >> 7) * DD + d) * DD + (c & 127)];
    else             v = root[d * DD + (c - RR * DD)];
    g_Whi[idx] = __float2half_rn(v);
}

// ---------------- HMMA GEMM: Y[N,1152] = X[N,128] @ W^T ---------------------
// CTA tile: 128 rows x 128 cols, 8 warps (4x2), warp tile 32x64, K=128 resident.
// Single fp16 pass. 70 KB smem -> 3 CTAs/SM. cp.async prologue; epilogue staged
// through smem (A region reused) for coalesced STG.128.
#define LDS_ROW 272          // 136 halves per smem row (pad 128+8)
#define SM_A   0
#define SM_BHI 34816
#define GEMM_SMEM 69632

__global__ __launch_bounds__(256, 3) void gemm_kernel() {
    extern __shared__ char smem[];
    const uint32_t sb = smem_u32(smem);
    const int tid = threadIdx.x, wid = tid >> 5, lane = tid & 31;
    const int cb = blockIdx.x * 128;
    const int nb = blockIdx.y * 128;

    // A tile via cp.async: 128 rows x 128 halves, 16B per op, zero-fill OOB
#pragma unroll
    for (int i = 0; i < 8; i++) {
        int idx = tid + i * 256;
        int row = idx >> 4;
        int ch = idx & 15;
        int gn = nb + row;
        uint32_t ssz = (gn < NN) ? 16u : 0u;
        const char* src = (const char*)(g_Xh + (size_t)gn * DD) + ch * 16;
        CP_ASYNC16(sb + SM_A + row * LDS_ROW + ch * 16, src, ssz);
    }
    // B tile via cp.async: 128 rows x 128 halves
#pragma unroll
    for (int i = 0; i < 8; i++) {
        int idx = tid + i * 256;
        int row = idx >> 4;
        int ch = idx & 15;
        const char* src = (const char*)(g_Whi + (size_t)(cb + row) * DD) + ch * 16;
        CP_ASYNC16(sb + SM_BHI + row * LDS_ROW + ch * 16, src, 16u);
    }
    CP_COMMIT_WAIT();
    __syncthreads();

    // 8 warps: 4 along M (32 rows each), 2 along N (64 cols each)
    const int wm = (wid >> 1) * 32;
    const int wn = (wid & 1) * 64;

    const uint32_t aRow = wm + (lane & 15);
    const uint32_t aOff = (lane >> 4) * 16;
    const uint32_t aAd = sb + SM_A + aRow * LDS_ROW + aOff;
    const uint32_t bRow = wn + ((lane >> 4) & 1) * 8 + (lane & 7);
    const uint32_t bOff = ((lane >> 3) & 1) * 16;
    const uint32_t bHi = sb + SM_BHI + bRow * LDS_ROW + bOff;

    float acc[2][8][4];
#pragma unroll
    for (int mt = 0; mt < 2; mt++)
#pragma unroll
        for (int nt = 0; nt < 8; nt++)
#pragma unroll
            for (int k = 0; k < 4; k++) acc[mt][nt][k] = 0.f;

#pragma unroll
    for (int ks = 0; ks < 8; ks++) {
        uint32_t ah[2][4];
#pragma unroll
        for (int mt = 0; mt < 2; mt++) {
            uint32_t o = mt * (16 * LDS_ROW) + ks * 32;
            LDSM4(ah[mt][0], ah[mt][1], ah[mt][2], ah[mt][3], aAd + o);
        }
#pragma unroll
        for (int bt = 0; bt < 4; bt++) {
            uint32_t bh[4];
            uint32_t o = bt * (16 * LDS_ROW) + ks * 32;
            LDSM4(bh[0], bh[1], bh[2], bh[3], bHi + o);
#pragma unroll
            for (int mt = 0; mt < 2; mt++) {
#pragma unroll
                for (int ni = 0; ni < 2; ni++) {
                    int nt = bt * 2 + ni;
                    int bi = ni * 2;
                    MMA_F16(acc[mt][nt], ah[mt], bh[bi], bh[bi + 1]);
                }
            }
        }
    }

    // epilogue: stage fp16 tile in smem (A region is dead), then coalesced STG
    __syncthreads();
    {
        const int rBase = wm + (lane >> 2);
        const int cBase = wn + (lane & 3) * 2;
#pragma unroll
        for (int mt = 0; mt < 2; mt++) {
#pragma unroll
            for (int nt = 0; nt < 8; nt++) {
                uint32_t a0 = sb + SM_A + (rBase + mt * 16) * LDS_ROW
                            + (cBase + nt * 8) * 2;
                __half2 h0 = __floats2half2_rn(acc[mt][nt][0], acc[mt][nt][1]);
                __half2 h1 = __floats2half2_rn(acc[mt][nt][2], acc[mt][nt][3]);
                asm volatile("st.shared.b32 [%0], %1;"
                             :: "r"(a0), "r"(*(uint32_t*)&h0) : "memory");
                asm volatile("st.shared.b32 [%0], %1;"
                             :: "r"(a0 + 8 * LDS_ROW), "r"(*(uint32_t*)&h1) : "memory");
            }
        }
    }
    __syncthreads();
#pragma unroll
    for (int i = 0; i < 8; i++) {
        int idx = tid + i * 256;
        int row = idx >> 4;
        int ch = idx & 15;
        int gn = nb + row;
        if (gn < NN) {
            uint4 v;
            asm volatile("ld.shared.v4.b32 {%0,%1,%2,%3}, [%4];"
                         : "=r"(v.x), "=r"(v.y), "=r"(v.z), "=r"(v.w)
                         : "r"(sb + SM_A + row * LDS_ROW + ch * 16));
            *(uint4*)((char*)(g_Y + (size_t)gn * KC + cb) + ch * 16) = v;
        }
    }
}

// ---------------- CSR aggregation (+ fused LN+ReLU + fp16 convert) ---------
__global__ __launch_bounds__(256)
void agg_kernel(const float* __restrict__ bias, const float* __restrict__ gma,
                const float* __restrict__ bta, float* __restrict__ ext_out,
                int do_ln) {
    int gt = blockIdx.x * blockDim.x + threadIdx.x;
    int row = gt >> 5;
    if (row >= NN) return;
    int lane = gt & 31;

    // root part (fp16) + bias
    float4 acc;
    {
        uint2 p = *(const uint2*)(g_Y + (size_t)row * KC + RR * DD + lane * 4);
        __half2 a0 = *reinterpret_cast<__half2*>(&p.x);
        __half2 a1 = *reinterpret_cast<__half2*>(&p.y);
        float2 f0 = __half22float2(a0);
        float2 f1 = __half22float2(a1);
        acc = make_float4(f0.x, f0.y, f1.x, f1.y);
    }
    float4 bb = ((const float4*)bias)[lane];
    acc.x += bb.x; acc.y += bb.y; acc.z += bb.z; acc.w += bb.w;

    int beg = g_rowptr[row], end = g_rowptr[row + 1];
    for (int i = beg; i < end; i++) {
        int pk = __ldg(&g_csr[i]);
        int src = pk >> 3, t = pk & 7;
        float iv = __ldg(&g_inv[(row << 3) + t]);
        uint2 p = __ldg((const uint2*)(g_Y + (size_t)src * KC + (t << 7) + lane * 4));
        __half2 v0 = *reinterpret_cast<__half2*>(&p.x);
        __half2 v1 = *reinterpret_cast<__half2*>(&p.y);
        float2 f0 = __half22float2(v0);
        float2 f1 = __half22float2(v1);
        acc.x = fmaf(iv, f0.x, acc.x);
        acc.y = fmaf(iv, f0.y, acc.y);
        acc.z = fmaf(iv, f1.x, acc.z);
        acc.w = fmaf(iv, f1.y, acc.w);
    }

    if (do_ln) {
        float s = acc.x + acc.y + acc.z + acc.w;
#pragma unroll
        for (int off = 16; off > 0; off >>= 1) s += __shfl_xor_sync(0xffffffffu, s, off);
        float mu = s * (1.0f / 128.0f);
        float dx = acc.x - mu, dy = acc.y - mu, dz = acc.z - mu, dw = acc.w - mu;
        float q = dx * dx + dy * dy + dz * dz + dw * dw;
#pragma unroll
        for (int off = 16; off > 0; off >>= 1) q += __shfl_xor_sync(0xffffffffu, q, off);
        float rs = rsqrtf(q * (1.0f / 128.0f) + LN_EPS);
        float4 gg = ((const float4*)gma)[lane];
        float4 b2 = ((const float4*)bta)[lane];
        float ox = fmaxf(dx * rs * gg.x + b2.x, 0.f);
        float oy = fmaxf(dy * rs * gg.y + b2.y, 0.f);
        float oz = fmaxf(dz * rs * gg.z + b2.z, 0.f);
        float ow = fmaxf(dw * rs * gg.w + b2.w, 0.f);
        __half2 h0 = __floats2half2_rn(ox, oy);
        __half2 h1 = __floats2half2_rn(oz, ow);
        uint32_t* xh = (uint32_t*)g_Xh;
        xh[row * 64 + lane * 2]     = *reinterpret_cast<uint32_t*>(&h0);
        xh[row * 64 + lane * 2 + 1] = *reinterpret_cast<uint32_t*>(&h1);
    } else {
        ((float4*)ext_out)[row * 32 + lane] = acc;
    }
}

// ---------------- launch ----------------------------------------------------
extern "C" void kernel_launch(void* const* d_in, const int* in_sizes, int n_in,
                              void* d_out, int out_size) {
    const int*   node_ids = (const int*)d_in[0];
    const int*   ei       = (const int*)d_in[1];
    const int*   et       = (const int*)d_in[2];
    const float* emb      = (const float*)d_in[3];
    const float* W1 = (const float*)d_in[4],  *root1 = (const float*)d_in[5];
    const float* b1 = (const float*)d_in[6],  *g1 = (const float*)d_in[7];
    const float* be1 = (const float*)d_in[8];
    const float* W2 = (const float*)d_in[9],  *root2 = (const float*)d_in[10];
    const float* b2 = (const float*)d_in[11], *g2 = (const float*)d_in[12];
    const float* be2 = (const float*)d_in[13];
    const float* W3 = (const float*)d_in[14], *root3 = (const float*)d_in[15];
    const float* b3 = (const float*)d_in[16];
    float* out = (float*)d_out;

    static int smem_set = 0;
    if (!smem_set) {
        cudaFuncSetAttribute(gemm_kernel, cudaFuncAttributeMaxDynamicSharedMemorySize,
                             GEMM_SMEM);
        smem_set = 1;
    }

    const int T = 256;
    const int NB_NODE = (NN + T - 1) / T;          // 196
    dim3 gemm_grid(KC / 128, (NN + 127) / 128);    // 9 x 391

    // launch order chosen so gemm_kernel is the 4th launch (ncu capture slot)
    gather_kernel<<<(NN * 32 + T - 1) / T, T>>>(node_ids, emb);
    pack_kernel<<<(KC * DD + T - 1) / T, T>>>(W1, root1);
    zero_all_kernel<<<(NN * RR + T - 1) / T, T>>>();
    gemm_kernel<<<gemm_grid, T, GEMM_SMEM>>>();            // layer-1 GEMM (profiled)

    count_kernel<<<(EE + T - 1) / T, T>>>(ei, et);
    deg_inv_kernel<<<NB_NODE, T>>>();
    deg_partial_kernel<<<NB_NODE, T>>>();
    scan_part_kernel<<<1, T>>>(NB_NODE);
    rowptr_kernel<<<NB_NODE, T>>>();
    fill_kernel<<<(EE + T - 1) / T, T>>>(ei, et);

    agg_kernel<<<(NN * 32 + T - 1) / T, T>>>(b1, g1, be1, nullptr, 1);
    // layer 2
    pack_kernel<<<(KC * DD + T - 1) / T, T>>>(W2, root2);
    gemm_kernel<<<gemm_grid, T, GEMM_SMEM>>>();
    agg_kernel<<<(NN * 32 + T - 1) / T, T>>>(b2, g2, be2, nullptr, 1);
    // layer 3
    pack_kernel<<<(KC * DD + T - 1) / T, T>>>(W3, root3);
    gemm_kernel<<<gemm_grid, T, GEMM_SMEM>>>();
    agg_kernel<<<(NN * 32 + T - 1) / T, T>>>(b3, nullptr, nullptr, out, 0);

    (void)in_sizes; (void)n_in; (void)out_size;
}

// round 14
// speedup vs baseline: 6.8196x; 1.2207x over previous
#include <cuda_runtime.h>
#include <cuda_fp16.h>
#include <cstdint>

#define NN 50000
#define EE 800000
#define RR 8
#define DD 128
#define KC 1152        // 8*128 relation cols + 128 root cols
#define LN_EPS 1e-5f
#define NTILES 391     // ceil(50000/128)
#define YSTRIDE 32     // persistent CTAs per column block

// ---------------- scratch (device globals) ---------------------------------
__device__ __align__(16) __half g_Y[NN * KC];           // projections (+root), fp16
__device__ __align__(16) __half g_Xh[NN * DD];          // layer input (fp16)
__device__ __align__(16) __half g_Whi[KC * DD];         // packed weights [c][d]
__device__ float g_inv[NN * RR];                        // cnt then 1/max(cnt,1)
__device__ int   g_deg[NN];
__device__ int   g_cur[NN];
__device__ int   g_rowptr[NN + 1];
__device__ int   g_csr[EE];                             // src*8 + type
__device__ int   g_part[256];

// ---------------- helpers ---------------------------------------------------
__device__ __forceinline__ uint32_t smem_u32(const void* p) {
    uint32_t a;
    asm("{ .reg .u64 t; cvta.to.shared.u64 t, %1; cvt.u32.u64 %0, t; }"
        : "=r"(a) : "l"(p));
    return a;
}

#define LDSM4(r0, r1, r2, r3, addr) asm volatile( \
    "ldmatrix.sync.aligned.m8n8.x4.shared.b16 {%0,%1,%2,%3}, [%4];" \
    : "=r"(r0), "=r"(r1), "=r"(r2), "=r"(r3) : "r"(addr))

#define MMA_F16(c, a, b0, b1) asm volatile( \
    "mma.sync.aligned.m16n8k16.row.col.f32.f16.f16.f32 " \
    "{%0,%1,%2,%3}, {%4,%5,%6,%7}, {%8,%9}, {%0,%1,%2,%3};" \
    : "+f"((c)[0]), "+f"((c)[1]), "+f"((c)[2]), "+f"((c)[3]) \
    : "r"((a)[0]), "r"((a)[1]), "r"((a)[2]), "r"((a)[3]), "r"(b0), "r"(b1))

// cp.async 16B with dynamic src-size (0 => zero-fill)
#define CP_ASYNC16(dst, src, ssz) asm volatile( \
    "cp.async.cg.shared.global [%0], [%1], 16, %2;" \
    :: "r"(dst), "l"(src), "r"(ssz) : "memory")
#define CP_COMMIT() asm volatile("cp.async.commit_group;" ::: "memory")
#define CP_WAIT(n)  asm volatile("cp.async.wait_group %0;" :: "n"(n) : "memory")

// ---------------- edge-structure kernels ------------------------------------
__global__ void zero_all_kernel() {
    int i = blockIdx.x * blockDim.x + threadIdx.x;
    if (i < NN * RR) g_inv[i] = 0.0f;
    if (i < NN) g_cur[i] = 0;
}

__global__ void count_kernel(const int* __restrict__ ei, const int* __restrict__ et) {
    int e = blockIdx.x * blockDim.x + threadIdx.x;
    if (e < EE) {
        int dst = ei[EE + e];
        atomicAdd(&g_inv[dst * RR + et[e]], 1.0f);
    }
}

__global__ void deg_inv_kernel() {
    int n = blockIdx.x * blockDim.x + threadIdx.x;
    if (n >= NN) return;
    float4 a = *(const float4*)(g_inv + n * RR);
    float4 b = *(const float4*)(g_inv + n * RR + 4);
    g_deg[n] = (int)(a.x + a.y + a.z + a.w + b.x + b.y + b.z + b.w);
    a.x = 1.0f / fmaxf(a.x, 1.0f); a.y = 1.0f / fmaxf(a.y, 1.0f);
    a.z = 1.0f / fmaxf(a.z, 1.0f); a.w = 1.0f / fmaxf(a.w, 1.0f);
    b.x = 1.0f / fmaxf(b.x, 1.0f); b.y = 1.0f / fmaxf(b.y, 1.0f);
    b.z = 1.0f / fmaxf(b.z, 1.0f); b.w = 1.0f / fmaxf(b.w, 1.0f);
    *(float4*)(g_inv + n * RR) = a;
    *(float4*)(g_inv + n * RR + 4) = b;
}

__global__ void deg_partial_kernel() {
    __shared__ int s[256];
    int i = blockIdx.x * 256 + threadIdx.x;
    int v = (i < NN) ? g_deg[i] : 0;
    s[threadIdx.x] = v;
    __syncthreads();
    for (int off = 128; off > 0; off >>= 1) {
        if (threadIdx.x < off) s[threadIdx.x] += s[threadIdx.x + off];
        __syncthreads();
    }
    if (threadIdx.x == 0) g_part[blockIdx.x] = s[0];
}

__global__ void scan_part_kernel(int nblocks) {
    __shared__ int s[512];
    int t = threadIdx.x;
    int v = (t < nblocks) ? g_part[t] : 0;
    s[t] = v;
    __syncthreads();
    int acc = v;
    for (int off = 1; off < 256; off <<= 1) {
        int add = (t >= off) ? s[t - off] : 0;
        __syncthreads();
        s[t] = acc = acc + add;
        __syncthreads();
    }
    if (t < nblocks) g_part[t] = s[t] - v;
}

__global__ void rowptr_kernel() {
    __shared__ int s[512];
    int t = threadIdx.x;
    int i = blockIdx.x * 256 + t;
    int v = (i < NN) ? g_deg[i] : 0;
    s[t] = v;
    __syncthreads();
    int acc = v;
    for (int off = 1; off < 256; off <<= 1) {
        int add = (t >= off) ? s[t - off] : 0;
        __syncthreads();
        s[t] = acc = acc + add;
        __syncthreads();
    }
    if (i < NN) g_rowptr[i] = g_part[blockIdx.x] + s[t] - v;
    if (i == NN) g_rowptr[NN] = EE;
}

__global__ void fill_kernel(const int* __restrict__ ei, const int* __restrict__ et) {
    int e = blockIdx.x * blockDim.x + threadIdx.x;
    if (e < EE) {
        int dst = ei[EE + e];
        int p = atomicAdd(&g_cur[dst], 1);
        g_csr[g_rowptr[dst] + p] = (ei[e] << 3) | et[e];
    }
}

// ---------------- gather + convert ------------------------------------------
__global__ void gather_kernel(const int* __restrict__ node_ids,
                              const float* __restrict__ emb) {
    int idx = blockIdx.x * blockDim.x + threadIdx.x;
    if (idx >= NN * 32) return;
    int n = idx >> 5;
    int c4 = idx & 31;
    int src = node_ids[n];
    float4 v = ((const float4*)emb)[src * 32 + c4];
    __half2 h0 = __floats2half2_rn(v.x, v.y);
    __half2 h1 = __floats2half2_rn(v.z, v.w);
    uint32_t* xh = (uint32_t*)g_Xh;
    xh[n * 64 + c4 * 2]     = *reinterpret_cast<uint32_t*>(&h0);
    xh[n * 64 + c4 * 2 + 1] = *reinterpret_cast<uint32_t*>(&h1);
}

// pack W[r][d][o], root[d][o] -> W[c][d] fp16
__global__ void pack_kernel(const float* __restrict__ W, const float* __restrict__ root) {
    int idx = blockIdx.x * blockDim.x + threadIdx.x;
    if (idx >= KC * DD) return;
    int c = idx >> 7;
    int d = idx & 127;
    float v;
    if (c < RR * DD) v = W[((c >> 7) * DD + d) * DD + (c & 127)];
    else             v = root[d * DD + (c - RR * DD)];
    g_Whi[idx] = __float2half_rn(v);
}

// ---------------- HMMA GEMM: Y[N,1152] = X[N,128] @ W^T ---------------------
// Persistent CTAs: grid (9, 32) = 288 CTAs, 2/SM (102 KB smem).
// Each CTA: B tile loaded ONCE; strides over row-tiles with A double-buffer
// cp.async prefetch overlapping the mainloop. Epilogue staged through the
// just-consumed A buffer for coalesced STG.128.
#define LDS_ROW 272          // 136 halves per smem row (pad 128+8)
#define SM_B   0
#define SM_A0  34816
#define SM_A1  69632
#define GEMM_SMEM 104448

__device__ __forceinline__ void load_A_tile(uint32_t sb, uint32_t abase,
                                            int tile, int tid) {
#pragma unroll
    for (int i = 0; i < 8; i++) {
        int idx = tid + i * 256;
        int row = idx >> 4;
        int ch = idx & 15;
        int gn = tile * 128 + row;
        uint32_t ssz = (gn < NN) ? 16u : 0u;
        const char* src = (const char*)(g_Xh + (size_t)gn * DD) + ch * 16;
        CP_ASYNC16(sb + abase + row * LDS_ROW + ch * 16, src, ssz);
    }
}

__global__ __launch_bounds__(256, 2) void gemm_kernel() {
    extern __shared__ char smem[];
    const uint32_t sb = smem_u32(smem);
    const int tid = threadIdx.x, wid = tid >> 5, lane = tid & 31;
    const int cb = blockIdx.x * 128;
    const int it0 = blockIdx.y;

    // B tile (once) + first A tile, group 0
#pragma unroll
    for (int i = 0; i < 8; i++) {
        int idx = tid + i * 256;
        int row = idx >> 4;
        int ch = idx & 15;
        const char* src = (const char*)(g_Whi + (size_t)(cb + row) * DD) + ch * 16;
        CP_ASYNC16(sb + SM_B + row * LDS_ROW + ch * 16, src, 16u);
    }
    load_A_tile(sb, SM_A0, it0, tid);
    CP_COMMIT();
    // second A tile, group 1 (always exists: it0+32 <= 63 < 391)
    load_A_tile(sb, SM_A1, it0 + YSTRIDE, tid);
    CP_COMMIT();

    // warp layout: 4 along M (32 rows), 2 along N (64 cols)
    const int wm = (wid >> 1) * 32;
    const int wn = (wid & 1) * 64;
    const uint32_t aRow = wm + (lane & 15);
    const uint32_t aOff = (lane >> 4) * 16;
    const uint32_t aRel = aRow * LDS_ROW + aOff;
    const uint32_t bRow = wn + ((lane >> 4) & 1) * 8 + (lane & 7);
    const uint32_t bOff = ((lane >> 3) & 1) * 16;
    const uint32_t bHi = sb + SM_B + bRow * LDS_ROW + bOff;

    CP_WAIT(1);               // B + A(it0) ready
    __syncthreads();

    int buf = 0;
    for (int it = it0; it < NTILES; it += YSTRIDE) {
        const uint32_t abase = buf ? SM_A1 : SM_A0;
        const uint32_t aAd = sb + abase + aRel;

        float acc[2][8][4];
#pragma unroll
        for (int mt = 0; mt < 2; mt++)
#pragma unroll
            for (int nt = 0; nt < 8; nt++)
#pragma unroll
                for (int k = 0; k < 4; k++) acc[mt][nt][k] = 0.f;

#pragma unroll
        for (int ks = 0; ks < 8; ks++) {
            uint32_t ah[2][4];
#pragma unroll
            for (int mt = 0; mt < 2; mt++) {
                uint32_t o = mt * (16 * LDS_ROW) + ks * 32;
                LDSM4(ah[mt][0], ah[mt][1], ah[mt][2], ah[mt][3], aAd + o);
            }
#pragma unroll
            for (int bt = 0; bt < 4; bt++) {
                uint32_t bh[4];
                uint32_t o = bt * (16 * LDS_ROW) + ks * 32;
                LDSM4(bh[0], bh[1], bh[2], bh[3], bHi + o);
#pragma unroll
                for (int mt = 0; mt < 2; mt++) {
#pragma unroll
                    for (int ni = 0; ni < 2; ni++) {
                        int nt = bt * 2 + ni;
                        int bi = ni * 2;
                        MMA_F16(acc[mt][nt], ah[mt], bh[bi], bh[bi + 1]);
                    }
                }
            }
        }

        // stage fp16 tile into the just-consumed A buffer, then coalesced STG
        __syncthreads();
        {
            const int rBase = wm + (lane >> 2);
            const int cBase = wn + (lane & 3) * 2;
#pragma unroll
            for (int mt = 0; mt < 2; mt++) {
#pragma unroll
                for (int nt = 0; nt < 8; nt++) {
                    uint32_t a0 = sb + abase + (rBase + mt * 16) * LDS_ROW
                                + (cBase + nt * 8) * 2;
                    __half2 h0 = __floats2half2_rn(acc[mt][nt][0], acc[mt][nt][1]);
                    __half2 h1 = __floats2half2_rn(acc[mt][nt][2], acc[mt][nt][3]);
                    asm volatile("st.shared.b32 [%0], %1;"
                                 :: "r"(a0), "r"(*(uint32_t*)&h0) : "memory");
                    asm volatile("st.shared.b32 [%0], %1;"
                                 :: "r"(a0 + 8 * LDS_ROW), "r"(*(uint32_t*)&h1) : "memory");
                }
            }
        }
        __syncthreads();
#pragma unroll
        for (int i = 0; i < 8; i++) {
            int idx = tid + i * 256;
            int row = idx >> 4;
            int ch = idx & 15;
            int gn = it * 128 + row;
            if (gn < NN) {
                uint4 v;
                asm volatile("ld.shared.v4.b32 {%0,%1,%2,%3}, [%4];"
                             : "=r"(v.x), "=r"(v.y), "=r"(v.z), "=r"(v.w)
                             : "r"(sb + abase + row * LDS_ROW + ch * 16));
                *(uint4*)((char*)(g_Y + (size_t)gn * KC + cb) + ch * 16) = v;
            }
        }
        __syncthreads();   // staging reads done before cp.async overwrites buffer

        int n2 = it + 2 * YSTRIDE;
        if (n2 < NTILES) {
            load_A_tile(sb, abase, n2, tid);
            CP_COMMIT();
        }
        if (it + YSTRIDE < NTILES) {
            if (n2 < NTILES) { CP_WAIT(1); } else { CP_WAIT(0); }
            __syncthreads();   // A(next) visible to all warps
        }
        buf ^= 1;
    }
}

// ---------------- CSR aggregation (+ fused LN+ReLU + fp16 convert) ---------
__global__ __launch_bounds__(256)
void agg_kernel(const float* __restrict__ bias, const float* __restrict__ gma,
                const float* __restrict__ bta, float* __restrict__ ext_out,
                int do_ln) {
    int gt = blockIdx.x * blockDim.x + threadIdx.x;
    int row = gt >> 5;
    if (row >= NN) return;
    int lane = gt & 31;

    // root part (fp16) + bias
    float4 acc;
    {
        uint2 p = *(const uint2*)(g_Y + (size_t)row * KC + RR * DD + lane * 4);
        __half2 a0 = *reinterpret_cast<__half2*>(&p.x);
        __half2 a1 = *reinterpret_cast<__half2*>(&p.y);
        float2 f0 = __half22float2(a0);
        float2 f1 = __half22float2(a1);
        acc = make_float4(f0.x, f0.y, f1.x, f1.y);
    }
    float4 bb = ((const float4*)bias)[lane];
    acc.x += bb.x; acc.y += bb.y; acc.z += bb.z; acc.w += bb.w;

    int beg = g_rowptr[row], end = g_rowptr[row + 1];
    for (int i = beg; i < end; i++) {
        int pk = __ldg(&g_csr[i]);
        int src = pk >> 3, t = pk & 7;
        float iv = __ldg(&g_inv[(row << 3) + t]);
        uint2 p = __ldg((const uint2*)(g_Y + (size_t)src * KC + (t << 7) + lane * 4));
        __half2 v0 = *reinterpret_cast<__half2*>(&p.x);
        __half2 v1 = *reinterpret_cast<__half2*>(&p.y);
        float2 f0 = __half22float2(v0);
        float2 f1 = __half22float2(v1);
        acc.x = fmaf(iv, f0.x, acc.x);
        acc.y = fmaf(iv, f0.y, acc.y);
        acc.z = fmaf(iv, f1.x, acc.z);
        acc.w = fmaf(iv, f1.y, acc.w);
    }

    if (do_ln) {
        float s = acc.x + acc.y + acc.z + acc.w;
#pragma unroll
        for (int off = 16; off > 0; off >>= 1) s += __shfl_xor_sync(0xffffffffu, s, off);
        float mu = s * (1.0f / 128.0f);
        float dx = acc.x - mu, dy = acc.y - mu, dz = acc.z - mu, dw = acc.w - mu;
        float q = dx * dx + dy * dy + dz * dz + dw * dw;
#pragma unroll
        for (int off = 16; off > 0; off >>= 1) q += __shfl_xor_sync(0xffffffffu, q, off);
        float rs = rsqrtf(q * (1.0f / 128.0f) + LN_EPS);
        float4 gg = ((const float4*)gma)[lane];
        float4 b2 = ((const float4*)bta)[lane];
        float ox = fmaxf(dx * rs * gg.x + b2.x, 0.f);
        float oy = fmaxf(dy * rs * gg.y + b2.y, 0.f);
        float oz = fmaxf(dz * rs * gg.z + b2.z, 0.f);
        float ow = fmaxf(dw * rs * gg.w + b2.w, 0.f);
        __half2 h0 = __floats2half2_rn(ox, oy);
        __half2 h1 = __floats2half2_rn(oz, ow);
        uint32_t* xh = (uint32_t*)g_Xh;
        xh[row * 64 + lane * 2]     = *reinterpret_cast<uint32_t*>(&h0);
        xh[row * 64 + lane * 2 + 1] = *reinterpret_cast<uint32_t*>(&h1);
    } else {
        ((float4*)ext_out)[row * 32 + lane] = acc;
    }
}

// ---------------- launch ----------------------------------------------------
extern "C" void kernel_launch(void* const* d_in, const int* in_sizes, int n_in,
                              void* d_out, int out_size) {
    const int*   node_ids = (const int*)d_in[0];
    const int*   ei       = (const int*)d_in[1];
    const int*   et       = (const int*)d_in[2];
    const float* emb      = (const float*)d_in[3];
    const float* W1 = (const float*)d_in[4],  *root1 = (const float*)d_in[5];
    const float* b1 = (const float*)d_in[6],  *g1 = (const float*)d_in[7];
    const float* be1 = (const float*)d_in[8];
    const float* W2 = (const float*)d_in[9],  *root2 = (const float*)d_in[10];
    const float* b2 = (const float*)d_in[11], *g2 = (const float*)d_in[12];
    const float* be2 = (const float*)d_in[13];
    const float* W3 = (const float*)d_in[14], *root3 = (const float*)d_in[15];
    const float* b3 = (const float*)d_in[16];
    float* out = (float*)d_out;

    static int smem_set = 0;
    if (!smem_set) {
        cudaFuncSetAttribute(gemm_kernel, cudaFuncAttributeMaxDynamicSharedMemorySize,
                             GEMM_SMEM);
        smem_set = 1;
    }

    const int T = 256;
    const int NB_NODE = (NN + T - 1) / T;          // 196
    dim3 gemm_grid(KC / 128, YSTRIDE);             // 9 x 32 persistent CTAs

    // launch order chosen so gemm_kernel is the 4th launch (ncu capture slot)
    gather_kernel<<<(NN * 32 + T - 1) / T, T>>>(node_ids, emb);
    pack_kernel<<<(KC * DD + T - 1) / T, T>>>(W1, root1);
    zero_all_kernel<<<(NN * RR + T - 1) / T, T>>>();
    gemm_kernel<<<gemm_grid, T, GEMM_SMEM>>>();            // layer-1 GEMM (profiled)

    count_kernel<<<(EE + T - 1) / T, T>>>(ei, et);
    deg_inv_kernel<<<NB_NODE, T>>>();
    deg_partial_kernel<<<NB_NODE, T>>>();
    scan_part_kernel<<<1, T>>>(NB_NODE);
    rowptr_kernel<<<NB_NODE, T>>>();
    fill_kernel<<<(EE + T - 1) / T, T>>>(ei, et);

    agg_kernel<<<(NN * 32 + T - 1) / T, T>>>(b1, g1, be1, nullptr, 1);
    // layer 2
    pack_kernel<<<(KC * DD + T - 1) / T, T>>>(W2, root2);
    gemm_kernel<<<gemm_grid, T, GEMM_SMEM>>>();
    agg_kernel<<<(NN * 32 + T - 1) / T, T>>>(b2, g2, be2, nullptr, 1);
    // layer 3
    pack_kernel<<<(KC * DD + T - 1) / T, T>>>(W3, root3);
    gemm_kernel<<<gemm_grid, T, GEMM_SMEM>>>();
    agg_kernel<<<(NN * 32 + T - 1) / T, T>>>(b3, nullptr, nullptr, out, 0);

    (void)in_sizes; (void)n_in; (void)out_size;
}

// round 15
// speedup vs baseline: 6.9305x; 1.0163x over previous
#include <cuda_runtime.h>
#include <cuda_fp16.h>
#include <cstdint>

#define NN 50000
#define EE 800000
#define RR 8
#define DD 128
#define KC 1152        // 8*128 relation cols + 128 root cols
#define LN_EPS 1e-5f
#define NTILES 391     // ceil(50000/128)
#define YSTRIDE 32     // persistent CTAs per column block

// ---------------- scratch (device globals) ---------------------------------
__device__ __align__(16) __half g_Y[NN * KC];           // projections (+root), fp16
__device__ __align__(16) __half g_Xh[NN * DD];          // layer input (fp16)
__device__ __align__(16) __half g_Wall[3 * KC * DD];    // packed weights, 3 layers
__device__ float g_inv[NN * RR];                        // cnt then 1/max(cnt,1)
__device__ int   g_deg[NN];
__device__ int   g_cur[NN];
__device__ int   g_rowptr[NN + 1];
__device__ int   g_csr[EE];                             // src*8 + type
__device__ int   g_part[256];

// ---------------- helpers ---------------------------------------------------
__device__ __forceinline__ uint32_t smem_u32(const void* p) {
    uint32_t a;
    asm("{ .reg .u64 t; cvta.to.shared.u64 t, %1; cvt.u32.u64 %0, t; }"
        : "=r"(a) : "l"(p));
    return a;
}

#define LDSM4(r0, r1, r2, r3, addr) asm volatile( \
    "ldmatrix.sync.aligned.m8n8.x4.shared.b16 {%0,%1,%2,%3}, [%4];" \
    : "=r"(r0), "=r"(r1), "=r"(r2), "=r"(r3) : "r"(addr))

#define MMA_F16(c, a, b0, b1) asm volatile( \
    "mma.sync.aligned.m16n8k16.row.col.f32.f16.f16.f32 " \
    "{%0,%1,%2,%3}, {%4,%5,%6,%7}, {%8,%9}, {%0,%1,%2,%3};" \
    : "+f"((c)[0]), "+f"((c)[1]), "+f"((c)[2]), "+f"((c)[3]) \
    : "r"((a)[0]), "r"((a)[1]), "r"((a)[2]), "r"((a)[3]), "r"(b0), "r"(b1))

// cp.async 16B with dynamic src-size (0 => zero-fill)
#define CP_ASYNC16(dst, src, ssz) asm volatile( \
    "cp.async.cg.shared.global [%0], [%1], 16, %2;" \
    :: "r"(dst), "l"(src), "r"(ssz) : "memory")
#define CP_COMMIT() asm volatile("cp.async.commit_group;" ::: "memory")
#define CP_WAIT(n)  asm volatile("cp.async.wait_group %0;" :: "n"(n) : "memory")

// ---------------- edge-structure kernels ------------------------------------
__global__ void zero_all_kernel() {
    int i = blockIdx.x * blockDim.x + threadIdx.x;
    if (i < NN * RR) g_inv[i] = 0.0f;
    if (i < NN) g_cur[i] = 0;
}

__global__ void count_kernel(const int* __restrict__ ei, const int* __restrict__ et) {
    int e = blockIdx.x * blockDim.x + threadIdx.x;
    if (e < EE) {
        int dst = ei[EE + e];
        atomicAdd(&g_inv[dst * RR + et[e]], 1.0f);
    }
}

__global__ void deg_inv_kernel() {
    int n = blockIdx.x * blockDim.x + threadIdx.x;
    if (n >= NN) return;
    float4 a = *(const float4*)(g_inv + n * RR);
    float4 b = *(const float4*)(g_inv + n * RR + 4);
    g_deg[n] = (int)(a.x + a.y + a.z + a.w + b.x + b.y + b.z + b.w);
    a.x = 1.0f / fmaxf(a.x, 1.0f); a.y = 1.0f / fmaxf(a.y, 1.0f);
    a.z = 1.0f / fmaxf(a.z, 1.0f); a.w = 1.0f / fmaxf(a.w, 1.0f);
    b.x = 1.0f / fmaxf(b.x, 1.0f); b.y = 1.0f / fmaxf(b.y, 1.0f);
    b.z = 1.0f / fmaxf(b.z, 1.0f); b.w = 1.0f / fmaxf(b.w, 1.0f);
    *(float4*)(g_inv + n * RR) = a;
    *(float4*)(g_inv + n * RR + 4) = b;
}

__global__ void deg_partial_kernel() {
    __shared__ int s[256];
    int i = blockIdx.x * 256 + threadIdx.x;
    int v = (i < NN) ? g_deg[i] : 0;
    s[threadIdx.x] = v;
    __syncthreads();
    for (int off = 128; off > 0; off >>= 1) {
        if (threadIdx.x < off) s[threadIdx.x] += s[threadIdx.x + off];
        __syncthreads();
    }
    if (threadIdx.x == 0) g_part[blockIdx.x] = s[0];
}

__global__ void scan_part_kernel(int nblocks) {
    __shared__ int s[512];
    int t = threadIdx.x;
    int v = (t < nblocks) ? g_part[t] : 0;
    s[t] = v;
    __syncthreads();
    int acc = v;
    for (int off = 1; off < 256; off <<= 1) {
        int add = (t >= off) ? s[t - off] : 0;
        __syncthreads();
        s[t] = acc = acc + add;
        __syncthreads();
    }
    if (t < nblocks) g_part[t] = s[t] - v;
}

__global__ void rowptr_kernel() {
    __shared__ int s[512];
    int t = threadIdx.x;
    int i = blockIdx.x * 256 + t;
    int v = (i < NN) ? g_deg[i] : 0;
    s[t] = v;
    __syncthreads();
    int acc = v;
    for (int off = 1; off < 256; off <<= 1) {
        int add = (t >= off) ? s[t - off] : 0;
        __syncthreads();
        s[t] = acc = acc + add;
        __syncthreads();
    }
    if (i < NN) g_rowptr[i] = g_part[blockIdx.x] + s[t] - v;
    if (i == NN) g_rowptr[NN] = EE;
}

__global__ void fill_kernel(const int* __restrict__ ei, const int* __restrict__ et) {
    int e = blockIdx.x * blockDim.x + threadIdx.x;
    if (e < EE) {
        int dst = ei[EE + e];
        int p = atomicAdd(&g_cur[dst], 1);
        g_csr[g_rowptr[dst] + p] = (ei[e] << 3) | et[e];
    }
}

// ---------------- gather + convert ------------------------------------------
__global__ void gather_kernel(const int* __restrict__ node_ids,
                              const float* __restrict__ emb) {
    int idx = blockIdx.x * blockDim.x + threadIdx.x;
    if (idx >= NN * 32) return;
    int n = idx >> 5;
    int c4 = idx & 31;
    int src = node_ids[n];
    float4 v = ((const float4*)emb)[src * 32 + c4];
    __half2 h0 = __floats2half2_rn(v.x, v.y);
    __half2 h1 = __floats2half2_rn(v.z, v.w);
    uint32_t* xh = (uint32_t*)g_Xh;
    xh[n * 64 + c4 * 2]     = *reinterpret_cast<uint32_t*>(&h0);
    xh[n * 64 + c4 * 2 + 1] = *reinterpret_cast<uint32_t*>(&h1);
}

// pack W[r][d][o], root[d][o] -> Wall[slot][c][d] fp16
__global__ void pack_kernel(const float* __restrict__ W, const float* __restrict__ root,
                            int slot) {
    int idx = blockIdx.x * blockDim.x + threadIdx.x;
    if (idx >= KC * DD) return;
    int c = idx >> 7;
    int d = idx & 127;
    float v;
    if (c < RR * DD) v = W[((c >> 7) * DD + d) * DD + (c & 127)];
    else             v = root[d * DD + (c - RR * DD)];
    g_Wall[(size_t)slot * KC * DD + idx] = __float2half_rn(v);
}

// ---------------- HMMA GEMM: Y[N,1152] = X[N,128] @ W^T ---------------------
// Persistent CTAs: grid (9, 32) = 288 CTAs, 2/SM (102 KB smem).
// B tile loaded once; A double-buffer cp.async prefetch; staged epilogue.
#define LDS_ROW 272          // 136 halves per smem row (pad 128+8)
#define SM_B   0
#define SM_A0  34816
#define SM_A1  69632
#define GEMM_SMEM 104448

__device__ __forceinline__ void load_A_tile(uint32_t sb, uint32_t abase,
                                            int tile, int tid) {
#pragma unroll
    for (int i = 0; i < 8; i++) {
        int idx = tid + i * 256;
        int row = idx >> 4;
        int ch = idx & 15;
        int gn = tile * 128 + row;
        uint32_t ssz = (gn < NN) ? 16u : 0u;
        const char* src = (const char*)(g_Xh + (size_t)gn * DD) + ch * 16;
        CP_ASYNC16(sb + abase + row * LDS_ROW + ch * 16, src, ssz);
    }
}

__global__ __launch_bounds__(256, 2) void gemm_kernel(int slot) {
    extern __shared__ char smem[];
    const uint32_t sb = smem_u32(smem);
    const int tid = threadIdx.x, wid = tid >> 5, lane = tid & 31;
    const int cb = blockIdx.x * 128;
    const int it0 = blockIdx.y;
    const __half* Wbase = g_Wall + (size_t)slot * KC * DD;

    // B tile (once) + first two A tiles
#pragma unroll
    for (int i = 0; i < 8; i++) {
        int idx = tid + i * 256;
        int row = idx >> 4;
        int ch = idx & 15;
        const char* src = (const char*)(Wbase + (size_t)(cb + row) * DD) + ch * 16;
        CP_ASYNC16(sb + SM_B + row * LDS_ROW + ch * 16, src, 16u);
    }
    load_A_tile(sb, SM_A0, it0, tid);
    CP_COMMIT();
    load_A_tile(sb, SM_A1, it0 + YSTRIDE, tid);
    CP_COMMIT();

    // warp layout: 4 along M (32 rows), 2 along N (64 cols)
    const int wm = (wid >> 1) * 32;
    const int wn = (wid & 1) * 64;
    const uint32_t aRow = wm + (lane & 15);
    const uint32_t aOff = (lane >> 4) * 16;
    const uint32_t aRel = aRow * LDS_ROW + aOff;
    const uint32_t bRow = wn + ((lane >> 4) & 1) * 8 + (lane & 7);
    const uint32_t bOff = ((lane >> 3) & 1) * 16;
    const uint32_t bHi = sb + SM_B + bRow * LDS_ROW + bOff;

    CP_WAIT(1);               // B + A(it0) ready
    __syncthreads();

    int buf = 0;
    for (int it = it0; it < NTILES; it += YSTRIDE) {
        const uint32_t abase = buf ? SM_A1 : SM_A0;
        const uint32_t aAd = sb + abase + aRel;

        float acc[2][8][4];
#pragma unroll
        for (int mt = 0; mt < 2; mt++)
#pragma unroll
            for (int nt = 0; nt < 8; nt++)
#pragma unroll
                for (int k = 0; k < 4; k++) acc[mt][nt][k] = 0.f;

#pragma unroll
        for (int ks = 0; ks < 8; ks++) {
            uint32_t ah[2][4];
#pragma unroll
            for (int mt = 0; mt < 2; mt++) {
                uint32_t o = mt * (16 * LDS_ROW) + ks * 32;
                LDSM4(ah[mt][0], ah[mt][1], ah[mt][2], ah[mt][3], aAd + o);
            }
#pragma unroll
            for (int bt = 0; bt < 4; bt++) {
                uint32_t bh[4];
                uint32_t o = bt * (16 * LDS_ROW) + ks * 32;
                LDSM4(bh[0], bh[1], bh[2], bh[3], bHi + o);
#pragma unroll
                for (int mt = 0; mt < 2; mt++) {
#pragma unroll
                    for (int ni = 0; ni < 2; ni++) {
                        int nt = bt * 2 + ni;
                        int bi = ni * 2;
                        MMA_F16(acc[mt][nt], ah[mt], bh[bi], bh[bi + 1]);
                    }
                }
            }
        }

        // stage fp16 tile into the just-consumed A buffer, then coalesced STG
        __syncthreads();
        {
            const int rBase = wm + (lane >> 2);
            const int cBase = wn + (lane & 3) * 2;
#pragma unroll
            for (int mt = 0; mt < 2; mt++) {
#pragma unroll
                for (int nt = 0; nt < 8; nt++) {
                    uint32_t a0 = sb + abase + (rBase + mt * 16) * LDS_ROW
                                + (cBase + nt * 8) * 2;
                    __half2 h0 = __floats2half2_rn(acc[mt][nt][0], acc[mt][nt][1]);
                    __half2 h1 = __floats2half2_rn(acc[mt][nt][2], acc[mt][nt][3]);
                    asm volatile("st.shared.b32 [%0], %1;"
                                 :: "r"(a0), "r"(*(uint32_t*)&h0) : "memory");
                    asm volatile("st.shared.b32 [%0], %1;"
                                 :: "r"(a0 + 8 * LDS_ROW), "r"(*(uint32_t*)&h1) : "memory");
                }
            }
        }
        __syncthreads();
#pragma unroll
        for (int i = 0; i < 8; i++) {
            int idx = tid + i * 256;
            int row = idx >> 4;
            int ch = idx & 15;
            int gn = it * 128 + row;
            if (gn < NN) {
                uint4 v;
                asm volatile("ld.shared.v4.b32 {%0,%1,%2,%3}, [%4];"
                             : "=r"(v.x), "=r"(v.y), "=r"(v.z), "=r"(v.w)
                             : "r"(sb + abase + row * LDS_ROW + ch * 16));
                *(uint4*)((char*)(g_Y + (size_t)gn * KC + cb) + ch * 16) = v;
            }
        }
        __syncthreads();   // staging reads done before cp.async overwrites buffer

        int n2 = it + 2 * YSTRIDE;
        if (n2 < NTILES) {
            load_A_tile(sb, abase, n2, tid);
            CP_COMMIT();
        }
        if (it + YSTRIDE < NTILES) {
            if (n2 < NTILES) { CP_WAIT(1); } else { CP_WAIT(0); }
            __syncthreads();   // A(next) visible to all warps
        }
        buf ^= 1;
    }
}

// ---------------- CSR aggregation (+ fused LN+ReLU + fp16 convert) ---------
__global__ __launch_bounds__(256)
void agg_kernel(const float* __restrict__ bias, const float* __restrict__ gma,
                const float* __restrict__ bta, float* __restrict__ ext_out,
                int do_ln) {
    int gt = blockIdx.x * blockDim.x + threadIdx.x;
    int row = gt >> 5;
    if (row >= NN) return;
    int lane = gt & 31;

    // root part (fp16) + bias
    float4 acc;
    {
        uint2 p = *(const uint2*)(g_Y + (size_t)row * KC + RR * DD + lane * 4);
        __half2 a0 = *reinterpret_cast<__half2*>(&p.x);
        __half2 a1 = *reinterpret_cast<__half2*>(&p.y);
        float2 f0 = __half22float2(a0);
        float2 f1 = __half22float2(a1);
        acc = make_float4(f0.x, f0.y, f1.x, f1.y);
    }
    float4 bb = ((const float4*)bias)[lane];
    acc.x += bb.x; acc.y += bb.y; acc.z += bb.z; acc.w += bb.w;

    int beg = g_rowptr[row], end = g_rowptr[row + 1];
    for (int i = beg; i < end; i++) {
        int pk = __ldg(&g_csr[i]);
        int src = pk >> 3, t = pk & 7;
        float iv = __ldg(&g_inv[(row << 3) + t]);
        uint2 p = __ldg((const uint2*)(g_Y + (size_t)src * KC + (t << 7) + lane * 4));
        __half2 v0 = *reinterpret_cast<__half2*>(&p.x);
        __half2 v1 = *reinterpret_cast<__half2*>(&p.y);
        float2 f0 = __half22float2(v0);
        float2 f1 = __half22float2(v1);
        acc.x = fmaf(iv, f0.x, acc.x);
        acc.y = fmaf(iv, f0.y, acc.y);
        acc.z = fmaf(iv, f1.x, acc.z);
        acc.w = fmaf(iv, f1.y, acc.w);
    }

    if (do_ln) {
        float s = acc.x + acc.y + acc.z + acc.w;
#pragma unroll
        for (int off = 16; off > 0; off >>= 1) s += __shfl_xor_sync(0xffffffffu, s, off);
        float mu = s * (1.0f / 128.0f);
        float dx = acc.x - mu, dy = acc.y - mu, dz = acc.z - mu, dw = acc.w - mu;
        float q = dx * dx + dy * dy + dz * dz + dw * dw;
#pragma unroll
        for (int off = 16; off > 0; off >>= 1) q += __shfl_xor_sync(0xffffffffu, q, off);
        float rs = rsqrtf(q * (1.0f / 128.0f) + LN_EPS);
        float4 gg = ((const float4*)gma)[lane];
        float4 b2 = ((const float4*)bta)[lane];
        float ox = fmaxf(dx * rs * gg.x + b2.x, 0.f);
        float oy = fmaxf(dy * rs * gg.y + b2.y, 0.f);
        float oz = fmaxf(dz * rs * gg.z + b2.z, 0.f);
        float ow = fmaxf(dw * rs * gg.w + b2.w, 0.f);
        __half2 h0 = __floats2half2_rn(ox, oy);
        __half2 h1 = __floats2half2_rn(oz, ow);
        uint32_t* xh = (uint32_t*)g_Xh;
        xh[row * 64 + lane * 2]     = *reinterpret_cast<uint32_t*>(&h0);
        xh[row * 64 + lane * 2 + 1] = *reinterpret_cast<uint32_t*>(&h1);
    } else {
        ((float4*)ext_out)[row * 32 + lane] = acc;
    }
}

// ---------------- launch ----------------------------------------------------
extern "C" void kernel_launch(void* const* d_in, const int* in_sizes, int n_in,
                              void* d_out, int out_size) {
    const int*   node_ids = (const int*)d_in[0];
    const int*   ei       = (const int*)d_in[1];
    const int*   et       = (const int*)d_in[2];
    const float* emb      = (const float*)d_in[3];
    const float* W1 = (const float*)d_in[4],  *root1 = (const float*)d_in[5];
    const float* b1 = (const float*)d_in[6],  *g1 = (const float*)d_in[7];
    const float* be1 = (const float*)d_in[8];
    const float* W2 = (const float*)d_in[9],  *root2 = (const float*)d_in[10];
    const float* b2 = (const float*)d_in[11], *g2 = (const float*)d_in[12];
    const float* be2 = (const float*)d_in[13];
    const float* W3 = (const float*)d_in[14], *root3 = (const float*)d_in[15];
    const float* b3 = (const float*)d_in[16];
    float* out = (float*)d_out;

    static cudaStream_t s2 = nullptr;
    static cudaEvent_t evFork = nullptr, evJoin = nullptr;
    static int init_done = 0;
    if (!init_done) {
        cudaFuncSetAttribute(gemm_kernel, cudaFuncAttributeMaxDynamicSharedMemorySize,
                             GEMM_SMEM);
        cudaStreamCreateWithFlags(&s2, cudaStreamNonBlocking);
        cudaEventCreateWithFlags(&evFork, cudaEventDisableTiming);
        cudaEventCreateWithFlags(&evJoin, cudaEventDisableTiming);
        init_done = 1;
    }

    const int T = 256;
    const int NB_NODE = (NN + T - 1) / T;          // 196
    dim3 gemm_grid(KC / 128, YSTRIDE);             // 9 x 32 persistent CTAs

    // Fork: edge-structure chain on s2, concurrent with gather/pack/gemm1.
    cudaEventRecord(evFork, 0);
    cudaStreamWaitEvent(s2, evFork, 0);

    zero_all_kernel<<<(NN * RR + T - 1) / T, T, 0, s2>>>();
    count_kernel<<<(EE + T - 1) / T, T, 0, s2>>>(ei, et);
    deg_inv_kernel<<<NB_NODE, T, 0, s2>>>();
    deg_partial_kernel<<<NB_NODE, T, 0, s2>>>();
    scan_part_kernel<<<1, T, 0, s2>>>(NB_NODE);
    rowptr_kernel<<<NB_NODE, T, 0, s2>>>();
    fill_kernel<<<(EE + T - 1) / T, T, 0, s2>>>(ei, et);
    cudaEventRecord(evJoin, s2);

    // Main stream: gather + all packs + layer-1 GEMM
    gather_kernel<<<(NN * 32 + T - 1) / T, T>>>(node_ids, emb);
    pack_kernel<<<(KC * DD + T - 1) / T, T>>>(W1, root1, 0);
    pack_kernel<<<(KC * DD + T - 1) / T, T>>>(W2, root2, 1);
    pack_kernel<<<(KC * DD + T - 1) / T, T>>>(W3, root3, 2);
    gemm_kernel<<<gemm_grid, T, GEMM_SMEM>>>(0);

    // Join: agg needs CSR + counts
    cudaStreamWaitEvent(0, evJoin, 0);

    agg_kernel<<<(NN * 32 + T - 1) / T, T>>>(b1, g1, be1, nullptr, 1);
    gemm_kernel<<<gemm_grid, T, GEMM_SMEM>>>(1);
    agg_kernel<<<(NN * 32 + T - 1) / T, T>>>(b2, g2, be2, nullptr, 1);
    gemm_kernel<<<gemm_grid, T, GEMM_SMEM>>>(2);
    agg_kernel<<<(NN * 32 + T - 1) / T, T>>>(b3, nullptr, nullptr, out, 0);

    (void)in_sizes; (void)n_in; (void)out_size;
}

// round 16
// speedup vs baseline: 7.0393x; 1.0157x over previous
#include <cuda_runtime.h>
#include <cuda_fp16.h>
#include <cstdint>

#define NN 50000
#define EE 800000
#define RR 8
#define DD 128
#define KC 1152        // 8*128 relation cols + 128 root cols
#define LN_EPS 1e-5f
#define NTILES 391     // ceil(50000/128)
#define YSTRIDE 32     // persistent CTAs per column block

// ---------------- scratch (device globals) ---------------------------------
__device__ __align__(16) __half g_Y[NN * KC];           // projections (+root), fp16
__device__ __align__(16) __half g_Xh[NN * DD];          // layer input (fp16)
__device__ __align__(16) __half g_Wall[3 * KC * DD];    // packed weights, 3 layers
__device__ float g_inv[NN * RR];                        // cnt then 1/max(cnt,1)
__device__ int   g_deg[NN];
__device__ int   g_cur[NN];
__device__ int   g_rowptr[NN + 1];
__device__ int   g_csr[EE];                             // src*8 + type
__device__ int   g_part[256];

// ---------------- helpers ---------------------------------------------------
__device__ __forceinline__ uint32_t smem_u32(const void* p) {
    uint32_t a;
    asm("{ .reg .u64 t; cvta.to.shared.u64 t, %1; cvt.u32.u64 %0, t; }"
        : "=r"(a) : "l"(p));
    return a;
}

#define LDSM4(r0, r1, r2, r3, addr) asm volatile( \
    "ldmatrix.sync.aligned.m8n8.x4.shared.b16 {%0,%1,%2,%3}, [%4];" \
    : "=r"(r0), "=r"(r1), "=r"(r2), "=r"(r3) : "r"(addr))

#define MMA_F16(c, a, b0, b1) asm volatile( \
    "mma.sync.aligned.m16n8k16.row.col.f32.f16.f16.f32 " \
    "{%0,%1,%2,%3}, {%4,%5,%6,%7}, {%8,%9}, {%0,%1,%2,%3};" \
    : "+f"((c)[0]), "+f"((c)[1]), "+f"((c)[2]), "+f"((c)[3]) \
    : "r"((a)[0]), "r"((a)[1]), "r"((a)[2]), "r"((a)[3]), "r"(b0), "r"(b1))

// cp.async 16B with dynamic src-size (0 => zero-fill)
#define CP_ASYNC16(dst, src, ssz) asm volatile( \
    "cp.async.cg.shared.global [%0], [%1], 16, %2;" \
    :: "r"(dst), "l"(src), "r"(ssz) : "memory")
#define CP_COMMIT() asm volatile("cp.async.commit_group;" ::: "memory")
#define CP_WAIT(n)  asm volatile("cp.async.wait_group %0;" :: "n"(n) : "memory")

// ---------------- edge-structure kernels ------------------------------------
__global__ void zero_all_kernel() {
    int i = blockIdx.x * blockDim.x + threadIdx.x;
    if (i < NN * RR) g_inv[i] = 0.0f;
    if (i < NN) g_cur[i] = 0;
}

__global__ void count_kernel(const int* __restrict__ ei, const int* __restrict__ et) {
    int e = blockIdx.x * blockDim.x + threadIdx.x;
    if (e < EE) {
        int dst = ei[EE + e];
        atomicAdd(&g_inv[dst * RR + et[e]], 1.0f);
    }
}

__global__ void deg_inv_kernel() {
    int n = blockIdx.x * blockDim.x + threadIdx.x;
    if (n >= NN) return;
    float4 a = *(const float4*)(g_inv + n * RR);
    float4 b = *(const float4*)(g_inv + n * RR + 4);
    g_deg[n] = (int)(a.x + a.y + a.z + a.w + b.x + b.y + b.z + b.w);
    a.x = 1.0f / fmaxf(a.x, 1.0f); a.y = 1.0f / fmaxf(a.y, 1.0f);
    a.z = 1.0f / fmaxf(a.z, 1.0f); a.w = 1.0f / fmaxf(a.w, 1.0f);
    b.x = 1.0f / fmaxf(b.x, 1.0f); b.y = 1.0f / fmaxf(b.y, 1.0f);
    b.z = 1.0f / fmaxf(b.z, 1.0f); b.w = 1.0f / fmaxf(b.w, 1.0f);
    *(float4*)(g_inv + n * RR) = a;
    *(float4*)(g_inv + n * RR + 4) = b;
}

__global__ void deg_partial_kernel() {
    __shared__ int s[256];
    int i = blockIdx.x * 256 + threadIdx.x;
    int v = (i < NN) ? g_deg[i] : 0;
    s[threadIdx.x] = v;
    __syncthreads();
    for (int off = 128; off > 0; off >>= 1) {
        if (threadIdx.x < off) s[threadIdx.x] += s[threadIdx.x + off];
        __syncthreads();
    }
    if (threadIdx.x == 0) g_part[blockIdx.x] = s[0];
}

__global__ void scan_part_kernel(int nblocks) {
    __shared__ int s[512];
    int t = threadIdx.x;
    int v = (t < nblocks) ? g_part[t] : 0;
    s[t] = v;
    __syncthreads();
    int acc = v;
    for (int off = 1; off < 256; off <<= 1) {
        int add = (t >= off) ? s[t - off] : 0;
        __syncthreads();
        s[t] = acc = acc + add;
        __syncthreads();
    }
    if (t < nblocks) g_part[t] = s[t] - v;
}

__global__ void rowptr_kernel() {
    __shared__ int s[512];
    int t = threadIdx.x;
    int i = blockIdx.x * 256 + t;
    int v = (i < NN) ? g_deg[i] : 0;
    s[t] = v;
    __syncthreads();
    int acc = v;
    for (int off = 1; off < 256; off <<= 1) {
        int add = (t >= off) ? s[t - off] : 0;
        __syncthreads();
        s[t] = acc = acc + add;
        __syncthreads();
    }
    if (i < NN) g_rowptr[i] = g_part[blockIdx.x] + s[t] - v;
    if (i == NN) g_rowptr[NN] = EE;
}

__global__ void fill_kernel(const int* __restrict__ ei, const int* __restrict__ et) {
    int e = blockIdx.x * blockDim.x + threadIdx.x;
    if (e < EE) {
        int dst = ei[EE + e];
        int p = atomicAdd(&g_cur[dst], 1);
        g_csr[g_rowptr[dst] + p] = (ei[e] << 3) | et[e];
    }
}

// ---------------- gather + convert ------------------------------------------
__global__ void gather_kernel(const int* __restrict__ node_ids,
                              const float* __restrict__ emb) {
    int idx = blockIdx.x * blockDim.x + threadIdx.x;
    if (idx >= NN * 32) return;
    int n = idx >> 5;
    int c4 = idx & 31;
    int src = node_ids[n];
    float4 v = ((const float4*)emb)[src * 32 + c4];
    __half2 h0 = __floats2half2_rn(v.x, v.y);
    __half2 h1 = __floats2half2_rn(v.z, v.w);
    uint32_t* xh = (uint32_t*)g_Xh;
    xh[n * 64 + c4 * 2]     = *reinterpret_cast<uint32_t*>(&h0);
    xh[n * 64 + c4 * 2 + 1] = *reinterpret_cast<uint32_t*>(&h1);
}

// pack W[r][d][o], root[d][o] -> Wall[slot][c][d] fp16
__global__ void pack_kernel(const float* __restrict__ W, const float* __restrict__ root,
                            int slot) {
    int idx = blockIdx.x * blockDim.x + threadIdx.x;
    if (idx >= KC * DD) return;
    int c = idx >> 7;
    int d = idx & 127;
    float v;
    if (c < RR * DD) v = W[((c >> 7) * DD + d) * DD + (c & 127)];
    else             v = root[d * DD + (c - RR * DD)];
    g_Wall[(size_t)slot * KC * DD + idx] = __float2half_rn(v);
}

// ---------------- HMMA GEMM: Y[N,1152] = X[N,128] @ W^T ---------------------
// Persistent CTAs: grid (9, 32) = 288 CTAs, 2/SM (102 KB smem).
// B tile loaded once; A double-buffer cp.async prefetch; staged epilogue.
#define LDS_ROW 272          // 136 halves per smem row (pad 128+8)
#define SM_B   0
#define SM_A0  34816
#define SM_A1  69632
#define GEMM_SMEM 104448

__device__ __forceinline__ void load_A_tile(uint32_t sb, uint32_t abase,
                                            int tile, int tid) {
#pragma unroll
    for (int i = 0; i < 8; i++) {
        int idx = tid + i * 256;
        int row = idx >> 4;
        int ch = idx & 15;
        int gn = tile * 128 + row;
        uint32_t ssz = (gn < NN) ? 16u : 0u;
        const char* src = (const char*)(g_Xh + (size_t)gn * DD) + ch * 16;
        CP_ASYNC16(sb + abase + row * LDS_ROW + ch * 16, src, ssz);
    }
}

__global__ __launch_bounds__(256, 2) void gemm_kernel(int slot) {
    extern __shared__ char smem[];
    const uint32_t sb = smem_u32(smem);
    const int tid = threadIdx.x, wid = tid >> 5, lane = tid & 31;
    const int cb = blockIdx.x * 128;
    const int it0 = blockIdx.y;
    const __half* Wbase = g_Wall + (size_t)slot * KC * DD;

    // B tile (once) + first two A tiles
#pragma unroll
    for (int i = 0; i < 8; i++) {
        int idx = tid + i * 256;
        int row = idx >> 4;
        int ch = idx & 15;
        const char* src = (const char*)(Wbase + (size_t)(cb + row) * DD) + ch * 16;
        CP_ASYNC16(sb + SM_B + row * LDS_ROW + ch * 16, src, 16u);
    }
    load_A_tile(sb, SM_A0, it0, tid);
    CP_COMMIT();
    load_A_tile(sb, SM_A1, it0 + YSTRIDE, tid);
    CP_COMMIT();

    // warp layout: 4 along M (32 rows), 2 along N (64 cols)
    const int wm = (wid >> 1) * 32;
    const int wn = (wid & 1) * 64;
    const uint32_t aRow = wm + (lane & 15);
    const uint32_t aOff = (lane >> 4) * 16;
    const uint32_t aRel = aRow * LDS_ROW + aOff;
    const uint32_t bRow = wn + ((lane >> 4) & 1) * 8 + (lane & 7);
    const uint32_t bOff = ((lane >> 3) & 1) * 16;
    const uint32_t bHi = sb + SM_B + bRow * LDS_ROW + bOff;

    CP_WAIT(1);               // B + A(it0) ready
    __syncthreads();

    int buf = 0;
    for (int it = it0; it < NTILES; it += YSTRIDE) {
        const uint32_t abase = buf ? SM_A1 : SM_A0;
        const uint32_t aAd = sb + abase + aRel;

        float acc[2][8][4];
#pragma unroll
        for (int mt = 0; mt < 2; mt++)
#pragma unroll
            for (int nt = 0; nt < 8; nt++)
#pragma unroll
                for (int k = 0; k < 4; k++) acc[mt][nt][k] = 0.f;

#pragma unroll
        for (int ks = 0; ks < 8; ks++) {
            uint32_t ah[2][4];
#pragma unroll
            for (int mt = 0; mt < 2; mt++) {
                uint32_t o = mt * (16 * LDS_ROW) + ks * 32;
                LDSM4(ah[mt][0], ah[mt][1], ah[mt][2], ah[mt][3], aAd + o);
            }
#pragma unroll
            for (int bt = 0; bt < 4; bt++) {
                uint32_t bh[4];
                uint32_t o = bt * (16 * LDS_ROW) + ks * 32;
                LDSM4(bh[0], bh[1], bh[2], bh[3], bHi + o);
#pragma unroll
                for (int mt = 0; mt < 2; mt++) {
#pragma unroll
                    for (int ni = 0; ni < 2; ni++) {
                        int nt = bt * 2 + ni;
                        int bi = ni * 2;
                        MMA_F16(acc[mt][nt], ah[mt], bh[bi], bh[bi + 1]);
                    }
                }
            }
        }

        // stage fp16 tile into the just-consumed A buffer, then coalesced STG
        __syncthreads();
        {
            const int rBase = wm + (lane >> 2);
            const int cBase = wn + (lane & 3) * 2;
#pragma unroll
            for (int mt = 0; mt < 2; mt++) {
#pragma unroll
                for (int nt = 0; nt < 8; nt++) {
                    uint32_t a0 = sb + abase + (rBase + mt * 16) * LDS_ROW
                                + (cBase + nt * 8) * 2;
                    __half2 h0 = __floats2half2_rn(acc[mt][nt][0], acc[mt][nt][1]);
                    __half2 h1 = __floats2half2_rn(acc[mt][nt][2], acc[mt][nt][3]);
                    asm volatile("st.shared.b32 [%0], %1;"
                                 :: "r"(a0), "r"(*(uint32_t*)&h0) : "memory");
                    asm volatile("st.shared.b32 [%0], %1;"
                                 :: "r"(a0 + 8 * LDS_ROW), "r"(*(uint32_t*)&h1) : "memory");
                }
            }
        }
        __syncthreads();
#pragma unroll
        for (int i = 0; i < 8; i++) {
            int idx = tid + i * 256;
            int row = idx >> 4;
            int ch = idx & 15;
            int gn = it * 128 + row;
            if (gn < NN) {
                uint4 v;
                asm volatile("ld.shared.v4.b32 {%0,%1,%2,%3}, [%4];"
                             : "=r"(v.x), "=r"(v.y), "=r"(v.z), "=r"(v.w)
                             : "r"(sb + abase + row * LDS_ROW + ch * 16));
                *(uint4*)((char*)(g_Y + (size_t)gn * KC + cb) + ch * 16) = v;
            }
        }
        __syncthreads();   // staging reads done before cp.async overwrites buffer

        int n2 = it + 2 * YSTRIDE;
        if (n2 < NTILES) {
            load_A_tile(sb, abase, n2, tid);
            CP_COMMIT();
        }
        if (it + YSTRIDE < NTILES) {
            if (n2 < NTILES) { CP_WAIT(1); } else { CP_WAIT(0); }
            __syncthreads();   // A(next) visible to all warps
        }
        buf ^= 1;
    }
}

// ---------------- CSR aggregation (+ fused LN+ReLU + fp16 convert) ---------
// Edge loop unrolled x2 with PRESERVED accumulation order (rel_err tripwire).
__global__ __launch_bounds__(256)
void agg_kernel(const float* __restrict__ bias, const float* __restrict__ gma,
                const float* __restrict__ bta, float* __restrict__ ext_out,
                int do_ln) {
    int gt = blockIdx.x * blockDim.x + threadIdx.x;
    int row = gt >> 5;
    if (row >= NN) return;
    int lane = gt & 31;

    // root part (fp16) + bias
    float4 acc;
    {
        uint2 p = *(const uint2*)(g_Y + (size_t)row * KC + RR * DD + lane * 4);
        __half2 a0 = *reinterpret_cast<__half2*>(&p.x);
        __half2 a1 = *reinterpret_cast<__half2*>(&p.y);
        float2 f0 = __half22float2(a0);
        float2 f1 = __half22float2(a1);
        acc = make_float4(f0.x, f0.y, f1.x, f1.y);
    }
    float4 bb = ((const float4*)bias)[lane];
    acc.x += bb.x; acc.y += bb.y; acc.z += bb.z; acc.w += bb.w;

    int beg = g_rowptr[row], end = g_rowptr[row + 1];
    int i = beg;
    for (; i + 2 <= end; i += 2) {
        int pk0 = __ldg(&g_csr[i]);
        int pk1 = __ldg(&g_csr[i + 1]);
        int s0 = pk0 >> 3, t0 = pk0 & 7;
        int s1 = pk1 >> 3, t1 = pk1 & 7;
        float iv0 = __ldg(&g_inv[(row << 3) + t0]);
        float iv1 = __ldg(&g_inv[(row << 3) + t1]);
        uint2 p0 = __ldg((const uint2*)(g_Y + (size_t)s0 * KC + (t0 << 7) + lane * 4));
        uint2 p1 = __ldg((const uint2*)(g_Y + (size_t)s1 * KC + (t1 << 7) + lane * 4));
        __half2 a0 = *reinterpret_cast<__half2*>(&p0.x);
        __half2 a1 = *reinterpret_cast<__half2*>(&p0.y);
        float2 e0 = __half22float2(a0);
        float2 e1 = __half22float2(a1);
        acc.x = fmaf(iv0, e0.x, acc.x);
        acc.y = fmaf(iv0, e0.y, acc.y);
        acc.z = fmaf(iv0, e1.x, acc.z);
        acc.w = fmaf(iv0, e1.y, acc.w);
        __half2 b0h = *reinterpret_cast<__half2*>(&p1.x);
        __half2 b1h = *reinterpret_cast<__half2*>(&p1.y);
        float2 f0 = __half22float2(b0h);
        float2 f1 = __half22float2(b1h);
        acc.x = fmaf(iv1, f0.x, acc.x);
        acc.y = fmaf(iv1, f0.y, acc.y);
        acc.z = fmaf(iv1, f1.x, acc.z);
        acc.w = fmaf(iv1, f1.y, acc.w);
    }
    for (; i < end; i++) {
        int pk = __ldg(&g_csr[i]);
        int src = pk >> 3, t = pk & 7;
        float iv = __ldg(&g_inv[(row << 3) + t]);
        uint2 p = __ldg((const uint2*)(g_Y + (size_t)src * KC + (t << 7) + lane * 4));
        __half2 v0 = *reinterpret_cast<__half2*>(&p.x);
        __half2 v1 = *reinterpret_cast<__half2*>(&p.y);
        float2 f0 = __half22float2(v0);
        float2 f1 = __half22float2(v1);
        acc.x = fmaf(iv, f0.x, acc.x);
        acc.y = fmaf(iv, f0.y, acc.y);
        acc.z = fmaf(iv, f1.x, acc.z);
        acc.w = fmaf(iv, f1.y, acc.w);
    }

    if (do_ln) {
        float s = acc.x + acc.y + acc.z + acc.w;
#pragma unroll
        for (int off = 16; off > 0; off >>= 1) s += __shfl_xor_sync(0xffffffffu, s, off);
        float mu = s * (1.0f / 128.0f);
        float dx = acc.x - mu, dy = acc.y - mu, dz = acc.z - mu, dw = acc.w - mu;
        float q = dx * dx + dy * dy + dz * dz + dw * dw;
#pragma unroll
        for (int off = 16; off > 0; off >>= 1) q += __shfl_xor_sync(0xffffffffu, q, off);
        float rs = rsqrtf(q * (1.0f / 128.0f) + LN_EPS);
        float4 gg = ((const float4*)gma)[lane];
        float4 b2 = ((const float4*)bta)[lane];
        float ox = fmaxf(dx * rs * gg.x + b2.x, 0.f);
        float oy = fmaxf(dy * rs * gg.y + b2.y, 0.f);
        float oz = fmaxf(dz * rs * gg.z + b2.z, 0.f);
        float ow = fmaxf(dw * rs * gg.w + b2.w, 0.f);
        __half2 h0 = __floats2half2_rn(ox, oy);
        __half2 h1 = __floats2half2_rn(oz, ow);
        uint32_t* xh = (uint32_t*)g_Xh;
        xh[row * 64 + lane * 2]     = *reinterpret_cast<uint32_t*>(&h0);
        xh[row * 64 + lane * 2 + 1] = *reinterpret_cast<uint32_t*>(&h1);
    } else {
        ((float4*)ext_out)[row * 32 + lane] = acc;
    }
}

// ---------------- launch ----------------------------------------------------
extern "C" void kernel_launch(void* const* d_in, const int* in_sizes, int n_in,
                              void* d_out, int out_size) {
    const int*   node_ids = (const int*)d_in[0];
    const int*   ei       = (const int*)d_in[1];
    const int*   et       = (const int*)d_in[2];
    const float* emb      = (const float*)d_in[3];
    const float* W1 = (const float*)d_in[4],  *root1 = (const float*)d_in[5];
    const float* b1 = (const float*)d_in[6],  *g1 = (const float*)d_in[7];
    const float* be1 = (const float*)d_in[8];
    const float* W2 = (const float*)d_in[9],  *root2 = (const float*)d_in[10];
    const float* b2 = (const float*)d_in[11], *g2 = (const float*)d_in[12];
    const float* be2 = (const float*)d_in[13];
    const float* W3 = (const float*)d_in[14], *root3 = (const float*)d_in[15];
    const float* b3 = (const float*)d_in[16];
    float* out = (float*)d_out;

    static cudaStream_t s2 = nullptr;
    static cudaEvent_t evFork = nullptr, evJoin = nullptr, evPack = nullptr;
    static int init_done = 0;
    if (!init_done) {
        cudaFuncSetAttribute(gemm_kernel, cudaFuncAttributeMaxDynamicSharedMemorySize,
                             GEMM_SMEM);
        cudaStreamCreateWithFlags(&s2, cudaStreamNonBlocking);
        cudaEventCreateWithFlags(&evFork, cudaEventDisableTiming);
        cudaEventCreateWithFlags(&evJoin, cudaEventDisableTiming);
        cudaEventCreateWithFlags(&evPack, cudaEventDisableTiming);
        init_done = 1;
    }

    const int T = 256;
    const int NB_NODE = (NN + T - 1) / T;          // 196
    dim3 gemm_grid(KC / 128, YSTRIDE);             // 9 x 32 persistent CTAs

    // Fork: packs + edge-structure chain on s2, concurrent with gather/gemm1.
    cudaEventRecord(evFork, 0);
    cudaStreamWaitEvent(s2, evFork, 0);

    pack_kernel<<<(KC * DD + T - 1) / T, T, 0, s2>>>(W1, root1, 0);
    cudaEventRecord(evPack, s2);                    // gemm1 needs only pack1
    pack_kernel<<<(KC * DD + T - 1) / T, T, 0, s2>>>(W2, root2, 1);
    pack_kernel<<<(KC * DD + T - 1) / T, T, 0, s2>>>(W3, root3, 2);
    zero_all_kernel<<<(NN * RR + T - 1) / T, T, 0, s2>>>();
    count_kernel<<<(EE + T - 1) / T, T, 0, s2>>>(ei, et);
    deg_inv_kernel<<<NB_NODE, T, 0, s2>>>();
    deg_partial_kernel<<<NB_NODE, T, 0, s2>>>();
    scan_part_kernel<<<1, T, 0, s2>>>(NB_NODE);
    rowptr_kernel<<<NB_NODE, T, 0, s2>>>();
    fill_kernel<<<(EE + T - 1) / T, T, 0, s2>>>(ei, et);
    cudaEventRecord(evJoin, s2);

    // Main stream: gather, then layer-1 GEMM (after pack1)
    gather_kernel<<<(NN * 32 + T - 1) / T, T>>>(node_ids, emb);
    cudaStreamWaitEvent(0, evPack, 0);
    gemm_kernel<<<gemm_grid, T, GEMM_SMEM>>>(0);

    // Join: agg needs CSR + counts
    cudaStreamWaitEvent(0, evJoin, 0);

    agg_kernel<<<(NN * 32 + T - 1) / T, T>>>(b1, g1, be1, nullptr, 1);
    gemm_kernel<<<gemm_grid, T, GEMM_SMEM>>>(1);
    agg_kernel<<<(NN * 32 + T - 1) / T, T>>>(b2, g2, be2, nullptr, 1);
    gemm_kernel<<<gemm_grid, T, GEMM_SMEM>>>(2);
    agg_kernel<<<(NN * 32 + T - 1) / T, T>>>(b3, nullptr, nullptr, out, 0);

    (void)in_sizes; (void)n_in; (void)out_size;
}